// round 2
// baseline (speedup 1.0000x reference)
#include <cuda_runtime.h>
#include <math.h>

#define B_  16
#define N_  512
#define C_  384
#define H_  6
#define HD_ 64
#define FF_ 1152
#define BN_ (B_*N_)   // 8192
#define BH_ (B_*H_)   // 96

// ---------------- scratch (static device globals; no runtime alloc) ------------
__device__ float g_x   [BN_*C_];
__device__ float g_qkv [BN_*3*C_];
__device__ float g_V   [192*64*512];
__device__ float g_tau [192*64];
__device__ float g_qgr [BH_*N_*HD_];
__device__ float g_kgr [BH_*N_*HD_];
__device__ float g_qn2 [BH_*N_];
__device__ float g_kn2 [BH_*N_];
__device__ float g_qk  [(long long)BH_*N_*N_];
__device__ float g_dots[(long long)BH_*N_*N_];
__device__ float g_attn[(long long)BH_*N_*N_];
__device__ float g_vT  [BH_*HD_*N_];
__device__ float g_ao  [BN_*C_];
__device__ float g_t   [BN_*C_];
__device__ float g_u   [BN_*C_];
__device__ float g_h1  [BN_*FF_];

// ---------------- block reductions --------------------------------------------
__device__ __forceinline__ float bred_sum(float v, float* red, int nw) {
    int lane = threadIdx.x & 31, wid = threadIdx.x >> 5;
    #pragma unroll
    for (int o = 16; o; o >>= 1) v += __shfl_xor_sync(0xffffffffu, v, o);
    if (lane == 0) red[wid] = v;
    __syncthreads();
    if (wid == 0) {
        float t = (lane < nw) ? red[lane] : 0.f;
        #pragma unroll
        for (int o = 16; o; o >>= 1) t += __shfl_xor_sync(0xffffffffu, t, o);
        if (lane == 0) red[32] = t;
    }
    __syncthreads();
    float r = red[32];
    __syncthreads();
    return r;
}

__device__ __forceinline__ float bred_max(float v, float* red, int nw) {
    int lane = threadIdx.x & 31, wid = threadIdx.x >> 5;
    #pragma unroll
    for (int o = 16; o; o >>= 1) v = fmaxf(v, __shfl_xor_sync(0xffffffffu, v, o));
    if (lane == 0) red[wid] = v;
    __syncthreads();
    if (wid == 0) {
        float t = (lane < nw) ? red[lane] : -INFINITY;
        #pragma unroll
        for (int o = 16; o; o >>= 1) t = fmaxf(t, __shfl_xor_sync(0xffffffffu, t, o));
        if (lane == 0) red[32] = t;
    }
    __syncthreads();
    float r = red[32];
    __syncthreads();
    return r;
}

// ---------------- LayerNorm (C=384, 128 threads per row) ----------------------
__global__ __launch_bounds__(128) void ln_kernel(
    const float* __restrict__ in, const float* __restrict__ w,
    const float* __restrict__ b, float* __restrict__ out) {
    __shared__ float red[33];
    int row = blockIdx.x;
    const float* x = in + (long long)row * C_;
    float v0[3]; float s = 0.f;
    #pragma unroll
    for (int i = 0; i < 3; i++) { v0[i] = x[threadIdx.x + 128*i]; s += v0[i]; }
    s = bred_sum(s, red, 4);
    float mu = s * (1.f / C_);
    float var = 0.f;
    #pragma unroll
    for (int i = 0; i < 3; i++) { float d = v0[i] - mu; var = fmaf(d, d, var); }
    var = bred_sum(var, red, 4) * (1.f / C_);
    float inv = rsqrtf(var + 1e-5f);
    #pragma unroll
    for (int i = 0; i < 3; i++) {
        int c = threadIdx.x + 128*i;
        out[(long long)row*C_ + c] = (v0[i] - mu) * inv * w[c] + b[c];
    }
}

// ---------------- generic batched GEMM: C = A * B^T (+bias,+gelu,+res) --------
// A: [M,K] lda ; B: [N,K] ldb ; C: [M,N] ldc. Batch z -> (zb=z/Hdiv, zh=z%Hdiv).
__global__ __launch_bounds__(256) void gemm_kernel(
    const float* __restrict__ A, const float* __restrict__ B,
    const float* __restrict__ R, const float* __restrict__ bias,
    float* __restrict__ C,
    int M, int N, int K, int lda, int ldb, int ldc,
    long long Ab, long long Ah, long long Bb, long long Bh,
    long long Cb, long long Ch, int Hdiv, int flags) {
    int z = blockIdx.z;
    int zb = z / Hdiv, zh = z - zb * Hdiv;
    A += Ab*zb + Ah*zh;
    B += Bb*zb + Bh*zh;
    long long co = Cb*zb + Ch*zh;
    C += co;
    const float* Rp = (flags & 4) ? (R + co) : nullptr;
    __shared__ float As[16][68];
    __shared__ float Bs[16][68];
    int m0 = blockIdx.y << 6, n0 = blockIdx.x << 6;
    int tid = threadIdx.x, tx = tid & 15, ty = tid >> 4;
    float acc[4][4] = {};
    for (int k0 = 0; k0 < K; k0 += 16) {
        #pragma unroll
        for (int l = tid; l < 1024; l += 256) {
            int mm = l >> 4, kk = l & 15;
            As[kk][mm] = A[(long long)(m0+mm)*lda + (k0+kk)];
            Bs[kk][mm] = B[(long long)(n0+mm)*ldb + (k0+kk)];
        }
        __syncthreads();
        #pragma unroll
        for (int kk = 0; kk < 16; kk++) {
            float a0[4], b0[4];
            #pragma unroll
            for (int i = 0; i < 4; i++) a0[i] = As[kk][(ty<<2)+i];
            #pragma unroll
            for (int j = 0; j < 4; j++) b0[j] = Bs[kk][(tx<<2)+j];
            #pragma unroll
            for (int i = 0; i < 4; i++)
                #pragma unroll
                for (int j = 0; j < 4; j++)
                    acc[i][j] = fmaf(a0[i], b0[j], acc[i][j]);
        }
        __syncthreads();
    }
    #pragma unroll
    for (int i = 0; i < 4; i++) {
        int m = m0 + (ty<<2) + i;
        #pragma unroll
        for (int j = 0; j < 4; j++) {
            int n = n0 + (tx<<2) + j;
            float v = acc[i][j];
            if (flags & 1) v += bias[n];
            if (flags & 2) v = 0.5f * v * (1.f + erff(v * 0.70710678118654752f));
            if (flags & 4) v += Rp[(long long)m*ldc + n];
            C[(long long)m*ldc + n] = v;
        }
    }
}

// ---------------- per-(b,h,n) squared norms of q,k ----------------------------
__global__ void sumsq_kernel(const float* __restrict__ qkv,
                             float* __restrict__ qn2, float* __restrict__ kn2) {
    int i = blockIdx.x * blockDim.x + threadIdx.x;
    if (i >= 2*BH_*N_) return;
    int which = i / (BH_*N_);
    int bhn = i - which*(BH_*N_);
    int bh = bhn >> 9, n = bhn & 511;
    int b = bh / 6, h = bh - (bh/6)*6;
    const float* p = qkv + (long long)(b*512 + n)*1152 + which*384 + h*64;
    float s = 0.f;
    #pragma unroll
    for (int d = 0; d < 64; d++) s = fmaf(p[d], p[d], s);
    if (which) kn2[bhn] = s; else qn2[bhn] = s;
}

// ---------------- v transpose: vT[b,h,d,m] = v[b,h,m,d] -----------------------
__global__ void vT_kernel(const float* __restrict__ qkv, float* __restrict__ vT) {
    int i = blockIdx.x * blockDim.x + threadIdx.x;
    if (i >= BH_*HD_*N_) return;
    int m = i & 511;
    int d = (i >> 9) & 63;
    int bh = i >> 15;
    int b = bh / 6, h = bh - (bh/6)*6;
    vT[i] = qkv[(long long)(b*512 + m)*1152 + 768 + h*64 + d];
}

// ---------------- Householder QR factorization (LAPACK slarfg convention) -----
// One CTA per 512x64 matrix; A column-major in smem; stores V (unit-lower) + tau.
__global__ __launch_bounds__(512) void qr_factor(const float* __restrict__ qkv,
                                                 float* __restrict__ V,
                                                 float* __restrict__ tau) {
    extern __shared__ float sm[];
    float* As  = sm;             // 64*512
    float* red = sm + 64*512;    // 33
    float* sc  = red + 33;       // 2
    int mat = blockIdx.x;
    int s = (mat >= 96) ? 1 : 0;
    int bh = mat - s*96;
    int b = bh / 6, h = bh - (bh/6)*6;
    const float* Ab = qkv + (long long)b*512*1152 + s*384 + h*64;
    int tid = threadIdx.x;
    for (int i = tid; i < 64*512; i += 512) {
        int d = i >> 9, n = i & 511;
        As[i] = Ab[(long long)n*1152 + d];
    }
    __syncthreads();
    for (int j = 0; j < 64; j++) {
        float* col = As + (j << 9);
        float xv = (tid > j) ? col[tid] : 0.f;
        float ss = bred_sum(xv*xv, red, 16);
        if (tid == 0) {
            float alpha = col[j];
            float tj, scl;
            if (ss == 0.f) { tj = 0.f; scl = 0.f; }
            else {
                float nrm  = sqrtf(alpha*alpha + ss);
                float beta = (alpha >= 0.f) ? -nrm : nrm;   // LAPACK sign
                tj  = (beta - alpha) / beta;
                scl = 1.f / (alpha - beta);
            }
            sc[0] = tj; sc[1] = scl;
            tau[(mat << 6) + j] = tj;
        }
        __syncthreads();
        float tj = sc[0], scl = sc[1];
        float vr;
        if (tid < j)       vr = 0.f;
        else if (tid == j) vr = 1.f;
        else { vr = col[tid] * scl; col[tid] = vr; }
        V[((long long)mat*64 + j)*512 + tid] = vr;
        __syncthreads();
        if (tj != 0.f) {
            int wid = tid >> 5, lane = tid & 31;
            for (int c = j + 1 + wid; c < 64; c += 16) {
                float* cc = As + (c << 9);
                float w = 0.f;
                for (int r = j + lane; r < 512; r += 32) {
                    float vv = (r == j) ? 1.f : col[r];
                    w = fmaf(vv, cc[r], w);
                }
                #pragma unroll
                for (int o = 16; o; o >>= 1) w += __shfl_xor_sync(0xffffffffu, w, o);
                float tw = tj * w;
                for (int r = j + lane; r < 512; r += 32) {
                    float vv = (r == j) ? 1.f : col[r];
                    cc[r] -= tw * vv;
                }
            }
        }
        __syncthreads();
    }
}

// ---------------- form reduced Q = H_0...H_63 [I;0]  (sorg2r) -----------------
__global__ __launch_bounds__(512) void qr_formq(const float* __restrict__ V,
                                                const float* __restrict__ tau,
                                                float* __restrict__ qgr,
                                                float* __restrict__ kgr) {
    extern __shared__ float sm[];
    float* Qs = sm;            // 64*512
    float* vb = sm + 64*512;   // 512
    int mat = blockIdx.x;
    int tid = threadIdx.x;
    for (int i = tid; i < 64*512; i += 512) {
        int c = i >> 9, r = i & 511;
        Qs[i] = (r == c) ? 1.f : 0.f;
    }
    __syncthreads();
    for (int j = 63; j >= 0; j--) {
        vb[tid] = V[((long long)mat*64 + j)*512 + tid];
        __syncthreads();
        float tj = tau[(mat << 6) + j];
        if (tj != 0.f) {
            int wid = tid >> 5, lane = tid & 31;
            for (int c = j + wid; c < 64; c += 16) {
                float* cc = Qs + (c << 9);
                float w = 0.f;
                for (int r = j + lane; r < 512; r += 32) w = fmaf(vb[r], cc[r], w);
                #pragma unroll
                for (int o = 16; o; o >>= 1) w += __shfl_xor_sync(0xffffffffu, w, o);
                float tw = tj * w;
                for (int r = j + lane; r < 512; r += 32) cc[r] -= tw * vb[r];
            }
        }
        __syncthreads();
    }
    float* outp = (mat < 96) ? qgr : kgr;
    int bh = (mat < 96) ? mat : mat - 96;
    for (int i = tid; i < 64*512; i += 512) {
        int d = i >> 9, n = i & 511;
        outp[(long long)bh*N_*HD_ + n*64 + d] = Qs[i];
    }
}

// ---------------- fused head-mix + softmax ------------------------------------
// block = (b,n); thread = m. Computes eucl/riem/grass for all 6 heads, mixes
// with conv_w (6x18), softmax over m, writes attn[b,o,n,m].
__global__ __launch_bounds__(512) void mix_softmax(
    const float* __restrict__ qk, const float* __restrict__ dots,
    const float* __restrict__ qn2, const float* __restrict__ kn2,
    const float* __restrict__ conv_w, const float* __restrict__ conv_b,
    const float* __restrict__ sp, const float* __restrict__ rp,
    const float* __restrict__ gp, float* __restrict__ attn) {
    __shared__ float red[33];
    __shared__ float wsh[108], bsh[6], qsh[6];
    int bn = blockIdx.x; int b = bn >> 9, n = bn & 511;
    int m = threadIdx.x;
    if (m < 108) wsh[m] = conv_w[m];
    if (m < 6) { bsh[m] = conv_b[m]; qsh[m] = qn2[((b*6 + m) << 9) + n]; }
    float scale = *sp, rs = *rp, gs = *gp;
    __syncthreads();
    float mixed[6];
    #pragma unroll
    for (int o = 0; o < 6; o++) mixed[o] = bsh[o];
    #pragma unroll
    for (int h = 0; h < 6; h++) {
        long long idx = ((long long)((b*6 + h)*512 + n) << 9) + m;
        float qv = qk[idx];
        float dd = dots[idx];
        float e  = qv * scale;
        float qn = qsh[h];
        float kn = kn2[((b*6 + h) << 9) + m];
        float d2 = qn*qn + kn*kn - 2.f*qv*qv;
        float ri = sqrtf(fmaxf(d2, 0.f)) * rs;
        float gg = dd*dd * gs;
        #pragma unroll
        for (int o = 0; o < 6; o++)
            mixed[o] += wsh[o*18 + h]*e + wsh[o*18 + 6 + h]*ri + wsh[o*18 + 12 + h]*gg;
    }
    #pragma unroll
    for (int o = 0; o < 6; o++) {
        float mx = bred_max(mixed[o], red, 16);
        float e  = expf(mixed[o] - mx);
        float s  = bred_sum(e, red, 16);
        attn[((long long)((b*6 + o)*512 + n) << 9) + m] = e / s;
    }
}

// ---------------- copy attn scratch -> d_out ----------------------------------
__global__ void copy_kernel(const float* __restrict__ src, float* __restrict__ dst, long long n) {
    long long i = (long long)blockIdx.x * blockDim.x + threadIdx.x;
    if (i < n) dst[i] = src[i];
}

// ================================================================================
extern "C" void kernel_launch(void* const* d_in, const int* in_sizes, int n_in,
                              void* d_out, int out_size) {
    const float* src     = (const float*)d_in[0];
    const float* pre_w   = (const float*)d_in[1];
    const float* pre_b   = (const float*)d_in[2];
    const float* qkv_w   = (const float*)d_in[3];
    const float* qkv_b   = (const float*)d_in[4];
    const float* scale_p = (const float*)d_in[5];
    const float* riem_p  = (const float*)d_in[6];
    const float* grass_p = (const float*)d_in[7];
    const float* conv_w  = (const float*)d_in[8];
    const float* conv_b  = (const float*)d_in[9];
    const float* proj_w  = (const float*)d_in[10];
    const float* proj_b  = (const float*)d_in[11];
    const float* n1_w    = (const float*)d_in[12];
    const float* n1_b    = (const float*)d_in[13];
    const float* l1_w    = (const float*)d_in[14];
    const float* l1_b    = (const float*)d_in[15];
    const float* l2_w    = (const float*)d_in[16];
    const float* l2_b    = (const float*)d_in[17];
    float* out = (float*)d_out;

    float *x, *qkv, *V, *tau, *qgr, *kgr, *qn2, *kn2, *qk, *dots, *attn, *vT, *ao, *t, *u, *h1;
    cudaGetSymbolAddress((void**)&x,    g_x);
    cudaGetSymbolAddress((void**)&qkv,  g_qkv);
    cudaGetSymbolAddress((void**)&V,    g_V);
    cudaGetSymbolAddress((void**)&tau,  g_tau);
    cudaGetSymbolAddress((void**)&qgr,  g_qgr);
    cudaGetSymbolAddress((void**)&kgr,  g_kgr);
    cudaGetSymbolAddress((void**)&qn2,  g_qn2);
    cudaGetSymbolAddress((void**)&kn2,  g_kn2);
    cudaGetSymbolAddress((void**)&qk,   g_qk);
    cudaGetSymbolAddress((void**)&dots, g_dots);
    cudaGetSymbolAddress((void**)&attn, g_attn);
    cudaGetSymbolAddress((void**)&vT,   g_vT);
    cudaGetSymbolAddress((void**)&ao,   g_ao);
    cudaGetSymbolAddress((void**)&t,    g_t);
    cudaGetSymbolAddress((void**)&u,    g_u);
    cudaGetSymbolAddress((void**)&h1,   g_h1);

    const int SMEM_FACTOR = (64*512 + 35) * 4;
    const int SMEM_FORMQ  = (64*512 + 512) * 4;
    cudaFuncSetAttribute(qr_factor, cudaFuncAttributeMaxDynamicSharedMemorySize, SMEM_FACTOR);
    cudaFuncSetAttribute(qr_formq,  cudaFuncAttributeMaxDynamicSharedMemorySize, SMEM_FORMQ);

    long long need = (long long)BN_*C_ + (long long)BH_*N_*N_;
    bool attn_in_out = ((long long)out_size >= need);
    float* attn_dst = attn_in_out ? (out + (long long)BN_*C_) : attn;

    // 1. pre-LN
    ln_kernel<<<BN_, 128>>>(src, pre_w, pre_b, x);
    // 2. QKV GEMM: [8192,384] @ [1152,384]^T + bias
    gemm_kernel<<<dim3(FF_/64, BN_/64, 1), 256>>>(x, qkv_w, nullptr, qkv_b, qkv,
        BN_, FF_, C_, C_, C_, FF_, 0,0,0,0,0,0, 1, 1);
    // 3. squared norms
    sumsq_kernel<<<(2*BH_*N_ + 255)/256, 256>>>(qkv, qn2, kn2);
    // 4. Householder QR (q: mats 0..95, k: 96..191)
    qr_factor<<<192, 512, SMEM_FACTOR>>>(qkv, V, tau);
    qr_formq <<<192, 512, SMEM_FORMQ >>>(V, tau, qgr, kgr);
    // 5. qk = q @ k^T  (batched over 96)
    gemm_kernel<<<dim3(8, 8, 96), 256>>>(qkv, qkv + 384, nullptr, nullptr, qk,
        512, 512, 64, 1152, 1152, 512,
        589824LL, 64LL, 589824LL, 64LL, 1572864LL, 262144LL, 6, 0);
    // 6. dots = qgr @ kgr^T (batched)
    gemm_kernel<<<dim3(8, 8, 96), 256>>>(qgr, kgr, nullptr, nullptr, dots,
        512, 512, 64, 64, 64, 512,
        196608LL, 32768LL, 196608LL, 32768LL, 1572864LL, 262144LL, 6, 0);
    // 7. v transpose
    vT_kernel<<<(BH_*HD_*N_ + 255)/256, 256>>>(qkv, vT);
    // 8. mix + softmax -> attn
    mix_softmax<<<BN_, 512>>>(qk, dots, qn2, kn2, conv_w, conv_b,
                              scale_p, riem_p, grass_p, attn_dst);
    // 9. out = attn @ v  -> ao laid out [b,n,h*64+d]
    gemm_kernel<<<dim3(1, 8, 96), 256>>>(attn_dst, vT, nullptr, nullptr, ao,
        512, 64, 512, 512, 512, 384,
        1572864LL, 262144LL, 196608LL, 32768LL, 196608LL, 64LL, 6, 0);
    // 10. proj + residual(src) -> t
    gemm_kernel<<<dim3(C_/64, BN_/64, 1), 256>>>(ao, proj_w, src, proj_b, t,
        BN_, C_, C_, C_, C_, C_, 0,0,0,0,0,0, 1, 1|4);
    // 11. norm1 -> u
    ln_kernel<<<BN_, 128>>>(t, n1_w, n1_b, u);
    // 12. lin1 + gelu -> h1
    gemm_kernel<<<dim3(FF_/64, BN_/64, 1), 256>>>(u, l1_w, nullptr, l1_b, h1,
        BN_, FF_, C_, C_, C_, FF_, 0,0,0,0,0,0, 1, 1|2);
    // 13. lin2 + bias + residual(u) -> d_out (final src)
    gemm_kernel<<<dim3(C_/64, BN_/64, 1), 256>>>(h1, l2_w, u, l2_b, out,
        BN_, C_, FF_, FF_, FF_, C_, 0,0,0,0,0,0, 1, 1|4);
}

// round 6
// speedup vs baseline: 1.1485x; 1.1485x over previous
#include <cuda_runtime.h>
#include <math.h>

#define B_  16
#define N_  512
#define C_  384
#define H_  6
#define HD_ 64
#define FF_ 1152
#define BN_ (B_*N_)   // 8192
#define BH_ (B_*H_)   // 96

// ---------------- scratch (static device globals; no runtime alloc) ------------
__device__ __align__(16) float g_x   [BN_*C_];
__device__ __align__(16) float g_qkv [BN_*3*C_];
__device__ __align__(16) float g_qgr [BH_*N_*HD_];
__device__ __align__(16) float g_kgr [BH_*N_*HD_];
__device__ __align__(16) float g_qn2 [BH_*N_];
__device__ __align__(16) float g_kn2 [BH_*N_];
__device__ __align__(16) float g_qk  [(long long)BH_*N_*N_];
__device__ __align__(16) float g_dots[(long long)BH_*N_*N_];
__device__ __align__(16) float g_attn[(long long)BH_*N_*N_];
__device__ __align__(16) float g_vT  [BH_*HD_*N_];
__device__ __align__(16) float g_ao  [BN_*C_];
__device__ __align__(16) float g_t   [BN_*C_];
__device__ __align__(16) float g_u   [BN_*C_];
__device__ __align__(16) float g_h1  [BN_*FF_];

// ---------------- block reductions --------------------------------------------
__device__ __forceinline__ float bred_sum(float v, float* red, int nw) {
    int lane = threadIdx.x & 31, wid = threadIdx.x >> 5;
    #pragma unroll
    for (int o = 16; o; o >>= 1) v += __shfl_xor_sync(0xffffffffu, v, o);
    if (lane == 0) red[wid] = v;
    __syncthreads();
    if (wid == 0) {
        float t = (lane < nw) ? red[lane] : 0.f;
        #pragma unroll
        for (int o = 16; o; o >>= 1) t += __shfl_xor_sync(0xffffffffu, t, o);
        if (lane == 0) red[32] = t;
    }
    __syncthreads();
    float r = red[32];
    __syncthreads();
    return r;
}

__device__ __forceinline__ float bred_max(float v, float* red, int nw) {
    int lane = threadIdx.x & 31, wid = threadIdx.x >> 5;
    #pragma unroll
    for (int o = 16; o; o >>= 1) v = fmaxf(v, __shfl_xor_sync(0xffffffffu, v, o));
    if (lane == 0) red[wid] = v;
    __syncthreads();
    if (wid == 0) {
        float t = (lane < nw) ? red[lane] : -INFINITY;
        #pragma unroll
        for (int o = 16; o; o >>= 1) t = fmaxf(t, __shfl_xor_sync(0xffffffffu, t, o));
        if (lane == 0) red[32] = t;
    }
    __syncthreads();
    float r = red[32];
    __syncthreads();
    return r;
}

// ---------------- LayerNorm (C=384, 128 threads per row) ----------------------
__global__ __launch_bounds__(128) void ln_kernel(
    const float* __restrict__ in, const float* __restrict__ w,
    const float* __restrict__ b, float* __restrict__ out) {
    __shared__ float red[33];
    int row = blockIdx.x;
    const float* x = in + (long long)row * C_;
    float v0[3]; float s = 0.f;
    #pragma unroll
    for (int i = 0; i < 3; i++) { v0[i] = x[threadIdx.x + 128*i]; s += v0[i]; }
    s = bred_sum(s, red, 4);
    float mu = s * (1.f / C_);
    float var = 0.f;
    #pragma unroll
    for (int i = 0; i < 3; i++) { float d = v0[i] - mu; var = fmaf(d, d, var); }
    var = bred_sum(var, red, 4) * (1.f / C_);
    float inv = rsqrtf(var + 1e-5f);
    #pragma unroll
    for (int i = 0; i < 3; i++) {
        int c = threadIdx.x + 128*i;
        out[(long long)row*C_ + c] = (v0[i] - mu) * inv * w[c] + b[c];
    }
}

// ---------------- templated batched GEMM: C = A * B^T (+bias,+gelu,+res) ------
// A: [M,K] lda ; B: [N,K] ldb ; C: [M,N] ldc. Batch z -> (zb=z/Hdiv, zh=z%Hdiv).
// Requires: M % BM == 0, N % BN == 0, K % 16 == 0, lda/ldb % 4 == 0, 16B-aligned ptrs.
template<int BM, int BN, int TM, int TN>
__global__ __launch_bounds__(256) void gemm_t(
    const float* __restrict__ A, const float* __restrict__ B,
    const float* __restrict__ R, const float* __restrict__ bias,
    float* __restrict__ C,
    int M, int N, int K, int lda, int ldb, int ldc,
    long long Ab, long long Ah, long long Bb, long long Bh,
    long long Cb, long long Ch, int Hdiv, int flags) {
    constexpr int KT = 16;
    int z = blockIdx.z;
    int zb = z / Hdiv, zh = z - zb * Hdiv;
    A += Ab*zb + Ah*zh;
    B += Bb*zb + Bh*zh;
    long long co = Cb*zb + Ch*zh;
    C += co;
    const float* Rp = (flags & 4) ? (R + co) : nullptr;
    __shared__ float As[KT][BM+4];
    __shared__ float Bs[KT][BN+4];
    int m0 = blockIdx.y * BM, n0 = blockIdx.x * BN;
    int tid = threadIdx.x;
    constexpr int TX = BN / TN;           // threads along n
    int tx = tid % TX, ty = tid / TX;     // ty in [0, BM/TM)
    float acc[TM][TN] = {};
    int lr = tid >> 2, lk = (tid & 3) * 4;
    for (int k0 = 0; k0 < K; k0 += KT) {
        #pragma unroll
        for (int rr = lr; rr < BM; rr += 64) {
            float4 v = *(const float4*)(A + (long long)(m0+rr)*lda + k0 + lk);
            As[lk+0][rr] = v.x; As[lk+1][rr] = v.y; As[lk+2][rr] = v.z; As[lk+3][rr] = v.w;
        }
        #pragma unroll
        for (int rr = lr; rr < BN; rr += 64) {
            float4 v = *(const float4*)(B + (long long)(n0+rr)*ldb + k0 + lk);
            Bs[lk+0][rr] = v.x; Bs[lk+1][rr] = v.y; Bs[lk+2][rr] = v.z; Bs[lk+3][rr] = v.w;
        }
        __syncthreads();
        #pragma unroll
        for (int kk = 0; kk < KT; kk++) {
            float a0[TM], b0[TN];
            #pragma unroll
            for (int i = 0; i < TM; i++) a0[i] = As[kk][ty*TM + i];
            #pragma unroll
            for (int j = 0; j < TN; j++) b0[j] = Bs[kk][tx*TN + j];
            #pragma unroll
            for (int i = 0; i < TM; i++)
                #pragma unroll
                for (int j = 0; j < TN; j++)
                    acc[i][j] = fmaf(a0[i], b0[j], acc[i][j]);
        }
        __syncthreads();
    }
    #pragma unroll
    for (int i = 0; i < TM; i++) {
        int m = m0 + ty*TM + i;
        #pragma unroll
        for (int j = 0; j < TN; j++) {
            int n = n0 + tx*TN + j;
            float v = acc[i][j];
            if (flags & 1) v += bias[n];
            if (flags & 2) v = 0.5f * v * (1.f + erff(v * 0.70710678118654752f));
            if (flags & 4) v += Rp[(long long)m*ldc + n];
            C[(long long)m*ldc + n] = v;
        }
    }
}

// ---------------- per-(b,h,n) squared norms of q,k ----------------------------
__global__ void sumsq_kernel(const float* __restrict__ qkv,
                             float* __restrict__ qn2, float* __restrict__ kn2) {
    int i = blockIdx.x * blockDim.x + threadIdx.x;
    if (i >= 2*BH_*N_) return;
    int which = i / (BH_*N_);
    int bhn = i - which*(BH_*N_);
    int bh = bhn >> 9, n = bhn & 511;
    int b = bh / 6, h = bh - (bh/6)*6;
    const float* p = qkv + (long long)(b*512 + n)*1152 + which*384 + h*64;
    float s = 0.f;
    #pragma unroll
    for (int d = 0; d < 64; d++) s = fmaf(p[d], p[d], s);
    if (which) kn2[bhn] = s; else qn2[bhn] = s;
}

// ---------------- v transpose: vT[b,h,d,m] = v[b,h,m,d] -----------------------
__global__ void vT_kernel(const float* __restrict__ qkv, float* __restrict__ vT) {
    int i = blockIdx.x * blockDim.x + threadIdx.x;
    if (i >= BH_*HD_*N_) return;
    int m = i & 511;
    int d = (i >> 9) & 63;
    int bh = i >> 15;
    int b = bh / 6, h = bh - (bh/6)*6;
    vT[i] = qkv[(long long)(b*512 + m)*1152 + 768 + h*64 + d];
}

// ---------------- fused Householder QR + form-Q (sgeqr2 + sorg2r, in place) ----
// One CTA per 512x64 matrix, entirely in smem. LAPACK slarfg sign convention.
// Reflector stored UNSCALED: u_r = x_r (r>j), u_j = alpha-beta; effective tau
// teff = tau/(alpha-beta)^2 so H = I - teff*u*u^T. Column-j+1 norm is fused
// into the trailing update (no separate block reduction per iteration).
#define QR_LDC 513
__global__ __launch_bounds__(512) void qr_fused(const float* __restrict__ qkv,
                                                float* __restrict__ qgr,
                                                float* __restrict__ kgr) {
    extern __shared__ float As[];          // 64 cols * QR_LDC
    __shared__ float red[33];
    __shared__ float steff[64];
    __shared__ float sc[2];                // sc[0]=ss carry / uj bcast, sc[1] unused spare
    __shared__ float s_ss;
    int mat = blockIdx.x;
    int s = (mat >= 96) ? 1 : 0;
    int bh = mat - s*96;
    int b = bh / 6, h = bh - (bh/6)*6;
    const float* Ab = qkv + (long long)b*512*1152 + s*384 + h*64;
    int tid = threadIdx.x;
    int wid = tid >> 5, lane = tid & 31;

    // coalesced load: consecutive tid -> consecutive d
    for (int i = tid; i < 64*512; i += 512) {
        int n = i >> 6, d = i & 63;
        As[d*QR_LDC + n] = Ab[(long long)n*1152 + d];
    }
    __syncthreads();

    // initial sum of squares of column 0 below row 0
    {
        float x = (tid > 0) ? As[tid] : 0.f;
        float ss0 = bred_sum(x*x, red, 16);
        if (tid == 0) s_ss = ss0;
    }
    __syncthreads();

    // ---------------- forward factorization ----------------
    for (int j = 0; j < 64; j++) {
        float* col = As + j*QR_LDC;
        if (tid == 0) {
            float alpha = col[j];
            float ss = s_ss;
            float teff;
            if (ss == 0.f) teff = 0.f;
            else {
                float nrm  = sqrtf(alpha*alpha + ss);
                float beta = (alpha >= 0.f) ? -nrm : nrm;   // LAPACK sign
                float tau  = (beta - alpha) / beta;
                float uj   = alpha - beta;
                teff = tau / (uj * uj);
                col[j] = uj;
            }
            steff[j] = teff;
        }
        __syncthreads();
        float teff = steff[j];
        // cache u (rows >= j) in registers
        float u[16];
        #pragma unroll
        for (int t = 0; t < 16; t++) {
            int r = j + lane + 32*t;
            u[t] = (r < 512) ? col[r] : 0.f;
        }
        // trailing update; warp 0 (c == j+1) fuses next column's sumsq
        for (int c = j + 1 + wid; c < 64; c += 16) {
            float* cc = As + c*QR_LDC;
            float w = 0.f;
            #pragma unroll
            for (int t = 0; t < 16; t++) {
                int r = j + lane + 32*t;
                if (r < 512) w = fmaf(u[t], cc[r], w);
            }
            #pragma unroll
            for (int o = 16; o; o >>= 1) w += __shfl_xor_sync(0xffffffffu, w, o);
            float tw = teff * w;
            float nss = 0.f;
            #pragma unroll
            for (int t = 0; t < 16; t++) {
                int r = j + lane + 32*t;
                if (r < 512) {
                    float nv = cc[r] - tw * u[t];
                    cc[r] = nv;
                    if (c == j+1 && r > j+1) nss = fmaf(nv, nv, nss);
                }
            }
            if (c == j+1) {
                #pragma unroll
                for (int o = 16; o; o >>= 1) nss += __shfl_xor_sync(0xffffffffu, nss, o);
                if (lane == 0) s_ss = nss;
            }
        }
        __syncthreads();
    }

    // ---------------- backward form-Q (sorg2r, in place) ----------------
    for (int j = 63; j >= 0; j--) {
        float* col = As + j*QR_LDC;
        float teff = steff[j];
        if (tid == 0) sc[0] = col[j];        // broadcast u_j
        // per-thread old value of its own row (for finalize)
        float ur_own = col[tid];
        // cache u in regs for update phase
        float u[16];
        #pragma unroll
        for (int t = 0; t < 16; t++) {
            int r = j + lane + 32*t;
            u[t] = (r < 512) ? col[r] : 0.f;
        }
        __syncthreads();                     // sc[0] visible; all reads of col done below via regs
        // apply H_j to already-built trailing Q columns c > j (rows >= j)
        for (int c = j + 1 + wid; c < 64; c += 16) {
            float* cc = As + c*QR_LDC;
            float w = 0.f;
            #pragma unroll
            for (int t = 0; t < 16; t++) {
                int r = j + lane + 32*t;
                if (r < 512) w = fmaf(u[t], cc[r], w);
            }
            #pragma unroll
            for (int o = 16; o; o >>= 1) w += __shfl_xor_sync(0xffffffffu, w, o);
            float tw = teff * w;
            #pragma unroll
            for (int t = 0; t < 16; t++) {
                int r = j + lane + 32*t;
                if (r < 512) cc[r] -= tw * u[t];
            }
        }
        __syncthreads();                     // updates done; col j reads (reg-cached) all complete
        // finalize column j: col_j = e_j - (teff*u_j) * u
        {
            float uj = sc[0];
            float tj = teff * uj;
            float v;
            if (tid < j)       v = 0.f;
            else if (tid == j) v = 1.f - tj * uj;
            else               v = -tj * ur_own;
            col[tid] = v;
        }
        __syncthreads();
    }

    // coalesced store: out[n*64+d], consecutive tid -> consecutive d
    float* outp = (mat < 96) ? qgr : kgr;
    for (int i = tid; i < 64*512; i += 512) {
        int n = i >> 6, d = i & 63;
        outp[(long long)bh*N_*HD_ + i] = As[d*QR_LDC + n];
    }
}

// ---------------- fused head-mix + softmax ------------------------------------
__global__ __launch_bounds__(512) void mix_softmax(
    const float* __restrict__ qk, const float* __restrict__ dots,
    const float* __restrict__ qn2, const float* __restrict__ kn2,
    const float* __restrict__ conv_w, const float* __restrict__ conv_b,
    const float* __restrict__ sp, const float* __restrict__ rp,
    const float* __restrict__ gp, float* __restrict__ attn) {
    __shared__ float red[33];
    __shared__ float wsh[108], bsh[6], qsh[6];
    int bn = blockIdx.x; int b = bn >> 9, n = bn & 511;
    int m = threadIdx.x;
    if (m < 108) wsh[m] = conv_w[m];
    if (m < 6) { bsh[m] = conv_b[m]; qsh[m] = qn2[((b*6 + m) << 9) + n]; }
    float scale = *sp, rs = *rp, gs = *gp;
    __syncthreads();
    float mixed[6];
    #pragma unroll
    for (int o = 0; o < 6; o++) mixed[o] = bsh[o];
    #pragma unroll
    for (int h = 0; h < 6; h++) {
        long long idx = ((long long)((b*6 + h)*512 + n) << 9) + m;
        float qv = qk[idx];
        float dd = dots[idx];
        float e  = qv * scale;
        float qn = qsh[h];
        float kn = kn2[((b*6 + h) << 9) + m];
        float d2 = qn*qn + kn*kn - 2.f*qv*qv;
        float ri = sqrtf(fmaxf(d2, 0.f)) * rs;
        float gg = dd*dd * gs;
        #pragma unroll
        for (int o = 0; o < 6; o++)
            mixed[o] += wsh[o*18 + h]*e + wsh[o*18 + 6 + h]*ri + wsh[o*18 + 12 + h]*gg;
    }
    #pragma unroll
    for (int o = 0; o < 6; o++) {
        float mx = bred_max(mixed[o], red, 16);
        float e  = expf(mixed[o] - mx);
        float s  = bred_sum(e, red, 16);
        attn[((long long)((b*6 + o)*512 + n) << 9) + m] = e / s;
    }
}

// ================================================================================
extern "C" void kernel_launch(void* const* d_in, const int* in_sizes, int n_in,
                              void* d_out, int out_size) {
    const float* src     = (const float*)d_in[0];
    const float* pre_w   = (const float*)d_in[1];
    const float* pre_b   = (const float*)d_in[2];
    const float* qkv_w   = (const float*)d_in[3];
    const float* qkv_b   = (const float*)d_in[4];
    const float* scale_p = (const float*)d_in[5];
    const float* riem_p  = (const float*)d_in[6];
    const float* grass_p = (const float*)d_in[7];
    const float* conv_w  = (const float*)d_in[8];
    const float* conv_b  = (const float*)d_in[9];
    const float* proj_w  = (const float*)d_in[10];
    const float* proj_b  = (const float*)d_in[11];
    const float* n1_w    = (const float*)d_in[12];
    const float* n1_b    = (const float*)d_in[13];
    const float* l1_w    = (const float*)d_in[14];
    const float* l1_b    = (const float*)d_in[15];
    const float* l2_w    = (const float*)d_in[16];
    const float* l2_b    = (const float*)d_in[17];
    float* out = (float*)d_out;

    float *x, *qkv, *qgr, *kgr, *qn2, *kn2, *qk, *dots, *attn, *vT, *ao, *t, *u, *h1;
    cudaGetSymbolAddress((void**)&x,    g_x);
    cudaGetSymbolAddress((void**)&qkv,  g_qkv);
    cudaGetSymbolAddress((void**)&qgr,  g_qgr);
    cudaGetSymbolAddress((void**)&kgr,  g_kgr);
    cudaGetSymbolAddress((void**)&qn2,  g_qn2);
    cudaGetSymbolAddress((void**)&kn2,  g_kn2);
    cudaGetSymbolAddress((void**)&qk,   g_qk);
    cudaGetSymbolAddress((void**)&dots, g_dots);
    cudaGetSymbolAddress((void**)&attn, g_attn);
    cudaGetSymbolAddress((void**)&vT,   g_vT);
    cudaGetSymbolAddress((void**)&ao,   g_ao);
    cudaGetSymbolAddress((void**)&t,    g_t);
    cudaGetSymbolAddress((void**)&u,    g_u);
    cudaGetSymbolAddress((void**)&h1,   g_h1);

    const int SMEM_QR = 64 * QR_LDC * 4;
    cudaFuncSetAttribute(qr_fused, cudaFuncAttributeMaxDynamicSharedMemorySize, SMEM_QR);

    long long need = (long long)BN_*C_ + (long long)BH_*N_*N_;
    bool attn_in_out = ((long long)out_size >= need);
    float* attn_dst = attn_in_out ? (out + (long long)BN_*C_) : attn;

    // 1. pre-LN
    ln_kernel<<<BN_, 128>>>(src, pre_w, pre_b, x);
    // 2. QKV GEMM: [8192,384] @ [1152,384]^T + bias
    gemm_t<128,128,8,8><<<dim3(FF_/128, BN_/128, 1), 256>>>(x, qkv_w, nullptr, qkv_b, qkv,
        BN_, FF_, C_, C_, C_, FF_, 0,0,0,0,0,0, 1, 1);
    // 3. squared norms
    sumsq_kernel<<<(2*BH_*N_ + 255)/256, 256>>>(qkv, qn2, kn2);
    // 4. fused Householder QR + form-Q (q: mats 0..95, k: 96..191)
    qr_fused<<<192, 512, SMEM_QR>>>(qkv, qgr, kgr);
    // 5. qk = q @ k^T  (batched over 96)
    gemm_t<128,128,8,8><<<dim3(4, 4, 96), 256>>>(qkv, qkv + 384, nullptr, nullptr, qk,
        512, 512, 64, 1152, 1152, 512,
        589824LL, 64LL, 589824LL, 64LL, 1572864LL, 262144LL, 6, 0);
    // 6. dots = qgr @ kgr^T (batched)
    gemm_t<128,128,8,8><<<dim3(4, 4, 96), 256>>>(qgr, kgr, nullptr, nullptr, dots,
        512, 512, 64, 64, 64, 512,
        196608LL, 32768LL, 196608LL, 32768LL, 1572864LL, 262144LL, 6, 0);
    // 7. v transpose
    vT_kernel<<<(BH_*HD_*N_ + 255)/256, 256>>>(qkv, vT);
    // 8. mix + softmax -> attn
    mix_softmax<<<BN_, 512>>>(qk, dots, qn2, kn2, conv_w, conv_b,
                              scale_p, riem_p, grass_p, attn_dst);
    // 9. out = attn @ v  -> ao laid out [b,n,h*64+d]
    gemm_t<128,64,8,4><<<dim3(1, 4, 96), 256>>>(attn_dst, vT, nullptr, nullptr, ao,
        512, 64, 512, 512, 512, 384,
        1572864LL, 262144LL, 196608LL, 32768LL, 196608LL, 64LL, 6, 0);
    // 10. proj + residual(src) -> t
    gemm_t<128,128,8,8><<<dim3(C_/128, BN_/128, 1), 256>>>(ao, proj_w, src, proj_b, t,
        BN_, C_, C_, C_, C_, C_, 0,0,0,0,0,0, 1, 1|4);
    // 11. norm1 -> u
    ln_kernel<<<BN_, 128>>>(t, n1_w, n1_b, u);
    // 12. lin1 + gelu -> h1
    gemm_t<128,128,8,8><<<dim3(FF_/128, BN_/128, 1), 256>>>(u, l1_w, nullptr, l1_b, h1,
        BN_, FF_, C_, C_, C_, FF_, 0,0,0,0,0,0, 1, 1|2);
    // 13. lin2 + bias + residual(u) -> d_out (final src)
    gemm_t<128,128,8,8><<<dim3(C_/128, BN_/128, 1), 256>>>(h1, l2_w, u, l2_b, out,
        BN_, C_, FF_, FF_, FF_, C_, 0,0,0,0,0,0, 1, 1|4);
}

// round 7
// speedup vs baseline: 1.2766x; 1.1115x over previous
#include <cuda_runtime.h>
#include <math.h>

#define B_  16
#define N_  512
#define C_  384
#define H_  6
#define HD_ 64
#define FF_ 1152
#define BN_ (B_*N_)   // 8192
#define BH_ (B_*H_)   // 96

// ---------------- scratch (static device globals; no runtime alloc) ------------
__device__ __align__(16) float g_x   [BN_*C_];
__device__ __align__(16) float g_qkv [BN_*3*C_];
__device__ __align__(16) float g_R   [192*64*64];
__device__ __align__(16) float g_RiT [192*64*64];
__device__ __align__(16) float g_qgr [BH_*N_*HD_];
__device__ __align__(16) float g_kgr [BH_*N_*HD_];
__device__ __align__(16) float g_qn2 [BH_*N_];
__device__ __align__(16) float g_kn2 [BH_*N_];
__device__ __align__(16) float g_qk  [(long long)BH_*N_*N_];
__device__ __align__(16) float g_dots[(long long)BH_*N_*N_];
__device__ __align__(16) float g_attn[(long long)BH_*N_*N_];
__device__ __align__(16) float g_vT  [BH_*HD_*N_];
__device__ __align__(16) float g_ao  [BN_*C_];
__device__ __align__(16) float g_t   [BN_*C_];
__device__ __align__(16) float g_u   [BN_*C_];
__device__ __align__(16) float g_h1  [BN_*FF_];

// ---------------- block reductions --------------------------------------------
__device__ __forceinline__ float bred_sum(float v, float* red, int nw) {
    int lane = threadIdx.x & 31, wid = threadIdx.x >> 5;
    #pragma unroll
    for (int o = 16; o; o >>= 1) v += __shfl_xor_sync(0xffffffffu, v, o);
    if (lane == 0) red[wid] = v;
    __syncthreads();
    if (wid == 0) {
        float t = (lane < nw) ? red[lane] : 0.f;
        #pragma unroll
        for (int o = 16; o; o >>= 1) t += __shfl_xor_sync(0xffffffffu, t, o);
        if (lane == 0) red[32] = t;
    }
    __syncthreads();
    float r = red[32];
    __syncthreads();
    return r;
}

__device__ __forceinline__ float bred_max(float v, float* red, int nw) {
    int lane = threadIdx.x & 31, wid = threadIdx.x >> 5;
    #pragma unroll
    for (int o = 16; o; o >>= 1) v = fmaxf(v, __shfl_xor_sync(0xffffffffu, v, o));
    if (lane == 0) red[wid] = v;
    __syncthreads();
    if (wid == 0) {
        float t = (lane < nw) ? red[lane] : -INFINITY;
        #pragma unroll
        for (int o = 16; o; o >>= 1) t = fmaxf(t, __shfl_xor_sync(0xffffffffu, t, o));
        if (lane == 0) red[32] = t;
    }
    __syncthreads();
    float r = red[32];
    __syncthreads();
    return r;
}

// ---------------- LayerNorm (C=384, 128 threads per row) ----------------------
__global__ __launch_bounds__(128) void ln_kernel(
    const float* __restrict__ in, const float* __restrict__ w,
    const float* __restrict__ b, float* __restrict__ out) {
    __shared__ float red[33];
    int row = blockIdx.x;
    const float* x = in + (long long)row * C_;
    float v0[3]; float s = 0.f;
    #pragma unroll
    for (int i = 0; i < 3; i++) { v0[i] = x[threadIdx.x + 128*i]; s += v0[i]; }
    s = bred_sum(s, red, 4);
    float mu = s * (1.f / C_);
    float var = 0.f;
    #pragma unroll
    for (int i = 0; i < 3; i++) { float d = v0[i] - mu; var = fmaf(d, d, var); }
    var = bred_sum(var, red, 4) * (1.f / C_);
    float inv = rsqrtf(var + 1e-5f);
    #pragma unroll
    for (int i = 0; i < 3; i++) {
        int c = threadIdx.x + 128*i;
        out[(long long)row*C_ + c] = (v0[i] - mu) * inv * w[c] + b[c];
    }
}

// ---------------- templated batched GEMM: C = A * B^T (+bias,+gelu,+res) ------
// A: [M,K] lda ; B: [N,K] ldb ; C: [M,N] ldc. Batch z -> (zb=z/Hdiv, zh=z%Hdiv).
// Requires: M % BM == 0, N % BN == 0, K % 16 == 0, lda/ldb % 4 == 0, 16B-aligned ptrs.
template<int BM, int BN, int TM, int TN>
__global__ __launch_bounds__(256) void gemm_t(
    const float* __restrict__ A, const float* __restrict__ B,
    const float* __restrict__ R, const float* __restrict__ bias,
    float* __restrict__ C,
    int M, int N, int K, int lda, int ldb, int ldc,
    long long Ab, long long Ah, long long Bb, long long Bh,
    long long Cb, long long Ch, int Hdiv, int flags) {
    constexpr int KT = 16;
    int z = blockIdx.z;
    int zb = z / Hdiv, zh = z - zb * Hdiv;
    A += Ab*zb + Ah*zh;
    B += Bb*zb + Bh*zh;
    long long co = Cb*zb + Ch*zh;
    C += co;
    const float* Rp = (flags & 4) ? (R + co) : nullptr;
    __shared__ float As[KT][BM+4];
    __shared__ float Bs[KT][BN+4];
    int m0 = blockIdx.y * BM, n0 = blockIdx.x * BN;
    int tid = threadIdx.x;
    constexpr int TX = BN / TN;           // threads along n
    int tx = tid % TX, ty = tid / TX;     // ty in [0, BM/TM)
    float acc[TM][TN] = {};
    int lr = tid >> 2, lk = (tid & 3) * 4;
    for (int k0 = 0; k0 < K; k0 += KT) {
        #pragma unroll
        for (int rr = lr; rr < BM; rr += 64) {
            float4 v = *(const float4*)(A + (long long)(m0+rr)*lda + k0 + lk);
            As[lk+0][rr] = v.x; As[lk+1][rr] = v.y; As[lk+2][rr] = v.z; As[lk+3][rr] = v.w;
        }
        #pragma unroll
        for (int rr = lr; rr < BN; rr += 64) {
            float4 v = *(const float4*)(B + (long long)(n0+rr)*ldb + k0 + lk);
            Bs[lk+0][rr] = v.x; Bs[lk+1][rr] = v.y; Bs[lk+2][rr] = v.z; Bs[lk+3][rr] = v.w;
        }
        __syncthreads();
        #pragma unroll
        for (int kk = 0; kk < KT; kk++) {
            float a0[TM], b0[TN];
            #pragma unroll
            for (int i = 0; i < TM; i++) a0[i] = As[kk][ty*TM + i];
            #pragma unroll
            for (int j = 0; j < TN; j++) b0[j] = Bs[kk][tx*TN + j];
            #pragma unroll
            for (int i = 0; i < TM; i++)
                #pragma unroll
                for (int j = 0; j < TN; j++)
                    acc[i][j] = fmaf(a0[i], b0[j], acc[i][j]);
        }
        __syncthreads();
    }
    #pragma unroll
    for (int i = 0; i < TM; i++) {
        int m = m0 + ty*TM + i;
        #pragma unroll
        for (int j = 0; j < TN; j++) {
            int n = n0 + tx*TN + j;
            float v = acc[i][j];
            if (flags & 1) v += bias[n];
            if (flags & 2) v = 0.5f * v * (1.f + erff(v * 0.70710678118654752f));
            if (flags & 4) v += Rp[(long long)m*ldc + n];
            C[(long long)m*ldc + n] = v;
        }
    }
}

// ---------------- per-(b,h,n) squared norms of q,k ----------------------------
__global__ void sumsq_kernel(const float* __restrict__ qkv,
                             float* __restrict__ qn2, float* __restrict__ kn2) {
    int i = blockIdx.x * blockDim.x + threadIdx.x;
    if (i >= 2*BH_*N_) return;
    int which = i / (BH_*N_);
    int bhn = i - which*(BH_*N_);
    int bh = bhn >> 9, n = bhn & 511;
    int b = bh / 6, h = bh - (bh/6)*6;
    const float* p = qkv + (long long)(b*512 + n)*1152 + which*384 + h*64;
    float s = 0.f;
    #pragma unroll
    for (int d = 0; d < 64; d++) s = fmaf(p[d], p[d], s);
    if (which) kn2[bhn] = s; else qn2[bhn] = s;
}

// ---------------- v transpose: vT[b,h,d,m] = v[b,h,m,d] -----------------------
__global__ void vT_kernel(const float* __restrict__ qkv, float* __restrict__ vT) {
    int i = blockIdx.x * blockDim.x + threadIdx.x;
    if (i >= BH_*HD_*N_) return;
    int m = i & 511;
    int d = (i >> 9) & 63;
    int bh = i >> 15;
    int b = bh / 6, h = bh - (bh/6)*6;
    vT[i] = qkv[(long long)(b*512 + m)*1152 + 768 + h*64 + d];
}

// ---------------- Householder QR factorization only (sgeqr2, in place) --------
// One CTA per 512x64 matrix. LAPACK slarfg sign convention. Outputs compact
// R (64x64, column-major per matrix: R_out[mat*4096 + c*64 + r] = R[r][c],
// diagonal = beta). Q is NOT formed here; downstream uses Q = A * R^{-1}.
// Single __syncthreads per iteration: all threads redundantly compute the
// reflector scalars; s_ss is double-buffered by iteration parity to avoid a
// cross-warp read/write race.
#define QR_LDC 513
__global__ __launch_bounds__(512) void qr_forward(const float* __restrict__ qkv,
                                                  float* __restrict__ R_out) {
    extern __shared__ float As[];          // 64 cols * QR_LDC
    __shared__ float red[33];
    __shared__ float sbeta[64];
    __shared__ float s_ss[2];
    int mat = blockIdx.x;
    int s = (mat >= 96) ? 1 : 0;
    int bh = mat - s*96;
    int b = bh / 6, h = bh - (bh/6)*6;
    const float* Ab = qkv + (long long)b*512*1152 + s*384 + h*64;
    int tid = threadIdx.x;
    int wid = tid >> 5, lane = tid & 31;

    // coalesced load: consecutive tid -> consecutive d
    for (int i = tid; i < 64*512; i += 512) {
        int n = i >> 6, d = i & 63;
        As[d*QR_LDC + n] = Ab[(long long)n*1152 + d];
    }
    __syncthreads();

    // initial sum of squares of column 0 below row 0 -> s_ss[0]
    {
        float x = (tid > 0) ? As[tid] : 0.f;
        float ss0 = bred_sum(x*x, red, 16);
        if (tid == 0) s_ss[0] = ss0;
    }
    __syncthreads();

    for (int j = 0; j < 64; j++) {
        float* col = As + j*QR_LDC;
        // all threads compute reflector scalars redundantly
        float alpha = col[j];
        float ss = s_ss[j & 1];
        float beta, teff, uj;
        if (ss == 0.f) { beta = alpha; teff = 0.f; uj = 1.f; }
        else {
            float nrm = sqrtf(alpha*alpha + ss);
            beta = (alpha >= 0.f) ? -nrm : nrm;   // LAPACK sign
            float tau = (beta - alpha) / beta;
            uj  = alpha - beta;
            teff = tau / (uj * uj);
        }
        if (tid == 0) sbeta[j] = beta;
        // reflector u in registers: fixed row ownership r = lane + 32*t
        float u[16];
        #pragma unroll
        for (int t = 0; t < 16; t++) {
            int r = lane + 32*t;
            u[t] = (r > j) ? col[r] : ((r == j) ? uj : 0.f);
        }
        // trailing update; warp 0 (c == j+1) fuses next column's sumsq
        for (int c = j + 1 + wid; c < 64; c += 16) {
            float* cc = As + c*QR_LDC;
            float w = 0.f;
            #pragma unroll
            for (int t = 0; t < 16; t++)
                w = fmaf(u[t], cc[lane + 32*t], w);
            #pragma unroll
            for (int o = 16; o; o >>= 1) w += __shfl_xor_sync(0xffffffffu, w, o);
            float tw = teff * w;
            if (c == j + 1) {
                float nss = 0.f;
                #pragma unroll
                for (int t = 0; t < 16; t++) {
                    int r = lane + 32*t;
                    float nv = cc[r] - tw * u[t];
                    cc[r] = nv;
                    if (r > j + 1) nss = fmaf(nv, nv, nss);
                }
                #pragma unroll
                for (int o = 16; o; o >>= 1) nss += __shfl_xor_sync(0xffffffffu, nss, o);
                if (lane == 0) s_ss[(j + 1) & 1] = nss;
            } else {
                #pragma unroll
                for (int t = 0; t < 16; t++) {
                    int r = lane + 32*t;
                    cc[r] -= tw * u[t];
                }
            }
        }
        __syncthreads();
    }

    // store compact R (column-major per matrix), diag from sbeta, zeros below
    for (int i = tid; i < 4096; i += 512) {
        int c = i >> 6, r = i & 63;
        float v = (r < c) ? As[c*QR_LDC + r] : ((r == c) ? sbeta[c] : 0.f);
        R_out[(long long)mat*4096 + i] = v;
    }
}

// ---------------- invert upper-triangular R; output transposed ----------------
// RiT[mat*4096 + n*64 + k] = Rinv[k][n]  (k<=n; zeros above) -- this is the
// B operand (ldb=64) for the Q = A * Rinv GEMM (C = A * B^T form).
__global__ __launch_bounds__(64) void rinv_kernel(const float* __restrict__ R,
                                                  float* __restrict__ RiT) {
    __shared__ float Rs[4096];     // Rs[c*64+r] = R[r][c]
    __shared__ float xs[64*65];
    int mat = blockIdx.x, tid = threadIdx.x;
    for (int i = tid; i < 4096; i += 64) Rs[i] = R[(long long)mat*4096 + i];
    __syncthreads();
    int c = tid;
    float* x = xs + c*65;
    // back-substitution: solve R x = e_c  (x = Rinv column c)
    for (int i = c; i >= 0; i--) {
        float sacc = (i == c) ? 1.f : 0.f;
        for (int k = i + 1; k <= c; k++)
            sacc = fmaf(-Rs[k*64 + i], x[k], sacc);
        x[i] = sacc / Rs[i*64 + i];
    }
    for (int k = 0; k < 64; k++)
        RiT[(long long)mat*4096 + c*64 + k] = (k <= c) ? x[k] : 0.f;
}

// ---------------- fused head-mix + softmax ------------------------------------
__global__ __launch_bounds__(512) void mix_softmax(
    const float* __restrict__ qk, const float* __restrict__ dots,
    const float* __restrict__ qn2, const float* __restrict__ kn2,
    const float* __restrict__ conv_w, const float* __restrict__ conv_b,
    const float* __restrict__ sp, const float* __restrict__ rp,
    const float* __restrict__ gp, float* __restrict__ attn) {
    __shared__ float red[33];
    __shared__ float wsh[108], bsh[6], qsh[6];
    int bn = blockIdx.x; int b = bn >> 9, n = bn & 511;
    int m = threadIdx.x;
    if (m < 108) wsh[m] = conv_w[m];
    if (m < 6) { bsh[m] = conv_b[m]; qsh[m] = qn2[((b*6 + m) << 9) + n]; }
    float scale = *sp, rs = *rp, gs = *gp;
    __syncthreads();
    float mixed[6];
    #pragma unroll
    for (int o = 0; o < 6; o++) mixed[o] = bsh[o];
    #pragma unroll
    for (int h = 0; h < 6; h++) {
        long long idx = ((long long)((b*6 + h)*512 + n) << 9) + m;
        float qv = qk[idx];
        float dd = dots[idx];
        float e  = qv * scale;
        float qn = qsh[h];
        float kn = kn2[((b*6 + h) << 9) + m];
        float d2 = qn*qn + kn*kn - 2.f*qv*qv;
        float ri = sqrtf(fmaxf(d2, 0.f)) * rs;
        float gg = dd*dd * gs;
        #pragma unroll
        for (int o = 0; o < 6; o++)
            mixed[o] += wsh[o*18 + h]*e + wsh[o*18 + 6 + h]*ri + wsh[o*18 + 12 + h]*gg;
    }
    #pragma unroll
    for (int o = 0; o < 6; o++) {
        float mx = bred_max(mixed[o], red, 16);
        float e  = expf(mixed[o] - mx);
        float s  = bred_sum(e, red, 16);
        attn[((long long)((b*6 + o)*512 + n) << 9) + m] = e / s;
    }
}

// ================================================================================
extern "C" void kernel_launch(void* const* d_in, const int* in_sizes, int n_in,
                              void* d_out, int out_size) {
    const float* src     = (const float*)d_in[0];
    const float* pre_w   = (const float*)d_in[1];
    const float* pre_b   = (const float*)d_in[2];
    const float* qkv_w   = (const float*)d_in[3];
    const float* qkv_b   = (const float*)d_in[4];
    const float* scale_p = (const float*)d_in[5];
    const float* riem_p  = (const float*)d_in[6];
    const float* grass_p = (const float*)d_in[7];
    const float* conv_w  = (const float*)d_in[8];
    const float* conv_b  = (const float*)d_in[9];
    const float* proj_w  = (const float*)d_in[10];
    const float* proj_b  = (const float*)d_in[11];
    const float* n1_w    = (const float*)d_in[12];
    const float* n1_b    = (const float*)d_in[13];
    const float* l1_w    = (const float*)d_in[14];
    const float* l1_b    = (const float*)d_in[15];
    const float* l2_w    = (const float*)d_in[16];
    const float* l2_b    = (const float*)d_in[17];
    float* out = (float*)d_out;

    float *x, *qkv, *R, *RiT, *qgr, *kgr, *qn2, *kn2, *qk, *dots, *attn, *vT, *ao, *t, *u, *h1;
    cudaGetSymbolAddress((void**)&x,    g_x);
    cudaGetSymbolAddress((void**)&qkv,  g_qkv);
    cudaGetSymbolAddress((void**)&R,    g_R);
    cudaGetSymbolAddress((void**)&RiT,  g_RiT);
    cudaGetSymbolAddress((void**)&qgr,  g_qgr);
    cudaGetSymbolAddress((void**)&kgr,  g_kgr);
    cudaGetSymbolAddress((void**)&qn2,  g_qn2);
    cudaGetSymbolAddress((void**)&kn2,  g_kn2);
    cudaGetSymbolAddress((void**)&qk,   g_qk);
    cudaGetSymbolAddress((void**)&dots, g_dots);
    cudaGetSymbolAddress((void**)&attn, g_attn);
    cudaGetSymbolAddress((void**)&vT,   g_vT);
    cudaGetSymbolAddress((void**)&ao,   g_ao);
    cudaGetSymbolAddress((void**)&t,    g_t);
    cudaGetSymbolAddress((void**)&u,    g_u);
    cudaGetSymbolAddress((void**)&h1,   g_h1);

    const int SMEM_QR = 64 * QR_LDC * 4;
    cudaFuncSetAttribute(qr_forward, cudaFuncAttributeMaxDynamicSharedMemorySize, SMEM_QR);

    long long need = (long long)BN_*C_ + (long long)BH_*N_*N_;
    bool attn_in_out = ((long long)out_size >= need);
    float* attn_dst = attn_in_out ? (out + (long long)BN_*C_) : attn;

    // 1. pre-LN
    ln_kernel<<<BN_, 128>>>(src, pre_w, pre_b, x);
    // 2. QKV GEMM: [8192,384] @ [1152,384]^T + bias
    gemm_t<128,128,8,8><<<dim3(FF_/128, BN_/128, 1), 256>>>(x, qkv_w, nullptr, qkv_b, qkv,
        BN_, FF_, C_, C_, C_, FF_, 0,0,0,0,0,0, 1, 1);
    // 3. squared norms
    sumsq_kernel<<<(2*BH_*N_ + 255)/256, 256>>>(qkv, qn2, kn2);
    // 4. Householder factorization -> R (q: mats 0..95, k: 96..191)
    qr_forward<<<192, 512, SMEM_QR>>>(qkv, R);
    // 4b. invert R (transposed output for GEMM B operand)
    rinv_kernel<<<192, 64>>>(R, RiT);
    // 4c. qgr = q @ Rinv_q, kgr = k @ Rinv_k (batched 512x64x64)
    gemm_t<128,64,8,4><<<dim3(1, 4, 96), 256>>>(qkv, RiT, nullptr, nullptr, qgr,
        512, 64, 64, 1152, 64, 64,
        589824LL, 64LL, 24576LL, 4096LL, 196608LL, 32768LL, 6, 0);
    gemm_t<128,64,8,4><<<dim3(1, 4, 96), 256>>>(qkv + 384, RiT + 96LL*4096, nullptr, nullptr, kgr,
        512, 64, 64, 1152, 64, 64,
        589824LL, 64LL, 24576LL, 4096LL, 196608LL, 32768LL, 6, 0);
    // 5. qk = q @ k^T  (batched over 96)
    gemm_t<128,128,8,8><<<dim3(4, 4, 96), 256>>>(qkv, qkv + 384, nullptr, nullptr, qk,
        512, 512, 64, 1152, 1152, 512,
        589824LL, 64LL, 589824LL, 64LL, 1572864LL, 262144LL, 6, 0);
    // 6. dots = qgr @ kgr^T (batched)
    gemm_t<128,128,8,8><<<dim3(4, 4, 96), 256>>>(qgr, kgr, nullptr, nullptr, dots,
        512, 512, 64, 64, 64, 512,
        196608LL, 32768LL, 196608LL, 32768LL, 1572864LL, 262144LL, 6, 0);
    // 7. v transpose
    vT_kernel<<<(BH_*HD_*N_ + 255)/256, 256>>>(qkv, vT);
    // 8. mix + softmax -> attn
    mix_softmax<<<BN_, 512>>>(qk, dots, qn2, kn2, conv_w, conv_b,
                              scale_p, riem_p, grass_p, attn_dst);
    // 9. out = attn @ v  -> ao laid out [b,n,h*64+d]
    gemm_t<128,64,8,4><<<dim3(1, 4, 96), 256>>>(attn_dst, vT, nullptr, nullptr, ao,
        512, 64, 512, 512, 512, 384,
        1572864LL, 262144LL, 196608LL, 32768LL, 196608LL, 64LL, 6, 0);
    // 10. proj + residual(src) -> t
    gemm_t<128,128,8,8><<<dim3(C_/128, BN_/128, 1), 256>>>(ao, proj_w, src, proj_b, t,
        BN_, C_, C_, C_, C_, C_, 0,0,0,0,0,0, 1, 1|4);
    // 11. norm1 -> u
    ln_kernel<<<BN_, 128>>>(t, n1_w, n1_b, u);
    // 12. lin1 + gelu -> h1
    gemm_t<128,128,8,8><<<dim3(FF_/128, BN_/128, 1), 256>>>(u, l1_w, nullptr, l1_b, h1,
        BN_, FF_, C_, C_, C_, FF_, 0,0,0,0,0,0, 1, 1|2);
    // 13. lin2 + bias + residual(u) -> d_out (final src)
    gemm_t<128,128,8,8><<<dim3(C_/128, BN_/128, 1), 256>>>(h1, l2_w, u, l2_b, out,
        BN_, C_, FF_, FF_, FF_, C_, 0,0,0,0,0,0, 1, 1|4);
}

// round 9
// speedup vs baseline: 1.9544x; 1.5310x over previous
#include <cuda_runtime.h>
#include <cuda_bf16.h>
#include <math.h>
#include <stdint.h>

typedef __nv_bfloat16 bf16;

#define B_  16
#define N_  512
#define C_  384
#define H_  6
#define HD_ 64
#define FF_ 1152
#define BN_ (B_*N_)   // 8192
#define BH_ (B_*H_)   // 96

// ---------------- fp32 scratch --------------------------------------------------
__device__ __align__(16) float g_x   [BN_*C_];
__device__ __align__(16) float g_qkv [BN_*3*C_];
__device__ __align__(16) float g_R   [192*64*64];
__device__ __align__(16) float g_RiT [192*64*64];
__device__ __align__(16) float g_qgr [BH_*N_*HD_];
__device__ __align__(16) float g_kgr [BH_*N_*HD_];
__device__ __align__(16) float g_qn2 [BH_*N_];
__device__ __align__(16) float g_kn2 [BH_*N_];
__device__ __align__(16) float g_qk  [(long long)BH_*N_*N_];
__device__ __align__(16) float g_dots[(long long)BH_*N_*N_];
__device__ __align__(16) float g_attn[(long long)BH_*N_*N_];
__device__ __align__(16) float g_ao  [BN_*C_];
__device__ __align__(16) float g_t   [BN_*C_];
__device__ __align__(16) float g_u   [BN_*C_];
__device__ __align__(16) float g_h1  [BN_*FF_];

// ---------------- bf16 hi/lo operand pools --------------------------------------
__device__ __align__(16) bf16 sX_hi [BN_*C_],        sX_lo [BN_*C_];
__device__ __align__(16) bf16 sQW_hi[FF_*C_],        sQW_lo[FF_*C_];
__device__ __align__(16) bf16 sQ_hi [BH_*N_*HD_],    sQ_lo [BH_*N_*HD_];
__device__ __align__(16) bf16 sK_hi [BH_*N_*HD_],    sK_lo [BH_*N_*HD_];
__device__ __align__(16) bf16 sRi_hi[192*64*64],     sRi_lo[192*64*64];
__device__ __align__(16) bf16 sQg_hi[BH_*N_*HD_],    sQg_lo[BH_*N_*HD_];
__device__ __align__(16) bf16 sKg_hi[BH_*N_*HD_],    sKg_lo[BH_*N_*HD_];
__device__ __align__(16) bf16 sVT_hi[BH_*HD_*N_],    sVT_lo[BH_*HD_*N_];
__device__ __align__(16) bf16 sAt_hi[(long long)BH_*N_*N_], sAt_lo[(long long)BH_*N_*N_];
__device__ __align__(16) bf16 sAo_hi[BN_*C_],        sAo_lo[BN_*C_];
__device__ __align__(16) bf16 sPW_hi[C_*C_],         sPW_lo[C_*C_];
__device__ __align__(16) bf16 sU_hi [BN_*C_],        sU_lo [BN_*C_];
__device__ __align__(16) bf16 sL1_hi[FF_*C_],        sL1_lo[FF_*C_];
__device__ __align__(16) bf16 sH1_hi[BN_*FF_],       sH1_lo[BN_*FF_];
__device__ __align__(16) bf16 sL2_hi[C_*FF_],        sL2_lo[C_*FF_];

// ---------------- PTX helpers ---------------------------------------------------
__device__ __forceinline__ uint32_t smem_u32(const void* p) {
    uint32_t a;
    asm("{ .reg .u64 t; cvta.to.shared.u64 t, %1; cvt.u32.u64 %0, t; }" : "=r"(a) : "l"(p));
    return a;
}
__device__ __forceinline__ void cpa16(uint32_t s, const void* g) {
    asm volatile("cp.async.ca.shared.global [%0], [%1], 16;" :: "r"(s), "l"(g));
}
__device__ __forceinline__ void cpa_commit() {
    asm volatile("cp.async.commit_group;" ::: "memory");
}
__device__ __forceinline__ void cpa_wait1() {
    asm volatile("cp.async.wait_group 1;" ::: "memory");
}
__device__ __forceinline__ void ldsm4(uint32_t* r, uint32_t addr) {
    asm volatile("ldmatrix.sync.aligned.m8n8.x4.shared.b16 {%0,%1,%2,%3}, [%4];"
        : "=r"(r[0]), "=r"(r[1]), "=r"(r[2]), "=r"(r[3]) : "r"(addr));
}
__device__ __forceinline__ void mma_bf16(float* d, const uint32_t* a, uint32_t b0, uint32_t b1) {
    asm volatile("mma.sync.aligned.m16n8k16.row.col.f32.bf16.bf16.f32 "
        "{%0,%1,%2,%3}, {%4,%5,%6,%7}, {%8,%9}, {%0,%1,%2,%3};"
        : "+f"(d[0]), "+f"(d[1]), "+f"(d[2]), "+f"(d[3])
        : "r"(a[0]), "r"(a[1]), "r"(a[2]), "r"(a[3]), "r"(b0), "r"(b1));
}
__device__ __forceinline__ float gelu_f(float v) {
    return 0.5f * v * (1.f + erff(v * 0.70710678118654752f));
}
__device__ __forceinline__ void wsplit(float v, bf16& h, bf16& l) {
    h = __float2bfloat16(v);
    l = __float2bfloat16(v - __bfloat162float(h));
}

// ---------------- block reductions ----------------------------------------------
__device__ __forceinline__ float bred_sum(float v, float* red, int nw) {
    int lane = threadIdx.x & 31, wid = threadIdx.x >> 5;
    #pragma unroll
    for (int o = 16; o; o >>= 1) v += __shfl_xor_sync(0xffffffffu, v, o);
    if (lane == 0) red[wid] = v;
    __syncthreads();
    if (wid == 0) {
        float t = (lane < nw) ? red[lane] : 0.f;
        #pragma unroll
        for (int o = 16; o; o >>= 1) t += __shfl_xor_sync(0xffffffffu, t, o);
        if (lane == 0) red[32] = t;
    }
    __syncthreads();
    float r = red[32];
    __syncthreads();
    return r;
}
__device__ __forceinline__ float bred_max(float v, float* red, int nw) {
    int lane = threadIdx.x & 31, wid = threadIdx.x >> 5;
    #pragma unroll
    for (int o = 16; o; o >>= 1) v = fmaxf(v, __shfl_xor_sync(0xffffffffu, v, o));
    if (lane == 0) red[wid] = v;
    __syncthreads();
    if (wid == 0) {
        float t = (lane < nw) ? red[lane] : -INFINITY;
        #pragma unroll
        for (int o = 16; o; o >>= 1) t = fmaxf(t, __shfl_xor_sync(0xffffffffu, t, o));
        if (lane == 0) red[32] = t;
    }
    __syncthreads();
    float r = red[32];
    __syncthreads();
    return r;
}

// ---------------- LayerNorm (writes fp32 + bf16 hi/lo) --------------------------
__global__ __launch_bounds__(128) void ln_kernel(
    const float* __restrict__ in, const float* __restrict__ w,
    const float* __restrict__ b, float* __restrict__ out,
    bf16* __restrict__ ohi, bf16* __restrict__ olo) {
    __shared__ float red[33];
    int row = blockIdx.x;
    const float* x = in + (long long)row * C_;
    float v0[3]; float s = 0.f;
    #pragma unroll
    for (int i = 0; i < 3; i++) { v0[i] = x[threadIdx.x + 128*i]; s += v0[i]; }
    s = bred_sum(s, red, 4);
    float mu = s * (1.f / C_);
    float var = 0.f;
    #pragma unroll
    for (int i = 0; i < 3; i++) { float d = v0[i] - mu; var = fmaf(d, d, var); }
    var = bred_sum(var, red, 4) * (1.f / C_);
    float inv = rsqrtf(var + 1e-5f);
    #pragma unroll
    for (int i = 0; i < 3; i++) {
        int c = threadIdx.x + 128*i;
        float v = (v0[i] - mu) * inv * w[c] + b[c];
        long long idx = (long long)row*C_ + c;
        out[idx] = v;
        bf16 h, l; wsplit(v, h, l);
        ohi[idx] = h; olo[idx] = l;
    }
}

// ---------------- generic fp32 -> bf16 hi/lo split ------------------------------
__global__ void split_kernel(const float* __restrict__ src,
                             bf16* __restrict__ hi, bf16* __restrict__ lo,
                             long long total, int Cc, int ld, int RperZ,
                             long long Ab, long long Ah, int Hdiv) {
    long long i = (long long)blockIdx.x * blockDim.x + threadIdx.x;
    if (i >= total) return;
    int c = (int)(i % Cc);
    long long rz = i / Cc;
    int r = (int)(rz % RperZ);
    int z = (int)(rz / RperZ);
    float v = src[(long long)(z / Hdiv)*Ab + (long long)(z % Hdiv)*Ah + (long long)r*ld + c];
    bf16 h, l; wsplit(v, h, l);
    hi[i] = h; lo[i] = l;
}

// ---------------- bf16-split tensor-core GEMM: C = A * B^T ----------------------
// A packed [Z][M][K] bf16 hi/lo (lda=K), B packed [Z][N][K] (ldb=K).
// BM=128, BN template, BK=32. 256 threads = 8 warps (4 M x 2 N).
// flags: 1=bias, 2=gelu, 4=residual(Rres), 8=also write bf16 hi/lo (Whi/Wlo).
template<int BN>
__global__ __launch_bounds__(256) void mma_gemm(
    const bf16* __restrict__ Ahi, const bf16* __restrict__ Alo,
    const bf16* __restrict__ Bhi, const bf16* __restrict__ Blo,
    const float* __restrict__ Rres, const float* __restrict__ bias,
    float* __restrict__ Cout, bf16* __restrict__ Whi, bf16* __restrict__ Wlo,
    int K, int ldc, long long sA, long long sB,
    long long Cb, long long Ch, int Hdiv, int flags)
{
    constexpr int WN  = BN / 2;       // warp n-tile
    constexpr int NT  = WN / 16;      // n16 groups per warp
    constexpr int NF  = WN / 8;       // n8 fragments per warp
    constexpr int ATB = 128*40*2;     // bytes of one A half (hi or lo) per stage
    constexpr int BTB = BN*40*2;
    constexpr int STG = 2*ATB + 2*BTB;

    extern __shared__ __align__(16) bf16 dyn[];
    uint32_t sbase = smem_u32(dyn);

    int z = blockIdx.z;
    const bf16* pAhi = Ahi + (long long)z*sA;
    const bf16* pAlo = Alo + (long long)z*sA;
    const bf16* pBhi = Bhi + (long long)z*sB;
    const bf16* pBlo = Blo + (long long)z*sB;
    int zb = z / Hdiv, zh = z - zb*Hdiv;
    long long co = Cb*zb + Ch*zh;

    int m0 = blockIdx.y << 7, n0 = blockIdx.x * BN;
    int tid = threadIdx.x, wid = tid >> 5, lane = tid & 31;
    int wm = wid >> 1, wn = wid & 1;
    int r16 = lane & 15, kh = lane >> 4;

    float acc[2][NF][4];
    #pragma unroll
    for (int a = 0; a < 2; a++)
        #pragma unroll
        for (int f = 0; f < NF; f++)
            #pragma unroll
            for (int q = 0; q < 4; q++) acc[a][f][q] = 0.f;

    int kt = K >> 5;

    // --- loader: issue cp.asyncs for k-tile t into stage t%3 (no commit) ---
    auto load_tile = [&](int t) {
        int s = t % 3;
        uint32_t ab = sbase + (uint32_t)(s * STG);
        int k0 = t << 5;
        #pragma unroll
        for (int i = tid; i < 128*4; i += 256) {
            int r = i >> 2, c = i & 3;
            uint32_t so = ab + (uint32_t)((r*40 + c*8) * 2);
            const bf16* ga = pAhi + (long long)(m0 + r)*K + k0 + c*8;
            cpa16(so, ga);
            cpa16(so + ATB, pAlo + (long long)(m0 + r)*K + k0 + c*8);
        }
        uint32_t bbb = sbase + (uint32_t)(s * STG) + 2*ATB;
        #pragma unroll
        for (int i = tid; i < BN*4; i += 256) {
            int r = i >> 2, c = i & 3;
            uint32_t so = bbb + (uint32_t)((r*40 + c*8) * 2);
            cpa16(so, pBhi + (long long)(n0 + r)*K + k0 + c*8);
            cpa16(so + BTB, pBlo + (long long)(n0 + r)*K + k0 + c*8);
        }
    };

    load_tile(0); cpa_commit();
    if (kt > 1) load_tile(1);
    cpa_commit();

    for (int t = 0; t < kt; t++) {
        cpa_wait1();
        __syncthreads();
        if (t + 2 < kt) load_tile(t + 2);
        cpa_commit();

        int s = t % 3;
        uint32_t ab = sbase + (uint32_t)(s * STG);
        uint32_t bb = ab + 2*ATB;
        #pragma unroll
        for (int kk = 0; kk < 2; kk++) {
            uint32_t a_hi[2][4], a_lo[2][4];
            #pragma unroll
            for (int mt = 0; mt < 2; mt++) {
                uint32_t ad = ab + (uint32_t)(((wm*32 + mt*16 + r16)*40 + kk*16 + kh*8) * 2);
                ldsm4(a_hi[mt], ad);
                ldsm4(a_lo[mt], ad + ATB);
            }
            #pragma unroll
            for (int nt = 0; nt < NT; nt++) {
                uint32_t bh[4], bl[4];
                uint32_t bd = bb + (uint32_t)(((wn*WN + nt*16 + r16)*40 + kk*16 + kh*8) * 2);
                ldsm4(bh, bd);
                ldsm4(bl, bd + BTB);
                #pragma unroll
                for (int mt = 0; mt < 2; mt++) {
                    float* c0 = acc[mt][2*nt];
                    float* c1 = acc[mt][2*nt + 1];
                    mma_bf16(c0, a_hi[mt], bh[0], bh[2]);
                    mma_bf16(c0, a_hi[mt], bl[0], bl[2]);
                    mma_bf16(c0, a_lo[mt], bh[0], bh[2]);
                    mma_bf16(c1, a_hi[mt], bh[1], bh[3]);
                    mma_bf16(c1, a_hi[mt], bl[1], bl[3]);
                    mma_bf16(c1, a_lo[mt], bh[1], bh[3]);
                }
            }
        }
    }

    // --- epilogue ---
    #pragma unroll
    for (int mt = 0; mt < 2; mt++)
    #pragma unroll
    for (int f = 0; f < NF; f++) {
        float* c = acc[mt][f];
        int row = m0 + wm*32 + mt*16 + (lane >> 2);
        int col = n0 + wn*WN + f*8 + ((lane & 3) << 1);
        #pragma unroll
        for (int half = 0; half < 2; half++) {
            int r = row + half*8;
            float v0 = c[half*2 + 0], v1 = c[half*2 + 1];
            if (flags & 1) { v0 += bias[col]; v1 += bias[col + 1]; }
            if (flags & 2) { v0 = gelu_f(v0); v1 = gelu_f(v1); }
            long long idx = co + (long long)r*ldc + col;
            if (flags & 4) {
                float2 rr = *(const float2*)(Rres + idx);
                v0 += rr.x; v1 += rr.y;
            }
            float2 o; o.x = v0; o.y = v1;
            *(float2*)(Cout + idx) = o;
            if (flags & 8) {
                bf16 h0, l0, h1, l1;
                wsplit(v0, h0, l0); wsplit(v1, h1, l1);
                __nv_bfloat162 hh; hh.x = h0; hh.y = h1;
                __nv_bfloat162 ll; ll.x = l0; ll.y = l1;
                *(__nv_bfloat162*)(Whi + idx) = hh;
                *(__nv_bfloat162*)(Wlo + idx) = ll;
            }
        }
    }
}

// ---------------- per-(b,h,n) squared norms of q,k ------------------------------
__global__ void sumsq_kernel(const float* __restrict__ qkv,
                             float* __restrict__ qn2, float* __restrict__ kn2) {
    int i = blockIdx.x * blockDim.x + threadIdx.x;
    if (i >= 2*BH_*N_) return;
    int which = i / (BH_*N_);
    int bhn = i - which*(BH_*N_);
    int bh = bhn >> 9, n = bhn & 511;
    int b = bh / 6, h = bh - (bh/6)*6;
    const float* p = qkv + (long long)(b*512 + n)*1152 + which*384 + h*64;
    float s = 0.f;
    #pragma unroll
    for (int d = 0; d < 64; d++) s = fmaf(p[d], p[d], s);
    if (which) kn2[bhn] = s; else qn2[bhn] = s;
}

// ---------------- v transpose -> bf16 hi/lo: vT[b,h,d,m] = v[b,h,m,d] -----------
__global__ void vT_bf16_kernel(const float* __restrict__ qkv,
                               bf16* __restrict__ hi, bf16* __restrict__ lo) {
    int i = blockIdx.x * blockDim.x + threadIdx.x;
    if (i >= BH_*HD_*N_) return;
    int m = i & 511;
    int d = (i >> 9) & 63;
    int bh = i >> 15;
    int b = bh / 6, h = bh - (bh/6)*6;
    float v = qkv[(long long)(b*512 + m)*1152 + 768 + h*64 + d];
    bf16 h_, l_; wsplit(v, h_, l_);
    hi[i] = h_; lo[i] = l_;
}

// ---------------- Householder QR factorization (sgeqr2, in place) ---------------
#define QR_LDC 513
__global__ __launch_bounds__(512) void qr_forward(const float* __restrict__ qkv,
                                                  float* __restrict__ R_out) {
    extern __shared__ float As[];
    __shared__ float red[33];
    __shared__ float sbeta[64];
    __shared__ float s_ss[2];
    int mat = blockIdx.x;
    int s = (mat >= 96) ? 1 : 0;
    int bh = mat - s*96;
    int b = bh / 6, h = bh - (bh/6)*6;
    const float* Ab = qkv + (long long)b*512*1152 + s*384 + h*64;
    int tid = threadIdx.x;
    int wid = tid >> 5, lane = tid & 31;

    for (int i = tid; i < 64*512; i += 512) {
        int n = i >> 6, d = i & 63;
        As[d*QR_LDC + n] = Ab[(long long)n*1152 + d];
    }
    __syncthreads();
    {
        float x = (tid > 0) ? As[tid] : 0.f;
        float ss0 = bred_sum(x*x, red, 16);
        if (tid == 0) s_ss[0] = ss0;
    }
    __syncthreads();

    for (int j = 0; j < 64; j++) {
        float* col = As + j*QR_LDC;
        float alpha = col[j];
        float ss = s_ss[j & 1];
        float beta, teff, uj;
        if (ss == 0.f) { beta = alpha; teff = 0.f; uj = 1.f; }
        else {
            float nrm = sqrtf(alpha*alpha + ss);
            beta = (alpha >= 0.f) ? -nrm : nrm;   // LAPACK sign
            float tau = (beta - alpha) / beta;
            uj  = alpha - beta;
            teff = tau / (uj * uj);
        }
        if (tid == 0) sbeta[j] = beta;
        float u[16];
        #pragma unroll
        for (int t = 0; t < 16; t++) {
            int r = lane + 32*t;
            u[t] = (r > j) ? col[r] : ((r == j) ? uj : 0.f);
        }
        for (int c = j + 1 + wid; c < 64; c += 16) {
            float* cc = As + c*QR_LDC;
            float w = 0.f;
            #pragma unroll
            for (int t = 0; t < 16; t++)
                w = fmaf(u[t], cc[lane + 32*t], w);
            #pragma unroll
            for (int o = 16; o; o >>= 1) w += __shfl_xor_sync(0xffffffffu, w, o);
            float tw = teff * w;
            if (c == j + 1) {
                float nss = 0.f;
                #pragma unroll
                for (int t = 0; t < 16; t++) {
                    int r = lane + 32*t;
                    float nv = cc[r] - tw * u[t];
                    cc[r] = nv;
                    if (r > j + 1) nss = fmaf(nv, nv, nss);
                }
                #pragma unroll
                for (int o = 16; o; o >>= 1) nss += __shfl_xor_sync(0xffffffffu, nss, o);
                if (lane == 0) s_ss[(j + 1) & 1] = nss;
            } else {
                #pragma unroll
                for (int t = 0; t < 16; t++) {
                    int r = lane + 32*t;
                    cc[r] -= tw * u[t];
                }
            }
        }
        __syncthreads();
    }
    for (int i = tid; i < 4096; i += 512) {
        int c = i >> 6, r = i & 63;
        float v = (r < c) ? As[c*QR_LDC + r] : ((r == c) ? sbeta[c] : 0.f);
        R_out[(long long)mat*4096 + i] = v;
    }
}

// ---------------- invert upper-triangular R; transposed output ------------------
__global__ __launch_bounds__(64) void rinv_kernel(const float* __restrict__ R,
                                                  float* __restrict__ RiT) {
    __shared__ float Rs[4096];
    __shared__ float xs[64*65];
    int mat = blockIdx.x, tid = threadIdx.x;
    for (int i = tid; i < 4096; i += 64) Rs[i] = R[(long long)mat*4096 + i];
    __syncthreads();
    int c = tid;
    float* x = xs + c*65;
    for (int i = c; i >= 0; i--) {
        float sacc = (i == c) ? 1.f : 0.f;
        for (int k = i + 1; k <= c; k++)
            sacc = fmaf(-Rs[k*64 + i], x[k], sacc);
        x[i] = sacc / Rs[i*64 + i];
    }
    for (int k = 0; k < 64; k++)
        RiT[(long long)mat*4096 + c*64 + k] = (k <= c) ? x[k] : 0.f;
}

// ---------------- fused head-mix + softmax (writes fp32 + bf16 hi/lo) -----------
__global__ __launch_bounds__(512) void mix_softmax(
    const float* __restrict__ qk, const float* __restrict__ dots,
    const float* __restrict__ qn2, const float* __restrict__ kn2,
    const float* __restrict__ conv_w, const float* __restrict__ conv_b,
    const float* __restrict__ sp, const float* __restrict__ rp,
    const float* __restrict__ gp, float* __restrict__ attn,
    bf16* __restrict__ ahi, bf16* __restrict__ alo) {
    __shared__ float red[33];
    __shared__ float wsh[108], bsh[6], qsh[6];
    int bn = blockIdx.x; int b = bn >> 9, n = bn & 511;
    int m = threadIdx.x;
    if (m < 108) wsh[m] = conv_w[m];
    if (m < 6) { bsh[m] = conv_b[m]; qsh[m] = qn2[((b*6 + m) << 9) + n]; }
    float scale = *sp, rs = *rp, gs = *gp;
    __syncthreads();
    float mixed[6];
    #pragma unroll
    for (int o = 0; o < 6; o++) mixed[o] = bsh[o];
    #pragma unroll
    for (int h = 0; h < 6; h++) {
        long long idx = ((long long)((b*6 + h)*512 + n) << 9) + m;
        float qv = qk[idx];
        float dd = dots[idx];
        float e  = qv * scale;
        float qn = qsh[h];
        float kn = kn2[((b*6 + h) << 9) + m];
        float d2 = qn*qn + kn*kn - 2.f*qv*qv;
        float ri = sqrtf(fmaxf(d2, 0.f)) * rs;
        float gg = dd*dd * gs;
        #pragma unroll
        for (int o = 0; o < 6; o++)
            mixed[o] += wsh[o*18 + h]*e + wsh[o*18 + 6 + h]*ri + wsh[o*18 + 12 + h]*gg;
    }
    #pragma unroll
    for (int o = 0; o < 6; o++) {
        float mx = bred_max(mixed[o], red, 16);
        float e  = expf(mixed[o] - mx);
        float s  = bred_sum(e, red, 16);
        float v  = e / s;
        long long idx = ((long long)((b*6 + o)*512 + n) << 9) + m;
        attn[idx] = v;
        bf16 h_, l_; wsplit(v, h_, l_);
        ahi[idx] = h_; alo[idx] = l_;
    }
}

// ================================================================================
extern "C" void kernel_launch(void* const* d_in, const int* in_sizes, int n_in,
                              void* d_out, int out_size) {
    const float* src     = (const float*)d_in[0];
    const float* pre_w   = (const float*)d_in[1];
    const float* pre_b   = (const float*)d_in[2];
    const float* qkv_w   = (const float*)d_in[3];
    const float* qkv_b   = (const float*)d_in[4];
    const float* scale_p = (const float*)d_in[5];
    const float* riem_p  = (const float*)d_in[6];
    const float* grass_p = (const float*)d_in[7];
    const float* conv_w  = (const float*)d_in[8];
    const float* conv_b  = (const float*)d_in[9];
    const float* proj_w  = (const float*)d_in[10];
    const float* proj_b  = (const float*)d_in[11];
    const float* n1_w    = (const float*)d_in[12];
    const float* n1_b    = (const float*)d_in[13];
    const float* l1_w    = (const float*)d_in[14];
    const float* l1_b    = (const float*)d_in[15];
    const float* l2_w    = (const float*)d_in[16];
    const float* l2_b    = (const float*)d_in[17];
    float* out = (float*)d_out;

    float *x, *qkv, *R, *RiT, *qgr, *kgr, *qn2, *kn2, *qk, *dots, *attn, *ao, *t, *u, *h1;
    cudaGetSymbolAddress((void**)&x,    g_x);
    cudaGetSymbolAddress((void**)&qkv,  g_qkv);
    cudaGetSymbolAddress((void**)&R,    g_R);
    cudaGetSymbolAddress((void**)&RiT,  g_RiT);
    cudaGetSymbolAddress((void**)&qgr,  g_qgr);
    cudaGetSymbolAddress((void**)&kgr,  g_kgr);
    cudaGetSymbolAddress((void**)&qn2,  g_qn2);
    cudaGetSymbolAddress((void**)&kn2,  g_kn2);
    cudaGetSymbolAddress((void**)&qk,   g_qk);
    cudaGetSymbolAddress((void**)&dots, g_dots);
    cudaGetSymbolAddress((void**)&attn, g_attn);
    cudaGetSymbolAddress((void**)&ao,   g_ao);
    cudaGetSymbolAddress((void**)&t,    g_t);
    cudaGetSymbolAddress((void**)&u,    g_u);
    cudaGetSymbolAddress((void**)&h1,   g_h1);

    bf16 *xh,*xl,*qwh,*qwl,*qh,*ql,*kh,*kl,*rih,*ril,*qgh,*qgl,*kgh,*kgl,
         *vth,*vtl,*ath,*atl,*aoh,*aol,*pwh,*pwl,*uh,*ul,*l1h,*l1l,*h1h,*h1l,*l2h,*l2l;
    cudaGetSymbolAddress((void**)&xh,  sX_hi);  cudaGetSymbolAddress((void**)&xl,  sX_lo);
    cudaGetSymbolAddress((void**)&qwh, sQW_hi); cudaGetSymbolAddress((void**)&qwl, sQW_lo);
    cudaGetSymbolAddress((void**)&qh,  sQ_hi);  cudaGetSymbolAddress((void**)&ql,  sQ_lo);
    cudaGetSymbolAddress((void**)&kh,  sK_hi);  cudaGetSymbolAddress((void**)&kl,  sK_lo);
    cudaGetSymbolAddress((void**)&rih, sRi_hi); cudaGetSymbolAddress((void**)&ril, sRi_lo);
    cudaGetSymbolAddress((void**)&qgh, sQg_hi); cudaGetSymbolAddress((void**)&qgl, sQg_lo);
    cudaGetSymbolAddress((void**)&kgh, sKg_hi); cudaGetSymbolAddress((void**)&kgl, sKg_lo);
    cudaGetSymbolAddress((void**)&vth, sVT_hi); cudaGetSymbolAddress((void**)&vtl, sVT_lo);
    cudaGetSymbolAddress((void**)&ath, sAt_hi); cudaGetSymbolAddress((void**)&atl, sAt_lo);
    cudaGetSymbolAddress((void**)&aoh, sAo_hi); cudaGetSymbolAddress((void**)&aol, sAo_lo);
    cudaGetSymbolAddress((void**)&pwh, sPW_hi); cudaGetSymbolAddress((void**)&pwl, sPW_lo);
    cudaGetSymbolAddress((void**)&uh,  sU_hi);  cudaGetSymbolAddress((void**)&ul,  sU_lo);
    cudaGetSymbolAddress((void**)&l1h, sL1_hi); cudaGetSymbolAddress((void**)&l1l, sL1_lo);
    cudaGetSymbolAddress((void**)&h1h, sH1_hi); cudaGetSymbolAddress((void**)&h1l, sH1_lo);
    cudaGetSymbolAddress((void**)&l2h, sL2_hi); cudaGetSymbolAddress((void**)&l2l, sL2_lo);

    const int SMEM_QR = 64 * QR_LDC * 4;
    const int SMG128 = 3 * (2*128*40*2 + 2*128*40*2);   // 122880
    const int SMG64  = 3 * (2*128*40*2 + 2*64*40*2);    //  92160
    cudaFuncSetAttribute(qr_forward,    cudaFuncAttributeMaxDynamicSharedMemorySize, SMEM_QR);
    cudaFuncSetAttribute(mma_gemm<128>, cudaFuncAttributeMaxDynamicSharedMemorySize, SMG128);
    cudaFuncSetAttribute(mma_gemm<64>,  cudaFuncAttributeMaxDynamicSharedMemorySize, SMG64);

    long long need = (long long)BN_*C_ + (long long)BH_*N_*N_;
    bool attn_in_out = ((long long)out_size >= need);
    float* attn_dst = attn_in_out ? (out + (long long)BN_*C_) : attn;

    // 1. pre-LN -> x fp32 + bf16
    ln_kernel<<<BN_, 128>>>(src, pre_w, pre_b, x, xh, xl);
    // 1b. split qkv_w
    {
        long long tot = (long long)FF_*C_;
        split_kernel<<<(int)((tot + 255)/256), 256>>>(qkv_w, qwh, qwl, tot, C_, C_, FF_, 0, 0, 1);
    }
    // 2. QKV GEMM (M=8192, N=1152, K=384) + bias -> qkv fp32
    mma_gemm<128><<<dim3(9, 64, 1), 256, SMG128>>>(xh, xl, qwh, qwl, nullptr, qkv_b,
        qkv, nullptr, nullptr, C_, FF_, 0, 0, 0, 0, 1, 1);
    // 3. squared norms
    sumsq_kernel<<<(2*BH_*N_ + 255)/256, 256>>>(qkv, qn2, kn2);
    // 4. Householder factorization -> R ; invert -> RiT
    qr_forward<<<192, 512, SMEM_QR>>>(qkv, R);
    rinv_kernel<<<192, 64>>>(R, RiT);
    // 4a. split q, k (strided from qkv), RiT (contiguous)
    {
        long long tq = (long long)BH_*N_*HD_;
        split_kernel<<<(int)((tq + 255)/256), 256>>>(qkv, qh, ql, tq, 64, 1152, 512, 589824LL, 64LL, 6);
        split_kernel<<<(int)((tq + 255)/256), 256>>>(qkv + 384, kh, kl, tq, 64, 1152, 512, 589824LL, 64LL, 6);
        long long tr = 192LL*64*64;
        split_kernel<<<(int)((tr + 255)/256), 256>>>(RiT, rih, ril, tr, 64, 64, 12288, 0, 0, 1);
    }
    // 4b. qgr = q @ Rinv_q ; kgr = k @ Rinv_k  (512x64x64, z=96) -> bf16 via flag 8
    mma_gemm<64><<<dim3(1, 4, 96), 256, SMG64>>>(qh, ql, rih, ril, nullptr, nullptr,
        qgr, qgh, qgl, 64, 64, 32768LL, 4096LL, 32768LL, 0, 1, 8);
    mma_gemm<64><<<dim3(1, 4, 96), 256, SMG64>>>(kh, kl, rih + 96LL*4096, ril + 96LL*4096,
        nullptr, nullptr, kgr, kgh, kgl, 64, 64, 32768LL, 4096LL, 32768LL, 0, 1, 8);
    // 5. qk = q @ k^T (512x512x64, z=96)
    mma_gemm<128><<<dim3(4, 4, 96), 256, SMG128>>>(qh, ql, kh, kl, nullptr, nullptr,
        qk, nullptr, nullptr, 64, 512, 32768LL, 32768LL, 262144LL, 0, 1, 0);
    // 6. dots = qgr @ kgr^T
    mma_gemm<128><<<dim3(4, 4, 96), 256, SMG128>>>(qgh, qgl, kgh, kgl, nullptr, nullptr,
        dots, nullptr, nullptr, 64, 512, 32768LL, 32768LL, 262144LL, 0, 1, 0);
    // 7. v transpose -> bf16
    vT_bf16_kernel<<<(BH_*HD_*N_ + 255)/256, 256>>>(qkv, vth, vtl);
    // 8. mix + softmax -> attn fp32 + bf16
    mix_softmax<<<BN_, 512>>>(qk, dots, qn2, kn2, conv_w, conv_b,
                              scale_p, riem_p, grass_p, attn_dst, ath, atl);
    // 9. ao = attn @ v (512x64x512, z=96), C strided into [b,n,h*64+d] -> bf16 too
    mma_gemm<64><<<dim3(1, 4, 96), 256, SMG64>>>(ath, atl, vth, vtl, nullptr, nullptr,
        ao, aoh, aol, 512, 384, 262144LL, 32768LL, 196608LL, 64LL, 6, 8);
    // 9b. split proj_w
    {
        long long tp = (long long)C_*C_;
        split_kernel<<<(int)((tp + 255)/256), 256>>>(proj_w, pwh, pwl, tp, C_, C_, C_, 0, 0, 1);
    }
    // 10. proj + bias + residual(src) -> t
    mma_gemm<128><<<dim3(3, 64, 1), 256, SMG128>>>(aoh, aol, pwh, pwl, src, proj_b,
        t, nullptr, nullptr, C_, C_, 0, 0, 0, 0, 1, 1|4);
    // 11. norm1 -> u fp32 + bf16
    ln_kernel<<<BN_, 128>>>(t, n1_w, n1_b, u, uh, ul);
    // 11b. split l1_w, l2_w
    {
        long long t1 = (long long)FF_*C_;
        split_kernel<<<(int)((t1 + 255)/256), 256>>>(l1_w, l1h, l1l, t1, C_, C_, FF_, 0, 0, 1);
        long long t2 = (long long)C_*FF_;
        split_kernel<<<(int)((t2 + 255)/256), 256>>>(l2_w, l2h, l2l, t2, FF_, FF_, C_, 0, 0, 1);
    }
    // 12. lin1 + bias + gelu -> h1 (bf16 via flag 8)
    mma_gemm<128><<<dim3(9, 64, 1), 256, SMG128>>>(uh, ul, l1h, l1l, nullptr, l1_b,
        h1, h1h, h1l, C_, FF_, 0, 0, 0, 0, 1, 1|2|8);
    // 13. lin2 + bias + residual(u) -> d_out
    mma_gemm<128><<<dim3(3, 64, 1), 256, SMG128>>>(h1h, h1l, l2h, l2l, u, l2_b,
        out, nullptr, nullptr, FF_, C_, 0, 0, 0, 0, 1, 1|4);
}

// round 10
// speedup vs baseline: 2.3028x; 1.1783x over previous
#include <cuda_runtime.h>
#include <cuda_bf16.h>
#include <math.h>
#include <stdint.h>

typedef __nv_bfloat16 bf16;

#define B_  16
#define N_  512
#define C_  384
#define H_  6
#define HD_ 64
#define FF_ 1152
#define BN_ (B_*N_)   // 8192
#define BH_ (B_*H_)   // 96

// ---------------- fp32 scratch --------------------------------------------------
__device__ __align__(16) float g_x   [BN_*C_];
__device__ __align__(16) float g_qkv [BN_*3*C_];
__device__ __align__(16) float g_R   [192*64*64];
__device__ __align__(16) float g_RiT [192*64*64];
__device__ __align__(16) float g_qgr [2*BH_*N_*HD_];   // [q;k] grassmann fp32 sink
__device__ __align__(16) float g_qn2 [BH_*N_];
__device__ __align__(16) float g_kn2 [BH_*N_];
__device__ __align__(16) float g_qk  [(long long)BH_*N_*N_];
__device__ __align__(16) float g_dots[(long long)BH_*N_*N_];
__device__ __align__(16) float g_attn[(long long)BH_*N_*N_];
__device__ __align__(16) float g_ao  [BN_*C_];
__device__ __align__(16) float g_t   [BN_*C_];
__device__ __align__(16) float g_u   [BN_*C_];
__device__ __align__(16) float g_h1  [BN_*FF_];

// ---------------- bf16 hi/lo operand pools --------------------------------------
__device__ __align__(16) bf16 sX_hi [BN_*C_],        sX_lo [BN_*C_];
__device__ __align__(16) bf16 sQW_hi[FF_*C_],        sQW_lo[FF_*C_];
__device__ __align__(16) bf16 sQK_hi[2*BH_*N_*HD_],  sQK_lo[2*BH_*N_*HD_];  // [q;k]
__device__ __align__(16) bf16 sRi_hi[192*64*64],     sRi_lo[192*64*64];
__device__ __align__(16) bf16 sQg_hi[2*BH_*N_*HD_],  sQg_lo[2*BH_*N_*HD_];  // [qgr;kgr]
__device__ __align__(16) bf16 sVT_hi[BH_*HD_*N_],    sVT_lo[BH_*HD_*N_];
__device__ __align__(16) bf16 sAt_hi[(long long)BH_*N_*N_], sAt_lo[(long long)BH_*N_*N_];
__device__ __align__(16) bf16 sAo_hi[BN_*C_],        sAo_lo[BN_*C_];
__device__ __align__(16) bf16 sPW_hi[C_*C_],         sPW_lo[C_*C_];
__device__ __align__(16) bf16 sU_hi [BN_*C_],        sU_lo [BN_*C_];
__device__ __align__(16) bf16 sL1_hi[FF_*C_],        sL1_lo[FF_*C_];
__device__ __align__(16) bf16 sH1_hi[BN_*FF_],       sH1_lo[BN_*FF_];
__device__ __align__(16) bf16 sL2_hi[C_*FF_],        sL2_lo[C_*FF_];

// ---------------- PTX helpers ---------------------------------------------------
__device__ __forceinline__ uint32_t smem_u32(const void* p) {
    uint32_t a;
    asm("{ .reg .u64 t; cvta.to.shared.u64 t, %1; cvt.u32.u64 %0, t; }" : "=r"(a) : "l"(p));
    return a;
}
__device__ __forceinline__ void cpa16(uint32_t s, const void* g) {
    asm volatile("cp.async.ca.shared.global [%0], [%1], 16;" :: "r"(s), "l"(g));
}
__device__ __forceinline__ void cpa_commit() {
    asm volatile("cp.async.commit_group;" ::: "memory");
}
__device__ __forceinline__ void cpa_wait1() {
    asm volatile("cp.async.wait_group 1;" ::: "memory");
}
__device__ __forceinline__ void ldsm4(uint32_t* r, uint32_t addr) {
    asm volatile("ldmatrix.sync.aligned.m8n8.x4.shared.b16 {%0,%1,%2,%3}, [%4];"
        : "=r"(r[0]), "=r"(r[1]), "=r"(r[2]), "=r"(r[3]) : "r"(addr));
}
__device__ __forceinline__ void mma_bf16(float* d, const uint32_t* a, uint32_t b0, uint32_t b1) {
    asm volatile("mma.sync.aligned.m16n8k16.row.col.f32.bf16.bf16.f32 "
        "{%0,%1,%2,%3}, {%4,%5,%6,%7}, {%8,%9}, {%0,%1,%2,%3};"
        : "+f"(d[0]), "+f"(d[1]), "+f"(d[2]), "+f"(d[3])
        : "r"(a[0]), "r"(a[1]), "r"(a[2]), "r"(a[3]), "r"(b0), "r"(b1));
}
__device__ __forceinline__ float gelu_f(float v) {
    return 0.5f * v * (1.f + erff(v * 0.70710678118654752f));
}
__device__ __forceinline__ void wsplit(float v, bf16& h, bf16& l) {
    h = __float2bfloat16(v);
    l = __float2bfloat16(v - __bfloat162float(h));
}

// ---------------- block reductions (used by LN) ---------------------------------
__device__ __forceinline__ float bred_sum(float v, float* red, int nw) {
    int lane = threadIdx.x & 31, wid = threadIdx.x >> 5;
    #pragma unroll
    for (int o = 16; o; o >>= 1) v += __shfl_xor_sync(0xffffffffu, v, o);
    if (lane == 0) red[wid] = v;
    __syncthreads();
    if (wid == 0) {
        float t = (lane < nw) ? red[lane] : 0.f;
        #pragma unroll
        for (int o = 16; o; o >>= 1) t += __shfl_xor_sync(0xffffffffu, t, o);
        if (lane == 0) red[32] = t;
    }
    __syncthreads();
    float r = red[32];
    __syncthreads();
    return r;
}

// ---------------- LayerNorm (writes fp32 + bf16 hi/lo) --------------------------
__global__ __launch_bounds__(128) void ln_kernel(
    const float* __restrict__ in, const float* __restrict__ w,
    const float* __restrict__ b, float* __restrict__ out,
    bf16* __restrict__ ohi, bf16* __restrict__ olo) {
    __shared__ float red[33];
    int row = blockIdx.x;
    const float* x = in + (long long)row * C_;
    float v0[3]; float s = 0.f;
    #pragma unroll
    for (int i = 0; i < 3; i++) { v0[i] = x[threadIdx.x + 128*i]; s += v0[i]; }
    s = bred_sum(s, red, 4);
    float mu = s * (1.f / C_);
    float var = 0.f;
    #pragma unroll
    for (int i = 0; i < 3; i++) { float d = v0[i] - mu; var = fmaf(d, d, var); }
    var = bred_sum(var, red, 4) * (1.f / C_);
    float inv = rsqrtf(var + 1e-5f);
    #pragma unroll
    for (int i = 0; i < 3; i++) {
        int c = threadIdx.x + 128*i;
        float v = (v0[i] - mu) * inv * w[c] + b[c];
        long long idx = (long long)row*C_ + c;
        out[idx] = v;
        bf16 h, l; wsplit(v, h, l);
        ohi[idx] = h; olo[idx] = l;
    }
}

// ---------------- generic fp32 -> bf16 hi/lo split (weights, RiT) ---------------
__global__ void split_kernel(const float* __restrict__ src,
                             bf16* __restrict__ hi, bf16* __restrict__ lo,
                             long long total) {
    long long i = (long long)blockIdx.x * blockDim.x + threadIdx.x;
    if (i >= total) return;
    float v = src[i];
    bf16 h, l; wsplit(v, h, l);
    hi[i] = h; lo[i] = l;
}

// ---------------- fused q/k split + per-row sumsq (warp per row) ----------------
// z in [0,192): 0..95 = q heads, 96..191 = k heads. Coalesced 64-float rows.
__global__ __launch_bounds__(256) void qk_split_kernel(
    const float* __restrict__ qkv, bf16* __restrict__ hi, bf16* __restrict__ lo,
    float* __restrict__ qn2, float* __restrict__ kn2) {
    int gw = blockIdx.x * 8 + (threadIdx.x >> 5);
    int lane = threadIdx.x & 31;
    int r = gw & 511;
    int z = gw >> 9;
    int s = (z >= 96) ? 1 : 0;
    int bh = z - s*96;
    int b = bh / 6, h = bh - (bh/6)*6;
    const float* p = qkv + (long long)(b*512 + r)*1152 + s*384 + h*64;
    float v0 = p[lane], v1 = p[lane + 32];
    long long o = (long long)z*32768 + r*64 + lane;
    bf16 h0, l0, h1, l1;
    wsplit(v0, h0, l0); wsplit(v1, h1, l1);
    hi[o] = h0; lo[o] = l0;
    hi[o + 32] = h1; lo[o + 32] = l1;
    float ss = fmaf(v0, v0, v1*v1);
    #pragma unroll
    for (int d = 16; d; d >>= 1) ss += __shfl_xor_sync(0xffffffffu, ss, d);
    if (lane == 0) {
        if (s) kn2[bh*512 + r] = ss; else qn2[bh*512 + r] = ss;
    }
}

// ---------------- bf16-split tensor-core GEMM: C = A * B^T ----------------------
template<int BN>
__global__ __launch_bounds__(256) void mma_gemm(
    const bf16* __restrict__ Ahi, const bf16* __restrict__ Alo,
    const bf16* __restrict__ Bhi, const bf16* __restrict__ Blo,
    const float* __restrict__ Rres, const float* __restrict__ bias,
    float* __restrict__ Cout, bf16* __restrict__ Whi, bf16* __restrict__ Wlo,
    int K, int ldc, long long sA, long long sB,
    long long Cb, long long Ch, int Hdiv, int flags)
{
    constexpr int WN  = BN / 2;
    constexpr int NT  = WN / 16;
    constexpr int NF  = WN / 8;
    constexpr int ATB = 128*40*2;
    constexpr int BTB = BN*40*2;
    constexpr int STG = 2*ATB + 2*BTB;

    extern __shared__ __align__(16) bf16 dyn[];
    uint32_t sbase = smem_u32(dyn);

    int z = blockIdx.z;
    const bf16* pAhi = Ahi + (long long)z*sA;
    const bf16* pAlo = Alo + (long long)z*sA;
    const bf16* pBhi = Bhi + (long long)z*sB;
    const bf16* pBlo = Blo + (long long)z*sB;
    int zb = z / Hdiv, zh = z - zb*Hdiv;
    long long co = Cb*zb + Ch*zh;

    int m0 = blockIdx.y << 7, n0 = blockIdx.x * BN;
    int tid = threadIdx.x, wid = tid >> 5, lane = tid & 31;
    int wm = wid >> 1, wn = wid & 1;
    int r16 = lane & 15, kh = lane >> 4;

    float acc[2][NF][4];
    #pragma unroll
    for (int a = 0; a < 2; a++)
        #pragma unroll
        for (int f = 0; f < NF; f++)
            #pragma unroll
            for (int q = 0; q < 4; q++) acc[a][f][q] = 0.f;

    int kt = K >> 5;

    auto load_tile = [&](int t) {
        int s = t % 3;
        uint32_t ab = sbase + (uint32_t)(s * STG);
        int k0 = t << 5;
        #pragma unroll
        for (int i = tid; i < 128*4; i += 256) {
            int r = i >> 2, c = i & 3;
            uint32_t so = ab + (uint32_t)((r*40 + c*8) * 2);
            cpa16(so, pAhi + (long long)(m0 + r)*K + k0 + c*8);
            cpa16(so + ATB, pAlo + (long long)(m0 + r)*K + k0 + c*8);
        }
        uint32_t bbb = sbase + (uint32_t)(s * STG) + 2*ATB;
        #pragma unroll
        for (int i = tid; i < BN*4; i += 256) {
            int r = i >> 2, c = i & 3;
            uint32_t so = bbb + (uint32_t)((r*40 + c*8) * 2);
            cpa16(so, pBhi + (long long)(n0 + r)*K + k0 + c*8);
            cpa16(so + BTB, pBlo + (long long)(n0 + r)*K + k0 + c*8);
        }
    };

    load_tile(0); cpa_commit();
    if (kt > 1) load_tile(1);
    cpa_commit();

    for (int t = 0; t < kt; t++) {
        cpa_wait1();
        __syncthreads();
        if (t + 2 < kt) load_tile(t + 2);
        cpa_commit();

        int s = t % 3;
        uint32_t ab = sbase + (uint32_t)(s * STG);
        uint32_t bb = ab + 2*ATB;
        #pragma unroll
        for (int kk = 0; kk < 2; kk++) {
            uint32_t a_hi[2][4], a_lo[2][4];
            #pragma unroll
            for (int mt = 0; mt < 2; mt++) {
                uint32_t ad = ab + (uint32_t)(((wm*32 + mt*16 + r16)*40 + kk*16 + kh*8) * 2);
                ldsm4(a_hi[mt], ad);
                ldsm4(a_lo[mt], ad + ATB);
            }
            #pragma unroll
            for (int nt = 0; nt < NT; nt++) {
                uint32_t bh[4], bl[4];
                uint32_t bd = bb + (uint32_t)(((wn*WN + nt*16 + r16)*40 + kk*16 + kh*8) * 2);
                ldsm4(bh, bd);
                ldsm4(bl, bd + BTB);
                #pragma unroll
                for (int mt = 0; mt < 2; mt++) {
                    float* c0 = acc[mt][2*nt];
                    float* c1 = acc[mt][2*nt + 1];
                    mma_bf16(c0, a_hi[mt], bh[0], bh[2]);
                    mma_bf16(c0, a_hi[mt], bl[0], bl[2]);
                    mma_bf16(c0, a_lo[mt], bh[0], bh[2]);
                    mma_bf16(c1, a_hi[mt], bh[1], bh[3]);
                    mma_bf16(c1, a_hi[mt], bl[1], bl[3]);
                    mma_bf16(c1, a_lo[mt], bh[1], bh[3]);
                }
            }
        }
    }

    #pragma unroll
    for (int mt = 0; mt < 2; mt++)
    #pragma unroll
    for (int f = 0; f < NF; f++) {
        float* c = acc[mt][f];
        int row = m0 + wm*32 + mt*16 + (lane >> 2);
        int col = n0 + wn*WN + f*8 + ((lane & 3) << 1);
        #pragma unroll
        for (int half = 0; half < 2; half++) {
            int r = row + half*8;
            float v0 = c[half*2 + 0], v1 = c[half*2 + 1];
            if (flags & 1) { v0 += bias[col]; v1 += bias[col + 1]; }
            if (flags & 2) { v0 = gelu_f(v0); v1 = gelu_f(v1); }
            long long idx = co + (long long)r*ldc + col;
            if (flags & 4) {
                float2 rr = *(const float2*)(Rres + idx);
                v0 += rr.x; v1 += rr.y;
            }
            float2 o; o.x = v0; o.y = v1;
            *(float2*)(Cout + idx) = o;
            if (flags & 8) {
                bf16 h0, l0, h1, l1;
                wsplit(v0, h0, l0); wsplit(v1, h1, l1);
                __nv_bfloat162 hh; hh.x = h0; hh.y = h1;
                __nv_bfloat162 ll; ll.x = l0; ll.y = l1;
                *(__nv_bfloat162*)(Whi + idx) = hh;
                *(__nv_bfloat162*)(Wlo + idx) = ll;
            }
        }
    }
}

// ---------------- v transpose via smem tile (coalesced both sides) --------------
__global__ __launch_bounds__(256) void vT_bf16_kernel(const float* __restrict__ qkv,
                                                      bf16* __restrict__ hi,
                                                      bf16* __restrict__ lo) {
    __shared__ float tile[64][65];
    int bh = blockIdx.x;           // 96
    int m0 = blockIdx.y << 6;      // 8 tiles of 64
    int b = bh / 6, h = bh - (bh/6)*6;
    int tid = threadIdx.x;
    for (int i = tid; i < 4096; i += 256) {
        int m = i >> 6, d = i & 63;
        tile[d][m] = qkv[(long long)(b*512 + m0 + m)*1152 + 768 + h*64 + d];
    }
    __syncthreads();
    for (int i = tid; i < 4096; i += 256) {
        int d = i >> 6, m = i & 63;
        float v = tile[d][m];
        bf16 h_, l_; wsplit(v, h_, l_);
        long long o = (long long)bh*32768 + d*512 + m0 + m;
        hi[o] = h_; lo[o] = l_;
    }
}

// ---------------- Householder QR factorization (sgeqr2, float2 rows) ------------
// QR_LDC even so every column is float2-aligned; thread owns row pairs
// (2*lane + 64*t, +1) for t in 0..7 -> all inner-loop smem ops are LDS.64/STS.64.
#define QR_LDC 514
__global__ __launch_bounds__(512) void qr_forward(const float* __restrict__ qkv,
                                                  float* __restrict__ R_out) {
    extern __shared__ float As[];          // 64 * QR_LDC
    __shared__ float red[33];
    __shared__ float sbeta[64];
    __shared__ float s_ss[2];
    int mat = blockIdx.x;
    int s = (mat >= 96) ? 1 : 0;
    int bh = mat - s*96;
    int b = bh / 6, h = bh - (bh/6)*6;
    const float* Ab = qkv + (long long)b*512*1152 + s*384 + h*64;
    int tid = threadIdx.x;
    int wid = tid >> 5, lane = tid & 31;

    for (int i = tid; i < 64*512; i += 512) {
        int n = i >> 6, d = i & 63;
        As[d*QR_LDC + n] = Ab[(long long)n*1152 + d];
    }
    __syncthreads();
    {
        float x = (tid > 0) ? As[tid] : 0.f;
        float ss0 = bred_sum(x*x, red, 16);
        if (tid == 0) s_ss[0] = ss0;
    }
    __syncthreads();

    for (int j = 0; j < 64; j++) {
        float* col = As + j*QR_LDC;
        float alpha = col[j];
        float ss = s_ss[j & 1];
        float beta, teff, uj;
        if (ss == 0.f) { beta = alpha; teff = 0.f; uj = 1.f; }
        else {
            float nrm = sqrtf(alpha*alpha + ss);
            beta = (alpha >= 0.f) ? -nrm : nrm;   // LAPACK sign
            float tau = (beta - alpha) / beta;
            uj  = alpha - beta;
            teff = tau / (uj * uj);
        }
        if (tid == 0) sbeta[j] = beta;
        const float2* colv = (const float2*)col;
        float2 u[8];
        #pragma unroll
        for (int t = 0; t < 8; t++) {
            float2 vv = colv[lane + 32*t];
            int r0 = (lane + 32*t) << 1;
            u[t].x = (r0     > j) ? vv.x : ((r0     == j) ? uj : 0.f);
            u[t].y = (r0 + 1 > j) ? vv.y : ((r0 + 1 == j) ? uj : 0.f);
        }
        for (int c = j + 1 + wid; c < 64; c += 16) {
            float2* cc = (float2*)(As + c*QR_LDC);
            float2 cv[8];
            float w = 0.f;
            #pragma unroll
            for (int t = 0; t < 8; t++) {
                cv[t] = cc[lane + 32*t];
                w = fmaf(u[t].x, cv[t].x, w);
                w = fmaf(u[t].y, cv[t].y, w);
            }
            #pragma unroll
            for (int o = 16; o; o >>= 1) w += __shfl_xor_sync(0xffffffffu, w, o);
            float tw = teff * w;
            if (c == j + 1) {
                float nss = 0.f;
                #pragma unroll
                for (int t = 0; t < 8; t++) {
                    int r0 = (lane + 32*t) << 1;
                    float nx = cv[t].x - tw * u[t].x;
                    float ny = cv[t].y - tw * u[t].y;
                    float2 nv; nv.x = nx; nv.y = ny;
                    cc[lane + 32*t] = nv;
                    if (r0     > j + 1) nss = fmaf(nx, nx, nss);
                    if (r0 + 1 > j + 1) nss = fmaf(ny, ny, nss);
                }
                #pragma unroll
                for (int o = 16; o; o >>= 1) nss += __shfl_xor_sync(0xffffffffu, nss, o);
                if (lane == 0) s_ss[(j + 1) & 1] = nss;
            } else {
                #pragma unroll
                for (int t = 0; t < 8; t++) {
                    float2 nv;
                    nv.x = cv[t].x - tw * u[t].x;
                    nv.y = cv[t].y - tw * u[t].y;
                    cc[lane + 32*t] = nv;
                }
            }
        }
        __syncthreads();
    }
    for (int i = tid; i < 4096; i += 512) {
        int c = i >> 6, r = i & 63;
        float v = (r < c) ? As[c*QR_LDC + r] : ((r == c) ? sbeta[c] : 0.f);
        R_out[(long long)mat*4096 + i] = v;
    }
}

// ---------------- invert upper-triangular R; transposed output ------------------
__global__ __launch_bounds__(64) void rinv_kernel(const float* __restrict__ R,
                                                  float* __restrict__ RiT) {
    __shared__ float Rs[4096];
    __shared__ float xs[64*65];
    int mat = blockIdx.x, tid = threadIdx.x;
    for (int i = tid; i < 4096; i += 64) Rs[i] = R[(long long)mat*4096 + i];
    __syncthreads();
    int c = tid;
    float* x = xs + c*65;
    for (int i = c; i >= 0; i--) {
        float sacc = (i == c) ? 1.f : 0.f;
        for (int k = i + 1; k <= c; k++)
            sacc = fmaf(-Rs[k*64 + i], x[k], sacc);
        x[i] = sacc / Rs[i*64 + i];
    }
    for (int k = 0; k < 64; k++)
        RiT[(long long)mat*4096 + c*64 + k] = (k <= c) ? x[k] : 0.f;
}

// ---------------- fused head-mix + softmax (6-channel 2-level reduction) --------
__global__ __launch_bounds__(512) void mix_softmax(
    const float* __restrict__ qk, const float* __restrict__ dots,
    const float* __restrict__ qn2, const float* __restrict__ kn2,
    const float* __restrict__ conv_w, const float* __restrict__ conv_b,
    const float* __restrict__ sp, const float* __restrict__ rp,
    const float* __restrict__ gp, float* __restrict__ attn,
    bf16* __restrict__ ahi, bf16* __restrict__ alo) {
    __shared__ float wsh[108], bsh[6], qsh[6];
    __shared__ float part[6][17];
    __shared__ float fin[6], fin2[6];
    int bn = blockIdx.x; int b = bn >> 9, n = bn & 511;
    int m = threadIdx.x;
    int lane = m & 31, wid = m >> 5;
    if (m < 108) wsh[m] = conv_w[m];
    if (m < 6) { bsh[m] = conv_b[m]; qsh[m] = qn2[((b*6 + m) << 9) + n]; }
    float scale = *sp, rs = *rp, gs = *gp;
    __syncthreads();
    float mixed[6];
    #pragma unroll
    for (int o = 0; o < 6; o++) mixed[o] = bsh[o];
    #pragma unroll
    for (int h = 0; h < 6; h++) {
        long long idx = ((long long)((b*6 + h)*512 + n) << 9) + m;
        float qv = qk[idx];
        float dd = dots[idx];
        float e  = qv * scale;
        float qn = qsh[h];
        float kn = kn2[((b*6 + h) << 9) + m];
        float d2 = qn*qn + kn*kn - 2.f*qv*qv;
        float ri = sqrtf(fmaxf(d2, 0.f)) * rs;
        float gg = dd*dd * gs;
        #pragma unroll
        for (int o = 0; o < 6; o++)
            mixed[o] += wsh[o*18 + h]*e + wsh[o*18 + 6 + h]*ri + wsh[o*18 + 12 + h]*gg;
    }
    // max (all 6 channels simultaneously)
    #pragma unroll
    for (int o = 0; o < 6; o++) {
        float v = mixed[o];
        #pragma unroll
        for (int d = 16; d; d >>= 1) v = fmaxf(v, __shfl_xor_sync(0xffffffffu, v, d));
        if (lane == 0) part[o][wid] = v;
    }
    __syncthreads();
    if (m < 96) {
        int o = m >> 4, l = m & 15;
        float v = part[o][l];
        #pragma unroll
        for (int d = 8; d; d >>= 1) v = fmaxf(v, __shfl_xor_sync(0xffffffffu, v, d));
        if (l == 0) fin[o] = v;
    }
    __syncthreads();
    float e[6];
    #pragma unroll
    for (int o = 0; o < 6; o++) {
        e[o] = expf(mixed[o] - fin[o]);
        float v = e[o];
        #pragma unroll
        for (int d = 16; d; d >>= 1) v += __shfl_xor_sync(0xffffffffu, v, d);
        if (lane == 0) part[o][wid] = v;
    }
    __syncthreads();
    if (m < 96) {
        int o = m >> 4, l = m & 15;
        float v = part[o][l];
        #pragma unroll
        for (int d = 8; d; d >>= 1) v += __shfl_xor_sync(0xffffffffu, v, d);
        if (l == 0) fin2[o] = v;
    }
    __syncthreads();
    #pragma unroll
    for (int o = 0; o < 6; o++) {
        float v = e[o] / fin2[o];
        long long idx = ((long long)((b*6 + o)*512 + n) << 9) + m;
        attn[idx] = v;
        bf16 h_, l_; wsplit(v, h_, l_);
        ahi[idx] = h_; alo[idx] = l_;
    }
}

// ================================================================================
extern "C" void kernel_launch(void* const* d_in, const int* in_sizes, int n_in,
                              void* d_out, int out_size) {
    const float* src     = (const float*)d_in[0];
    const float* pre_w   = (const float*)d_in[1];
    const float* pre_b   = (const float*)d_in[2];
    const float* qkv_w   = (const float*)d_in[3];
    const float* qkv_b   = (const float*)d_in[4];
    const float* scale_p = (const float*)d_in[5];
    const float* riem_p  = (const float*)d_in[6];
    const float* grass_p = (const float*)d_in[7];
    const float* conv_w  = (const float*)d_in[8];
    const float* conv_b  = (const float*)d_in[9];
    const float* proj_w  = (const float*)d_in[10];
    const float* proj_b  = (const float*)d_in[11];
    const float* n1_w    = (const float*)d_in[12];
    const float* n1_b    = (const float*)d_in[13];
    const float* l1_w    = (const float*)d_in[14];
    const float* l1_b    = (const float*)d_in[15];
    const float* l2_w    = (const float*)d_in[16];
    const float* l2_b    = (const float*)d_in[17];
    float* out = (float*)d_out;

    float *x, *qkv, *R, *RiT, *qgr, *qn2, *kn2, *qk, *dots, *attn, *ao, *t, *u, *h1;
    cudaGetSymbolAddress((void**)&x,    g_x);
    cudaGetSymbolAddress((void**)&qkv,  g_qkv);
    cudaGetSymbolAddress((void**)&R,    g_R);
    cudaGetSymbolAddress((void**)&RiT,  g_RiT);
    cudaGetSymbolAddress((void**)&qgr,  g_qgr);
    cudaGetSymbolAddress((void**)&qn2,  g_qn2);
    cudaGetSymbolAddress((void**)&kn2,  g_kn2);
    cudaGetSymbolAddress((void**)&qk,   g_qk);
    cudaGetSymbolAddress((void**)&dots, g_dots);
    cudaGetSymbolAddress((void**)&attn, g_attn);
    cudaGetSymbolAddress((void**)&ao,   g_ao);
    cudaGetSymbolAddress((void**)&t,    g_t);
    cudaGetSymbolAddress((void**)&u,    g_u);
    cudaGetSymbolAddress((void**)&h1,   g_h1);

    bf16 *xh,*xl,*qwh,*qwl,*qkh,*qkl,*rih,*ril,*qgh,*qgl,
         *vth,*vtl,*ath,*atl,*aoh,*aol,*pwh,*pwl,*uh,*ul,*l1h,*l1l,*h1h,*h1l,*l2h,*l2l;
    cudaGetSymbolAddress((void**)&xh,  sX_hi);  cudaGetSymbolAddress((void**)&xl,  sX_lo);
    cudaGetSymbolAddress((void**)&qwh, sQW_hi); cudaGetSymbolAddress((void**)&qwl, sQW_lo);
    cudaGetSymbolAddress((void**)&qkh, sQK_hi); cudaGetSymbolAddress((void**)&qkl, sQK_lo);
    cudaGetSymbolAddress((void**)&rih, sRi_hi); cudaGetSymbolAddress((void**)&ril, sRi_lo);
    cudaGetSymbolAddress((void**)&qgh, sQg_hi); cudaGetSymbolAddress((void**)&qgl, sQg_lo);
    cudaGetSymbolAddress((void**)&vth, sVT_hi); cudaGetSymbolAddress((void**)&vtl, sVT_lo);
    cudaGetSymbolAddress((void**)&ath, sAt_hi); cudaGetSymbolAddress((void**)&atl, sAt_lo);
    cudaGetSymbolAddress((void**)&aoh, sAo_hi); cudaGetSymbolAddress((void**)&aol, sAo_lo);
    cudaGetSymbolAddress((void**)&pwh, sPW_hi); cudaGetSymbolAddress((void**)&pwl, sPW_lo);
    cudaGetSymbolAddress((void**)&uh,  sU_hi);  cudaGetSymbolAddress((void**)&ul,  sU_lo);
    cudaGetSymbolAddress((void**)&l1h, sL1_hi); cudaGetSymbolAddress((void**)&l1l, sL1_lo);
    cudaGetSymbolAddress((void**)&h1h, sH1_hi); cudaGetSymbolAddress((void**)&h1l, sH1_lo);
    cudaGetSymbolAddress((void**)&l2h, sL2_hi); cudaGetSymbolAddress((void**)&l2l, sL2_lo);

    const int SMEM_QR = 64 * QR_LDC * 4;
    const int SMG128 = 3 * (2*128*40*2 + 2*128*40*2);   // 122880
    const int SMG64  = 3 * (2*128*40*2 + 2*64*40*2);    //  92160
    cudaFuncSetAttribute(qr_forward,    cudaFuncAttributeMaxDynamicSharedMemorySize, SMEM_QR);
    cudaFuncSetAttribute(mma_gemm<128>, cudaFuncAttributeMaxDynamicSharedMemorySize, SMG128);
    cudaFuncSetAttribute(mma_gemm<64>,  cudaFuncAttributeMaxDynamicSharedMemorySize, SMG64);

    long long need = (long long)BN_*C_ + (long long)BH_*N_*N_;
    bool attn_in_out = ((long long)out_size >= need);
    float* attn_dst = attn_in_out ? (out + (long long)BN_*C_) : attn;

    // 1. pre-LN -> x fp32 + bf16
    ln_kernel<<<BN_, 128>>>(src, pre_w, pre_b, x, xh, xl);
    // 1b. split qkv_w
    split_kernel<<<(FF_*C_ + 255)/256, 256>>>(qkv_w, qwh, qwl, (long long)FF_*C_);
    // 2. QKV GEMM (M=8192, N=1152, K=384) + bias
    mma_gemm<128><<<dim3(9, 64, 1), 256, SMG128>>>(xh, xl, qwh, qwl, nullptr, qkv_b,
        qkv, nullptr, nullptr, C_, FF_, 0, 0, 0, 0, 1, 1);
    // 3. fused q/k split + norms (z=192 warp-per-row)
    qk_split_kernel<<<192*512/8, 256>>>(qkv, qkh, qkl, qn2, kn2);
    // 4. Householder factorization -> R ; invert -> RiT ; split RiT
    qr_forward<<<192, 512, SMEM_QR>>>(qkv, R);
    rinv_kernel<<<192, 64>>>(R, RiT);
    split_kernel<<<(int)((192LL*4096 + 255)/256), 256>>>(RiT, rih, ril, 192LL*4096);
    // 4b. [qgr;kgr] = [q;k] @ Rinv (z=192 merged)
    mma_gemm<64><<<dim3(1, 4, 192), 256, SMG64>>>(qkh, qkl, rih, ril, nullptr, nullptr,
        qgr, qgh, qgl, 64, 64, 32768LL, 4096LL, 32768LL, 0, 1, 8);
    // 5. qk = q @ k^T (512x512x64, z=96)
    mma_gemm<128><<<dim3(4, 4, 96), 256, SMG128>>>(qkh, qkl, qkh + 96LL*32768, qkl + 96LL*32768,
        nullptr, nullptr, qk, nullptr, nullptr, 64, 512, 32768LL, 32768LL, 262144LL, 0, 1, 0);
    // 6. dots = qgr @ kgr^T
    mma_gemm<128><<<dim3(4, 4, 96), 256, SMG128>>>(qgh, qgl, qgh + 96LL*32768, qgl + 96LL*32768,
        nullptr, nullptr, dots, nullptr, nullptr, 64, 512, 32768LL, 32768LL, 262144LL, 0, 1, 0);
    // 7. v transpose -> bf16 (smem tile, coalesced)
    vT_bf16_kernel<<<dim3(96, 8), 256>>>(qkv, vth, vtl);
    // 8. mix + softmax -> attn fp32 + bf16
    mix_softmax<<<BN_, 512>>>(qk, dots, qn2, kn2, conv_w, conv_b,
                              scale_p, riem_p, grass_p, attn_dst, ath, atl);
    // 9. ao = attn @ v (512x64x512, z=96) -> [b,n,h*64+d] + bf16
    mma_gemm<64><<<dim3(1, 4, 96), 256, SMG64>>>(ath, atl, vth, vtl, nullptr, nullptr,
        ao, aoh, aol, 512, 384, 262144LL, 32768LL, 196608LL, 64LL, 6, 8);
    // 9b. split proj_w
    split_kernel<<<(C_*C_ + 255)/256, 256>>>(proj_w, pwh, pwl, (long long)C_*C_);
    // 10. proj + bias + residual(src) -> t
    mma_gemm<128><<<dim3(3, 64, 1), 256, SMG128>>>(aoh, aol, pwh, pwl, src, proj_b,
        t, nullptr, nullptr, C_, C_, 0, 0, 0, 0, 1, 1|4);
    // 11. norm1 -> u fp32 + bf16
    ln_kernel<<<BN_, 128>>>(t, n1_w, n1_b, u, uh, ul);
    // 11b. split l1_w, l2_w
    split_kernel<<<(FF_*C_ + 255)/256, 256>>>(l1_w, l1h, l1l, (long long)FF_*C_);
    split_kernel<<<(C_*FF_ + 255)/256, 256>>>(l2_w, l2h, l2l, (long long)C_*FF_);
    // 12. lin1 + bias + gelu -> h1 (+bf16)
    mma_gemm<128><<<dim3(9, 64, 1), 256, SMG128>>>(uh, ul, l1h, l1l, nullptr, l1_b,
        h1, h1h, h1l, C_, FF_, 0, 0, 0, 0, 1, 1|2|8);
    // 13. lin2 + bias + residual(u) -> d_out
    mma_gemm<128><<<dim3(3, 64, 1), 256, SMG128>>>(h1h, h1l, l2h, l2l, u, l2_b,
        out, nullptr, nullptr, FF_, C_, 0, 0, 0, 0, 1, 1|4);
}

// round 11
// speedup vs baseline: 2.3240x; 1.0092x over previous
#include <cuda_runtime.h>
#include <cuda_bf16.h>
#include <math.h>
#include <stdint.h>

typedef __nv_bfloat16 bf16;

#define B_  16
#define N_  512
#define C_  384
#define H_  6
#define HD_ 64
#define FF_ 1152
#define BN_ (B_*N_)   // 8192
#define BH_ (B_*H_)   // 96

// ---------------- fp32 scratch --------------------------------------------------
__device__ __align__(16) float g_qkv [BN_*3*C_];
__device__ __align__(16) float g_R   [192*64*64];
__device__ __align__(16) float g_qn2 [BH_*N_];
__device__ __align__(16) float g_kn2 [BH_*N_];
__device__ __align__(16) float g_scores[(long long)2*BH_*N_*N_];  // [qk ; dots]
__device__ __align__(16) float g_attn[(long long)BH_*N_*N_];
__device__ __align__(16) float g_t   [BN_*C_];
__device__ __align__(16) float g_u   [BN_*C_];

// ---------------- bf16 hi/lo operand pools --------------------------------------
// unified score pool: slots [q(0..95) | k(96..191) | qgr(192..287) | kgr(288..383)]
__device__ __align__(16) bf16 sPool_hi[384LL*N_*HD_], sPool_lo[384LL*N_*HD_];
__device__ __align__(16) bf16 sX_hi [BN_*C_],        sX_lo [BN_*C_];
__device__ __align__(16) bf16 sQW_hi[FF_*C_],        sQW_lo[FF_*C_];
__device__ __align__(16) bf16 sRi_hi[192*64*64],     sRi_lo[192*64*64];
__device__ __align__(16) bf16 sVT_hi[BH_*HD_*N_],    sVT_lo[BH_*HD_*N_];
__device__ __align__(16) bf16 sAt_hi[(long long)BH_*N_*N_], sAt_lo[(long long)BH_*N_*N_];
__device__ __align__(16) bf16 sAo_hi[BN_*C_],        sAo_lo[BN_*C_];
__device__ __align__(16) bf16 sPW_hi[C_*C_],         sPW_lo[C_*C_];
__device__ __align__(16) bf16 sU_hi [BN_*C_],        sU_lo [BN_*C_];
__device__ __align__(16) bf16 sL1_hi[FF_*C_],        sL1_lo[FF_*C_];
__device__ __align__(16) bf16 sH1_hi[BN_*FF_],       sH1_lo[BN_*FF_];
__device__ __align__(16) bf16 sL2_hi[C_*FF_],        sL2_lo[C_*FF_];

// ---------------- PTX helpers ---------------------------------------------------
__device__ __forceinline__ uint32_t smem_u32(const void* p) {
    uint32_t a;
    asm("{ .reg .u64 t; cvta.to.shared.u64 t, %1; cvt.u32.u64 %0, t; }" : "=r"(a) : "l"(p));
    return a;
}
__device__ __forceinline__ void cpa16(uint32_t s, const void* g) {
    asm volatile("cp.async.ca.shared.global [%0], [%1], 16;" :: "r"(s), "l"(g));
}
__device__ __forceinline__ void cpa_commit() {
    asm volatile("cp.async.commit_group;" ::: "memory");
}
__device__ __forceinline__ void cpa_wait1() {
    asm volatile("cp.async.wait_group 1;" ::: "memory");
}
__device__ __forceinline__ void ldsm4(uint32_t* r, uint32_t addr) {
    asm volatile("ldmatrix.sync.aligned.m8n8.x4.shared.b16 {%0,%1,%2,%3}, [%4];"
        : "=r"(r[0]), "=r"(r[1]), "=r"(r[2]), "=r"(r[3]) : "r"(addr));
}
__device__ __forceinline__ void mma_bf16(float* d, const uint32_t* a, uint32_t b0, uint32_t b1) {
    asm volatile("mma.sync.aligned.m16n8k16.row.col.f32.bf16.bf16.f32 "
        "{%0,%1,%2,%3}, {%4,%5,%6,%7}, {%8,%9}, {%0,%1,%2,%3};"
        : "+f"(d[0]), "+f"(d[1]), "+f"(d[2]), "+f"(d[3])
        : "r"(a[0]), "r"(a[1]), "r"(a[2]), "r"(a[3]), "r"(b0), "r"(b1));
}
__device__ __forceinline__ float gelu_f(float v) {
    return 0.5f * v * (1.f + erff(v * 0.70710678118654752f));
}
__device__ __forceinline__ void wsplit(float v, bf16& h, bf16& l) {
    h = __float2bfloat16(v);
    l = __float2bfloat16(v - __bfloat162float(h));
}

// ---------------- block reductions (used by LN) ---------------------------------
__device__ __forceinline__ float bred_sum(float v, float* red, int nw) {
    int lane = threadIdx.x & 31, wid = threadIdx.x >> 5;
    #pragma unroll
    for (int o = 16; o; o >>= 1) v += __shfl_xor_sync(0xffffffffu, v, o);
    if (lane == 0) red[wid] = v;
    __syncthreads();
    if (wid == 0) {
        float t = (lane < nw) ? red[lane] : 0.f;
        #pragma unroll
        for (int o = 16; o; o >>= 1) t += __shfl_xor_sync(0xffffffffu, t, o);
        if (lane == 0) red[32] = t;
    }
    __syncthreads();
    float r = red[32];
    __syncthreads();
    return r;
}

// ---------------- LayerNorm (fp32 out optional + bf16 hi/lo) --------------------
__global__ __launch_bounds__(128) void ln_kernel(
    const float* __restrict__ in, const float* __restrict__ w,
    const float* __restrict__ b, float* __restrict__ out,
    bf16* __restrict__ ohi, bf16* __restrict__ olo) {
    __shared__ float red[33];
    int row = blockIdx.x;
    const float* x = in + (long long)row * C_;
    float v0[3]; float s = 0.f;
    #pragma unroll
    for (int i = 0; i < 3; i++) { v0[i] = x[threadIdx.x + 128*i]; s += v0[i]; }
    s = bred_sum(s, red, 4);
    float mu = s * (1.f / C_);
    float var = 0.f;
    #pragma unroll
    for (int i = 0; i < 3; i++) { float d = v0[i] - mu; var = fmaf(d, d, var); }
    var = bred_sum(var, red, 4) * (1.f / C_);
    float inv = rsqrtf(var + 1e-5f);
    #pragma unroll
    for (int i = 0; i < 3; i++) {
        int c = threadIdx.x + 128*i;
        float v = (v0[i] - mu) * inv * w[c] + b[c];
        long long idx = (long long)row*C_ + c;
        if (out) out[idx] = v;
        bf16 h, l; wsplit(v, h, l);
        ohi[idx] = h; olo[idx] = l;
    }
}

// ---------------- one-shot 4-segment fp32 -> bf16 hi/lo split -------------------
__global__ void split4_kernel(
    const float* __restrict__ s0, bf16* __restrict__ h0, bf16* __restrict__ l0, int n0,
    const float* __restrict__ s1, bf16* __restrict__ h1, bf16* __restrict__ l1, int n1,
    const float* __restrict__ s2, bf16* __restrict__ h2, bf16* __restrict__ l2, int n2,
    const float* __restrict__ s3, bf16* __restrict__ h3, bf16* __restrict__ l3, int n3) {
    int i = blockIdx.x * blockDim.x + threadIdx.x;
    const float* s; bf16 *hh, *ll; int j = i;
    if (j < n0) { s = s0; hh = h0; ll = l0; }
    else {
        j -= n0;
        if (j < n1) { s = s1; hh = h1; ll = l1; }
        else {
            j -= n1;
            if (j < n2) { s = s2; hh = h2; ll = l2; }
            else {
                j -= n2;
                if (j >= n3) return;
                s = s3; hh = h3; ll = l3;
            }
        }
    }
    float v = s[j];
    bf16 h, l; wsplit(v, h, l);
    hh[j] = h; ll[j] = l;
}

// ---------------- fused q/k split + per-row sumsq (warp per row) ----------------
__global__ __launch_bounds__(256) void qk_split_kernel(
    const float* __restrict__ qkv, bf16* __restrict__ hi, bf16* __restrict__ lo,
    float* __restrict__ qn2, float* __restrict__ kn2) {
    int gw = blockIdx.x * 8 + (threadIdx.x >> 5);
    int lane = threadIdx.x & 31;
    int r = gw & 511;
    int z = gw >> 9;
    int s = (z >= 96) ? 1 : 0;
    int bh = z - s*96;
    int b = bh / 6, h = bh - (bh/6)*6;
    const float* p = qkv + (long long)(b*512 + r)*1152 + s*384 + h*64;
    float v0 = p[lane], v1 = p[lane + 32];
    long long o = (long long)z*32768 + r*64 + lane;
    bf16 h0, l0, h1, l1;
    wsplit(v0, h0, l0); wsplit(v1, h1, l1);
    hi[o] = h0; lo[o] = l0;
    hi[o + 32] = h1; lo[o + 32] = l1;
    float ss = fmaf(v0, v0, v1*v1);
    #pragma unroll
    for (int d = 16; d; d >>= 1) ss += __shfl_xor_sync(0xffffffffu, ss, d);
    if (lane == 0) {
        if (s) kn2[bh*512 + r] = ss; else qn2[bh*512 + r] = ss;
    }
}

// ---------------- bf16-split tensor-core GEMM: C = A * B^T ----------------------
// flags: 1=bias, 2=gelu, 4=residual, 8=write bf16 hi/lo, 16=skip fp32 C,
//        32=score mode (zi = z + 96*[z>=96]; B pool offset pre-applied by caller)
template<int BN>
__global__ __launch_bounds__(256) void mma_gemm(
    const bf16* __restrict__ Ahi, const bf16* __restrict__ Alo,
    const bf16* __restrict__ Bhi, const bf16* __restrict__ Blo,
    const float* __restrict__ Rres, const float* __restrict__ bias,
    float* __restrict__ Cout, bf16* __restrict__ Whi, bf16* __restrict__ Wlo,
    int K, int ldc, long long sA, long long sB,
    long long Cb, long long Ch, int Hdiv, int flags)
{
    constexpr int WN  = BN / 2;
    constexpr int NT  = WN / 16;
    constexpr int NF  = WN / 8;
    constexpr int ATB = 128*40*2;
    constexpr int BTB = BN*40*2;
    constexpr int STG = 2*ATB + 2*BTB;

    extern __shared__ __align__(16) bf16 dyn[];
    uint32_t sbase = smem_u32(dyn);

    int z = blockIdx.z;
    int zi = z + ((flags & 32) && z >= 96 ? 96 : 0);
    const bf16* pAhi = Ahi + (long long)zi*sA;
    const bf16* pAlo = Alo + (long long)zi*sA;
    const bf16* pBhi = Bhi + (long long)zi*sB;
    const bf16* pBlo = Blo + (long long)zi*sB;
    int zb = z / Hdiv, zh = z - zb*Hdiv;
    long long co = Cb*zb + Ch*zh;

    int m0 = blockIdx.y << 7, n0 = blockIdx.x * BN;
    int tid = threadIdx.x, wid = tid >> 5, lane = tid & 31;
    int wm = wid >> 1, wn = wid & 1;
    int r16 = lane & 15, kh = lane >> 4;

    float acc[2][NF][4];
    #pragma unroll
    for (int a = 0; a < 2; a++)
        #pragma unroll
        for (int f = 0; f < NF; f++)
            #pragma unroll
            for (int q = 0; q < 4; q++) acc[a][f][q] = 0.f;

    int kt = K >> 5;

    auto load_tile = [&](int t) {
        int s = t % 3;
        uint32_t ab = sbase + (uint32_t)(s * STG);
        int k0 = t << 5;
        #pragma unroll
        for (int i = tid; i < 128*4; i += 256) {
            int r = i >> 2, c = i & 3;
            uint32_t so = ab + (uint32_t)((r*40 + c*8) * 2);
            cpa16(so, pAhi + (long long)(m0 + r)*K + k0 + c*8);
            cpa16(so + ATB, pAlo + (long long)(m0 + r)*K + k0 + c*8);
        }
        uint32_t bbb = sbase + (uint32_t)(s * STG) + 2*ATB;
        #pragma unroll
        for (int i = tid; i < BN*4; i += 256) {
            int r = i >> 2, c = i & 3;
            uint32_t so = bbb + (uint32_t)((r*40 + c*8) * 2);
            cpa16(so, pBhi + (long long)(n0 + r)*K + k0 + c*8);
            cpa16(so + BTB, pBlo + (long long)(n0 + r)*K + k0 + c*8);
        }
    };

    load_tile(0); cpa_commit();
    if (kt > 1) load_tile(1);
    cpa_commit();

    for (int t = 0; t < kt; t++) {
        cpa_wait1();
        __syncthreads();
        if (t + 2 < kt) load_tile(t + 2);
        cpa_commit();

        int s = t % 3;
        uint32_t ab = sbase + (uint32_t)(s * STG);
        uint32_t bb = ab + 2*ATB;
        #pragma unroll
        for (int kk = 0; kk < 2; kk++) {
            uint32_t a_hi[2][4], a_lo[2][4];
            #pragma unroll
            for (int mt = 0; mt < 2; mt++) {
                uint32_t ad = ab + (uint32_t)(((wm*32 + mt*16 + r16)*40 + kk*16 + kh*8) * 2);
                ldsm4(a_hi[mt], ad);
                ldsm4(a_lo[mt], ad + ATB);
            }
            #pragma unroll
            for (int nt = 0; nt < NT; nt++) {
                uint32_t bh[4], bl[4];
                uint32_t bd = bb + (uint32_t)(((wn*WN + nt*16 + r16)*40 + kk*16 + kh*8) * 2);
                ldsm4(bh, bd);
                ldsm4(bl, bd + BTB);
                #pragma unroll
                for (int mt = 0; mt < 2; mt++) {
                    float* c0 = acc[mt][2*nt];
                    float* c1 = acc[mt][2*nt + 1];
                    mma_bf16(c0, a_hi[mt], bh[0], bh[2]);
                    mma_bf16(c0, a_hi[mt], bl[0], bl[2]);
                    mma_bf16(c0, a_lo[mt], bh[0], bh[2]);
                    mma_bf16(c1, a_hi[mt], bh[1], bh[3]);
                    mma_bf16(c1, a_hi[mt], bl[1], bl[3]);
                    mma_bf16(c1, a_lo[mt], bh[1], bh[3]);
                }
            }
        }
    }

    #pragma unroll
    for (int mt = 0; mt < 2; mt++)
    #pragma unroll
    for (int f = 0; f < NF; f++) {
        float* c = acc[mt][f];
        int row = m0 + wm*32 + mt*16 + (lane >> 2);
        int col = n0 + wn*WN + f*8 + ((lane & 3) << 1);
        #pragma unroll
        for (int half = 0; half < 2; half++) {
            int r = row + half*8;
            float v0 = c[half*2 + 0], v1 = c[half*2 + 1];
            if (flags & 1) { v0 += bias[col]; v1 += bias[col + 1]; }
            if (flags & 2) { v0 = gelu_f(v0); v1 = gelu_f(v1); }
            long long idx = co + (long long)r*ldc + col;
            if (flags & 4) {
                float2 rr = *(const float2*)(Rres + idx);
                v0 += rr.x; v1 += rr.y;
            }
            if (!(flags & 16)) {
                float2 o; o.x = v0; o.y = v1;
                *(float2*)(Cout + idx) = o;
            }
            if (flags & 8) {
                bf16 h0, l0, h1, l1;
                wsplit(v0, h0, l0); wsplit(v1, h1, l1);
                __nv_bfloat162 hh; hh.x = h0; hh.y = h1;
                __nv_bfloat162 ll; ll.x = l0; ll.y = l1;
                *(__nv_bfloat162*)(Whi + idx) = hh;
                *(__nv_bfloat162*)(Wlo + idx) = ll;
            }
        }
    }
}

// ---------------- v transpose via smem tile (coalesced both sides) --------------
__global__ __launch_bounds__(256) void vT_bf16_kernel(const float* __restrict__ qkv,
                                                      bf16* __restrict__ hi,
                                                      bf16* __restrict__ lo) {
    __shared__ float tile[64][65];
    int bh = blockIdx.x;
    int m0 = blockIdx.y << 6;
    int b = bh / 6, h = bh - (bh/6)*6;
    int tid = threadIdx.x;
    for (int i = tid; i < 4096; i += 256) {
        int m = i >> 6, d = i & 63;
        tile[d][m] = qkv[(long long)(b*512 + m0 + m)*1152 + 768 + h*64 + d];
    }
    __syncthreads();
    for (int i = tid; i < 4096; i += 256) {
        int d = i >> 6, m = i & 63;
        float v = tile[d][m];
        bf16 h_, l_; wsplit(v, h_, l_);
        long long o = (long long)bh*32768 + d*512 + m0 + m;
        hi[o] = h_; lo[o] = l_;
    }
}

// ---------------- Householder QR factorization (sgeqr2, float2 rows) ------------
#define QR_LDC 514
__global__ __launch_bounds__(512) void qr_forward(const float* __restrict__ qkv,
                                                  float* __restrict__ R_out) {
    extern __shared__ float As[];
    __shared__ float red[33];
    __shared__ float sbeta[64];
    __shared__ float s_ss[2];
    int mat = blockIdx.x;
    int s = (mat >= 96) ? 1 : 0;
    int bh = mat - s*96;
    int b = bh / 6, h = bh - (bh/6)*6;
    const float* Ab = qkv + (long long)b*512*1152 + s*384 + h*64;
    int tid = threadIdx.x;
    int wid = tid >> 5, lane = tid & 31;

    for (int i = tid; i < 64*512; i += 512) {
        int n = i >> 6, d = i & 63;
        As[d*QR_LDC + n] = Ab[(long long)n*1152 + d];
    }
    __syncthreads();
    {
        float x = (tid > 0) ? As[tid] : 0.f;
        float ss0 = bred_sum(x*x, red, 16);
        if (tid == 0) s_ss[0] = ss0;
    }
    __syncthreads();

    for (int j = 0; j < 64; j++) {
        float* col = As + j*QR_LDC;
        float alpha = col[j];
        float ss = s_ss[j & 1];
        float beta, teff, uj;
        if (ss == 0.f) { beta = alpha; teff = 0.f; uj = 1.f; }
        else {
            float nrm = sqrtf(alpha*alpha + ss);
            beta = (alpha >= 0.f) ? -nrm : nrm;   // LAPACK sign
            float tau = (beta - alpha) / beta;
            uj  = alpha - beta;
            teff = tau / (uj * uj);
        }
        if (tid == 0) sbeta[j] = beta;
        const float2* colv = (const float2*)col;
        float2 u[8];
        #pragma unroll
        for (int t = 0; t < 8; t++) {
            float2 vv = colv[lane + 32*t];
            int r0 = (lane + 32*t) << 1;
            u[t].x = (r0     > j) ? vv.x : ((r0     == j) ? uj : 0.f);
            u[t].y = (r0 + 1 > j) ? vv.y : ((r0 + 1 == j) ? uj : 0.f);
        }
        for (int c = j + 1 + wid; c < 64; c += 16) {
            float2* cc = (float2*)(As + c*QR_LDC);
            float2 cv[8];
            float w = 0.f;
            #pragma unroll
            for (int t = 0; t < 8; t++) {
                cv[t] = cc[lane + 32*t];
                w = fmaf(u[t].x, cv[t].x, w);
                w = fmaf(u[t].y, cv[t].y, w);
            }
            #pragma unroll
            for (int o = 16; o; o >>= 1) w += __shfl_xor_sync(0xffffffffu, w, o);
            float tw = teff * w;
            if (c == j + 1) {
                float nss = 0.f;
                #pragma unroll
                for (int t = 0; t < 8; t++) {
                    int r0 = (lane + 32*t) << 1;
                    float nx = cv[t].x - tw * u[t].x;
                    float ny = cv[t].y - tw * u[t].y;
                    float2 nv; nv.x = nx; nv.y = ny;
                    cc[lane + 32*t] = nv;
                    if (r0     > j + 1) nss = fmaf(nx, nx, nss);
                    if (r0 + 1 > j + 1) nss = fmaf(ny, ny, nss);
                }
                #pragma unroll
                for (int o = 16; o; o >>= 1) nss += __shfl_xor_sync(0xffffffffu, nss, o);
                if (lane == 0) s_ss[(j + 1) & 1] = nss;
            } else {
                #pragma unroll
                for (int t = 0; t < 8; t++) {
                    float2 nv;
                    nv.x = cv[t].x - tw * u[t].x;
                    nv.y = cv[t].y - tw * u[t].y;
                    cc[lane + 32*t] = nv;
                }
            }
        }
        __syncthreads();
    }
    for (int i = tid; i < 4096; i += 512) {
        int c = i >> 6, r = i & 63;
        float v = (r < c) ? As[c*QR_LDC + r] : ((r == c) ? sbeta[c] : 0.f);
        R_out[(long long)mat*4096 + i] = v;
    }
}

// ---------------- invert upper-triangular R -> bf16 hi/lo transposed ------------
__global__ __launch_bounds__(64) void rinv_kernel(const float* __restrict__ R,
                                                  bf16* __restrict__ rih,
                                                  bf16* __restrict__ ril) {
    __shared__ float Rs[4096];
    __shared__ float xs[64*65];
    int mat = blockIdx.x, tid = threadIdx.x;
    for (int i = tid; i < 4096; i += 64) Rs[i] = R[(long long)mat*4096 + i];
    __syncthreads();
    int c = tid;
    float* x = xs + c*65;
    for (int i = c; i >= 0; i--) {
        float sacc = (i == c) ? 1.f : 0.f;
        for (int k = i + 1; k <= c; k++)
            sacc = fmaf(-Rs[k*64 + i], x[k], sacc);
        x[i] = sacc / Rs[i*64 + i];
    }
    for (int k = 0; k < 64; k++) {
        float v = (k <= c) ? x[k] : 0.f;
        bf16 h, l; wsplit(v, h, l);
        long long o = (long long)mat*4096 + c*64 + k;
        rih[o] = h; ril[o] = l;
    }
}

// ---------------- fused head-mix + softmax (6-channel 2-level reduction) --------
__global__ __launch_bounds__(512) void mix_softmax(
    const float* __restrict__ qk, const float* __restrict__ dots,
    const float* __restrict__ qn2, const float* __restrict__ kn2,
    const float* __restrict__ conv_w, const float* __restrict__ conv_b,
    const float* __restrict__ sp, const float* __restrict__ rp,
    const float* __restrict__ gp, float* __restrict__ attn,
    bf16* __restrict__ ahi, bf16* __restrict__ alo) {
    __shared__ float wsh[108], bsh[6], qsh[6];
    __shared__ float part[6][17];
    __shared__ float fin[6], fin2[6];
    int bn = blockIdx.x; int b = bn >> 9, n = bn & 511;
    int m = threadIdx.x;
    int lane = m & 31, wid = m >> 5;
    if (m < 108) wsh[m] = conv_w[m];
    if (m < 6) { bsh[m] = conv_b[m]; qsh[m] = qn2[((b*6 + m) << 9) + n]; }
    float scale = *sp, rs = *rp, gs = *gp;
    __syncthreads();
    float mixed[6];
    #pragma unroll
    for (int o = 0; o < 6; o++) mixed[o] = bsh[o];
    #pragma unroll
    for (int h = 0; h < 6; h++) {
        long long idx = ((long long)((b*6 + h)*512 + n) << 9) + m;
        float qv = qk[idx];
        float dd = dots[idx];
        float e  = qv * scale;
        float qn = qsh[h];
        float kn = kn2[((b*6 + h) << 9) + m];
        float d2 = qn*qn + kn*kn - 2.f*qv*qv;
        float ri = sqrtf(fmaxf(d2, 0.f)) * rs;
        float gg = dd*dd * gs;
        #pragma unroll
        for (int o = 0; o < 6; o++)
            mixed[o] += wsh[o*18 + h]*e + wsh[o*18 + 6 + h]*ri + wsh[o*18 + 12 + h]*gg;
    }
    #pragma unroll
    for (int o = 0; o < 6; o++) {
        float v = mixed[o];
        #pragma unroll
        for (int d = 16; d; d >>= 1) v = fmaxf(v, __shfl_xor_sync(0xffffffffu, v, d));
        if (lane == 0) part[o][wid] = v;
    }
    __syncthreads();
    if (m < 96) {
        int o = m >> 4, l = m & 15;
        float v = part[o][l];
        #pragma unroll
        for (int d = 8; d; d >>= 1) v = fmaxf(v, __shfl_xor_sync(0xffffffffu, v, d));
        if (l == 0) fin[o] = v;
    }
    __syncthreads();
    float e[6];
    #pragma unroll
    for (int o = 0; o < 6; o++) {
        e[o] = expf(mixed[o] - fin[o]);
        float v = e[o];
        #pragma unroll
        for (int d = 16; d; d >>= 1) v += __shfl_xor_sync(0xffffffffu, v, d);
        if (lane == 0) part[o][wid] = v;
    }
    __syncthreads();
    if (m < 96) {
        int o = m >> 4, l = m & 15;
        float v = part[o][l];
        #pragma unroll
        for (int d = 8; d; d >>= 1) v += __shfl_xor_sync(0xffffffffu, v, d);
        if (l == 0) fin2[o] = v;
    }
    __syncthreads();
    #pragma unroll
    for (int o = 0; o < 6; o++) {
        float v = e[o] / fin2[o];
        long long idx = ((long long)((b*6 + o)*512 + n) << 9) + m;
        attn[idx] = v;
        bf16 h_, l_; wsplit(v, h_, l_);
        ahi[idx] = h_; alo[idx] = l_;
    }
}

// ================================================================================
extern "C" void kernel_launch(void* const* d_in, const int* in_sizes, int n_in,
                              void* d_out, int out_size) {
    const float* src     = (const float*)d_in[0];
    const float* pre_w   = (const float*)d_in[1];
    const float* pre_b   = (const float*)d_in[2];
    const float* qkv_w   = (const float*)d_in[3];
    const float* qkv_b   = (const float*)d_in[4];
    const float* scale_p = (const float*)d_in[5];
    const float* riem_p  = (const float*)d_in[6];
    const float* grass_p = (const float*)d_in[7];
    const float* conv_w  = (const float*)d_in[8];
    const float* conv_b  = (const float*)d_in[9];
    const float* proj_w  = (const float*)d_in[10];
    const float* proj_b  = (const float*)d_in[11];
    const float* n1_w    = (const float*)d_in[12];
    const float* n1_b    = (const float*)d_in[13];
    const float* l1_w    = (const float*)d_in[14];
    const float* l1_b    = (const float*)d_in[15];
    const float* l2_w    = (const float*)d_in[16];
    const float* l2_b    = (const float*)d_in[17];
    float* out = (float*)d_out;

    float *qkv, *R, *qn2, *kn2, *scores, *attn, *t, *u;
    cudaGetSymbolAddress((void**)&qkv,    g_qkv);
    cudaGetSymbolAddress((void**)&R,      g_R);
    cudaGetSymbolAddress((void**)&qn2,    g_qn2);
    cudaGetSymbolAddress((void**)&kn2,    g_kn2);
    cudaGetSymbolAddress((void**)&scores, g_scores);
    cudaGetSymbolAddress((void**)&attn,   g_attn);
    cudaGetSymbolAddress((void**)&t,      g_t);
    cudaGetSymbolAddress((void**)&u,      g_u);

    bf16 *plh,*pll,*xh,*xl,*qwh,*qwl,*rih,*ril,
         *vth,*vtl,*ath,*atl,*aoh,*aol,*pwh,*pwl,*uh,*ul,*l1h,*l1l,*h1h,*h1l,*l2h,*l2l;
    cudaGetSymbolAddress((void**)&plh, sPool_hi); cudaGetSymbolAddress((void**)&pll, sPool_lo);
    cudaGetSymbolAddress((void**)&xh,  sX_hi);  cudaGetSymbolAddress((void**)&xl,  sX_lo);
    cudaGetSymbolAddress((void**)&qwh, sQW_hi); cudaGetSymbolAddress((void**)&qwl, sQW_lo);
    cudaGetSymbolAddress((void**)&rih, sRi_hi); cudaGetSymbolAddress((void**)&ril, sRi_lo);
    cudaGetSymbolAddress((void**)&vth, sVT_hi); cudaGetSymbolAddress((void**)&vtl, sVT_lo);
    cudaGetSymbolAddress((void**)&ath, sAt_hi); cudaGetSymbolAddress((void**)&atl, sAt_lo);
    cudaGetSymbolAddress((void**)&aoh, sAo_hi); cudaGetSymbolAddress((void**)&aol, sAo_lo);
    cudaGetSymbolAddress((void**)&pwh, sPW_hi); cudaGetSymbolAddress((void**)&pwl, sPW_lo);
    cudaGetSymbolAddress((void**)&uh,  sU_hi);  cudaGetSymbolAddress((void**)&ul,  sU_lo);
    cudaGetSymbolAddress((void**)&l1h, sL1_hi); cudaGetSymbolAddress((void**)&l1l, sL1_lo);
    cudaGetSymbolAddress((void**)&h1h, sH1_hi); cudaGetSymbolAddress((void**)&h1l, sH1_lo);
    cudaGetSymbolAddress((void**)&l2h, sL2_hi); cudaGetSymbolAddress((void**)&l2l, sL2_lo);

    const int SMEM_QR = 64 * QR_LDC * 4;
    const int SMG128 = 3 * (2*128*40*2 + 2*128*40*2);   // 122880
    const int SMG64  = 3 * (2*128*40*2 + 2*64*40*2);    //  92160
    cudaFuncSetAttribute(qr_forward,    cudaFuncAttributeMaxDynamicSharedMemorySize, SMEM_QR);
    cudaFuncSetAttribute(mma_gemm<128>, cudaFuncAttributeMaxDynamicSharedMemorySize, SMG128);
    cudaFuncSetAttribute(mma_gemm<64>,  cudaFuncAttributeMaxDynamicSharedMemorySize, SMG64);

    long long need = (long long)BN_*C_ + (long long)BH_*N_*N_;
    bool attn_in_out = ((long long)out_size >= need);
    float* attn_dst = attn_in_out ? (out + (long long)BN_*C_) : attn;

    const long long SLOT = 32768;   // one head-matrix (512x64) in pool

    // 1. pre-LN -> bf16 only (fp32 x is dead)
    ln_kernel<<<BN_, 128>>>(src, pre_w, pre_b, nullptr, xh, xl);
    // 1b. split all weights in one launch
    {
        int n0 = FF_*C_, n1 = C_*C_, n2 = FF_*C_, n3 = C_*FF_;
        int tot = n0 + n1 + n2 + n3;
        split4_kernel<<<(tot + 255)/256, 256>>>(
            qkv_w, qwh, qwl, n0,  proj_w, pwh, pwl, n1,
            l1_w, l1h, l1l, n2,   l2_w, l2h, l2l, n3);
    }
    // 2. QKV GEMM (M=8192, N=1152, K=384) + bias -> qkv fp32
    mma_gemm<128><<<dim3(9, 64, 1), 256, SMG128>>>(xh, xl, qwh, qwl, nullptr, qkv_b,
        qkv, nullptr, nullptr, C_, FF_, 0, 0, 0, 0, 1, 1);
    // 3. fused q/k split + norms -> pool slots 0..191
    qk_split_kernel<<<192*512/8, 256>>>(qkv, plh, pll, qn2, kn2);
    // 4. Householder factorization -> R ; invert -> RiT bf16 hi/lo
    qr_forward<<<192, 512, SMEM_QR>>>(qkv, R);
    rinv_kernel<<<192, 64>>>(R, rih, ril);
    // 4b. [qgr;kgr] = [q;k] @ Rinv -> pool slots 192..383 (bf16 only)
    mma_gemm<64><<<dim3(1, 4, 192), 256, SMG64>>>(plh, pll, rih, ril, nullptr, nullptr,
        nullptr, plh + 192*SLOT, pll + 192*SLOT, 64, 64, SLOT, 4096LL, SLOT, 0, 1, 8|16);
    // 5+6. merged score GEMM (z=192): qk for z<96, dots for z>=96
    mma_gemm<128><<<dim3(4, 4, 192), 256, SMG128>>>(plh, pll, plh + 96*SLOT, pll + 96*SLOT,
        nullptr, nullptr, scores, nullptr, nullptr, 64, 512,
        SLOT, SLOT, 262144LL, 0, 1, 32);
    // 7. v transpose -> bf16
    vT_bf16_kernel<<<dim3(96, 8), 256>>>(qkv, vth, vtl);
    // 8. mix + softmax -> attn fp32 + bf16
    mix_softmax<<<BN_, 512>>>(scores, scores + 96LL*262144, qn2, kn2, conv_w, conv_b,
                              scale_p, riem_p, grass_p, attn_dst, ath, atl);
    // 9. ao = attn @ v -> bf16 only, laid [b,n,h*64+d]
    mma_gemm<64><<<dim3(1, 4, 96), 256, SMG64>>>(ath, atl, vth, vtl, nullptr, nullptr,
        nullptr, aoh, aol, 512, 384, 262144LL, SLOT, 196608LL, 64LL, 6, 8|16);
    // 10. proj + bias + residual(src) -> t
    mma_gemm<128><<<dim3(3, 64, 1), 256, SMG128>>>(aoh, aol, pwh, pwl, src, proj_b,
        t, nullptr, nullptr, C_, C_, 0, 0, 0, 0, 1, 1|4);
    // 11. norm1 -> u fp32 (needed for residual) + bf16
    ln_kernel<<<BN_, 128>>>(t, n1_w, n1_b, u, uh, ul);
    // 12. lin1 + bias + gelu -> h1 bf16 only
    mma_gemm<128><<<dim3(9, 64, 1), 256, SMG128>>>(uh, ul, l1h, l1l, nullptr, l1_b,
        nullptr, h1h, h1l, C_, FF_, 0, 0, 0, 0, 1, 1|2|8|16);
    // 13. lin2 + bias + residual(u) -> d_out
    mma_gemm<128><<<dim3(3, 64, 1), 256, SMG128>>>(h1h, h1l, l2h, l2l, u, l2_b,
        out, nullptr, nullptr, FF_, C_, 0, 0, 0, 0, 1, 1|4);
}

// round 12
// speedup vs baseline: 2.3450x; 1.0090x over previous
#include <cuda_runtime.h>
#include <cuda_bf16.h>
#include <math.h>
#include <stdint.h>

typedef __nv_bfloat16 bf16;

#define B_  16
#define N_  512
#define C_  384
#define H_  6
#define HD_ 64
#define FF_ 1152
#define BN_ (B_*N_)   // 8192
#define BH_ (B_*H_)   // 96

// ---------------- fp32 scratch --------------------------------------------------
__device__ __align__(16) float g_qkv [BN_*3*C_];
__device__ __align__(16) float g_R   [192*64*64];
__device__ __align__(16) float g_qn2 [BH_*N_];
__device__ __align__(16) float g_kn2 [BH_*N_];
__device__ __align__(16) float g_scores[(long long)2*BH_*N_*N_];  // [qk ; dots]
__device__ __align__(16) float g_attn[(long long)BH_*N_*N_];
__device__ __align__(16) float g_t   [BN_*C_];
__device__ __align__(16) float g_u   [BN_*C_];

// ---------------- bf16 hi/lo operand pools --------------------------------------
// unified score pool: slots [q(0..95) | k(96..191) | qgr(192..287) | kgr(288..383)]
__device__ __align__(16) bf16 sPool_hi[384LL*N_*HD_], sPool_lo[384LL*N_*HD_];
__device__ __align__(16) bf16 sX_hi [BN_*C_],        sX_lo [BN_*C_];
__device__ __align__(16) bf16 sQW_hi[FF_*C_],        sQW_lo[FF_*C_];
__device__ __align__(16) bf16 sRi_hi[192*64*64],     sRi_lo[192*64*64];
__device__ __align__(16) bf16 sVT_hi[BH_*HD_*N_],    sVT_lo[BH_*HD_*N_];
__device__ __align__(16) bf16 sAt_hi[(long long)BH_*N_*N_], sAt_lo[(long long)BH_*N_*N_];
__device__ __align__(16) bf16 sAo_hi[BN_*C_],        sAo_lo[BN_*C_];
__device__ __align__(16) bf16 sPW_hi[C_*C_],         sPW_lo[C_*C_];
__device__ __align__(16) bf16 sU_hi [BN_*C_],        sU_lo [BN_*C_];
__device__ __align__(16) bf16 sL1_hi[FF_*C_],        sL1_lo[FF_*C_];
__device__ __align__(16) bf16 sH1_hi[BN_*FF_],       sH1_lo[BN_*FF_];
__device__ __align__(16) bf16 sL2_hi[C_*FF_],        sL2_lo[C_*FF_];

// ---------------- PTX helpers ---------------------------------------------------
__device__ __forceinline__ uint32_t smem_u32(const void* p) {
    uint32_t a;
    asm("{ .reg .u64 t; cvta.to.shared.u64 t, %1; cvt.u32.u64 %0, t; }" : "=r"(a) : "l"(p));
    return a;
}
__device__ __forceinline__ void cpa16(uint32_t s, const void* g) {
    asm volatile("cp.async.ca.shared.global [%0], [%1], 16;" :: "r"(s), "l"(g));
}
__device__ __forceinline__ void cpa_commit() {
    asm volatile("cp.async.commit_group;" ::: "memory");
}
__device__ __forceinline__ void cpa_wait1() {
    asm volatile("cp.async.wait_group 1;" ::: "memory");
}
__device__ __forceinline__ void ldsm4(uint32_t* r, uint32_t addr) {
    asm volatile("ldmatrix.sync.aligned.m8n8.x4.shared.b16 {%0,%1,%2,%3}, [%4];"
        : "=r"(r[0]), "=r"(r[1]), "=r"(r[2]), "=r"(r[3]) : "r"(addr));
}
__device__ __forceinline__ void mma_bf16(float* d, const uint32_t* a, uint32_t b0, uint32_t b1) {
    asm volatile("mma.sync.aligned.m16n8k16.row.col.f32.bf16.bf16.f32 "
        "{%0,%1,%2,%3}, {%4,%5,%6,%7}, {%8,%9}, {%0,%1,%2,%3};"
        : "+f"(d[0]), "+f"(d[1]), "+f"(d[2]), "+f"(d[3])
        : "r"(a[0]), "r"(a[1]), "r"(a[2]), "r"(a[3]), "r"(b0), "r"(b1));
}
__device__ __forceinline__ float gelu_f(float v) {
    return 0.5f * v * (1.f + erff(v * 0.70710678118654752f));
}
__device__ __forceinline__ void wsplit(float v, bf16& h, bf16& l) {
    h = __float2bfloat16(v);
    l = __float2bfloat16(v - __bfloat162float(h));
}

// ---------------- block reductions (used by LN) ---------------------------------
__device__ __forceinline__ float bred_sum(float v, float* red, int nw) {
    int lane = threadIdx.x & 31, wid = threadIdx.x >> 5;
    #pragma unroll
    for (int o = 16; o; o >>= 1) v += __shfl_xor_sync(0xffffffffu, v, o);
    if (lane == 0) red[wid] = v;
    __syncthreads();
    if (wid == 0) {
        float t = (lane < nw) ? red[lane] : 0.f;
        #pragma unroll
        for (int o = 16; o; o >>= 1) t += __shfl_xor_sync(0xffffffffu, t, o);
        if (lane == 0) red[32] = t;
    }
    __syncthreads();
    float r = red[32];
    __syncthreads();
    return r;
}

// ---------------- LayerNorm (fp32 out optional + bf16 hi/lo) --------------------
__global__ __launch_bounds__(128) void ln_kernel(
    const float* __restrict__ in, const float* __restrict__ w,
    const float* __restrict__ b, float* __restrict__ out,
    bf16* __restrict__ ohi, bf16* __restrict__ olo) {
    __shared__ float red[33];
    int row = blockIdx.x;
    const float* x = in + (long long)row * C_;
    float v0[3]; float s = 0.f;
    #pragma unroll
    for (int i = 0; i < 3; i++) { v0[i] = x[threadIdx.x + 128*i]; s += v0[i]; }
    s = bred_sum(s, red, 4);
    float mu = s * (1.f / C_);
    float var = 0.f;
    #pragma unroll
    for (int i = 0; i < 3; i++) { float d = v0[i] - mu; var = fmaf(d, d, var); }
    var = bred_sum(var, red, 4) * (1.f / C_);
    float inv = rsqrtf(var + 1e-5f);
    #pragma unroll
    for (int i = 0; i < 3; i++) {
        int c = threadIdx.x + 128*i;
        float v = (v0[i] - mu) * inv * w[c] + b[c];
        long long idx = (long long)row*C_ + c;
        if (out) out[idx] = v;
        bf16 h, l; wsplit(v, h, l);
        ohi[idx] = h; olo[idx] = l;
    }
}

// ---------------- one-shot 4-segment fp32 -> bf16 hi/lo split -------------------
__global__ void split4_kernel(
    const float* __restrict__ s0, bf16* __restrict__ h0, bf16* __restrict__ l0, int n0,
    const float* __restrict__ s1, bf16* __restrict__ h1, bf16* __restrict__ l1, int n1,
    const float* __restrict__ s2, bf16* __restrict__ h2, bf16* __restrict__ l2, int n2,
    const float* __restrict__ s3, bf16* __restrict__ h3, bf16* __restrict__ l3, int n3) {
    int i = blockIdx.x * blockDim.x + threadIdx.x;
    const float* s; bf16 *hh, *ll; int j = i;
    if (j < n0) { s = s0; hh = h0; ll = l0; }
    else {
        j -= n0;
        if (j < n1) { s = s1; hh = h1; ll = l1; }
        else {
            j -= n1;
            if (j < n2) { s = s2; hh = h2; ll = l2; }
            else {
                j -= n2;
                if (j >= n3) return;
                s = s3; hh = h3; ll = l3;
            }
        }
    }
    float v = s[j];
    bf16 h, l; wsplit(v, h, l);
    hh[j] = h; ll[j] = l;
}

// ---------------- fused q/k split + per-row sumsq (warp per row) ----------------
__global__ __launch_bounds__(256) void qk_split_kernel(
    const float* __restrict__ qkv, bf16* __restrict__ hi, bf16* __restrict__ lo,
    float* __restrict__ qn2, float* __restrict__ kn2) {
    int gw = blockIdx.x * 8 + (threadIdx.x >> 5);
    int lane = threadIdx.x & 31;
    int r = gw & 511;
    int z = gw >> 9;
    int s = (z >= 96) ? 1 : 0;
    int bh = z - s*96;
    int b = bh / 6, h = bh - (bh/6)*6;
    const float* p = qkv + (long long)(b*512 + r)*1152 + s*384 + h*64;
    float v0 = p[lane], v1 = p[lane + 32];
    long long o = (long long)z*32768 + r*64 + lane;
    bf16 h0, l0, h1, l1;
    wsplit(v0, h0, l0); wsplit(v1, h1, l1);
    hi[o] = h0; lo[o] = l0;
    hi[o + 32] = h1; lo[o + 32] = l1;
    float ss = fmaf(v0, v0, v1*v1);
    #pragma unroll
    for (int d = 16; d; d >>= 1) ss += __shfl_xor_sync(0xffffffffu, ss, d);
    if (lane == 0) {
        if (s) kn2[bh*512 + r] = ss; else qn2[bh*512 + r] = ss;
    }
}

// ---------------- bf16-split tensor-core GEMM: C = A * B^T ----------------------
// flags: 1=bias, 2=gelu, 4=residual, 8=write bf16 hi/lo, 16=skip fp32 C,
//        32=score mode (zi = z + 96*[z>=96]; B pool offset pre-applied by caller)
// Inner loop issues the three split terms in separate passes so each accumulator's
// RAW chain distance is NT*2 mmas instead of 1 (term order per acc unchanged:
// hh -> hl -> lh, so fp32 accumulation order — and thus numerics — is identical).
template<int BN>
__global__ __launch_bounds__(256) void mma_gemm(
    const bf16* __restrict__ Ahi, const bf16* __restrict__ Alo,
    const bf16* __restrict__ Bhi, const bf16* __restrict__ Blo,
    const float* __restrict__ Rres, const float* __restrict__ bias,
    float* __restrict__ Cout, bf16* __restrict__ Whi, bf16* __restrict__ Wlo,
    int K, int ldc, long long sA, long long sB,
    long long Cb, long long Ch, int Hdiv, int flags)
{
    constexpr int WN  = BN / 2;
    constexpr int NT  = WN / 16;
    constexpr int NF  = WN / 8;
    constexpr int ATB = 128*40*2;
    constexpr int BTB = BN*40*2;
    constexpr int STG = 2*ATB + 2*BTB;

    extern __shared__ __align__(16) bf16 dyn[];
    uint32_t sbase = smem_u32(dyn);

    int z = blockIdx.z;
    int zi = z + ((flags & 32) && z >= 96 ? 96 : 0);
    const bf16* pAhi = Ahi + (long long)zi*sA;
    const bf16* pAlo = Alo + (long long)zi*sA;
    const bf16* pBhi = Bhi + (long long)zi*sB;
    const bf16* pBlo = Blo + (long long)zi*sB;
    int zb = z / Hdiv, zh = z - zb*Hdiv;
    long long co = Cb*zb + Ch*zh;

    int m0 = blockIdx.y << 7, n0 = blockIdx.x * BN;
    int tid = threadIdx.x, wid = tid >> 5, lane = tid & 31;
    int wm = wid >> 1, wn = wid & 1;
    int r16 = lane & 15, kh = lane >> 4;

    float acc[2][NF][4];
    #pragma unroll
    for (int a = 0; a < 2; a++)
        #pragma unroll
        for (int f = 0; f < NF; f++)
            #pragma unroll
            for (int q = 0; q < 4; q++) acc[a][f][q] = 0.f;

    int kt = K >> 5;

    auto load_tile = [&](int t) {
        int s = t % 3;
        uint32_t ab = sbase + (uint32_t)(s * STG);
        int k0 = t << 5;
        #pragma unroll
        for (int i = tid; i < 128*4; i += 256) {
            int r = i >> 2, c = i & 3;
            uint32_t so = ab + (uint32_t)((r*40 + c*8) * 2);
            cpa16(so, pAhi + (long long)(m0 + r)*K + k0 + c*8);
            cpa16(so + ATB, pAlo + (long long)(m0 + r)*K + k0 + c*8);
        }
        uint32_t bbb = sbase + (uint32_t)(s * STG) + 2*ATB;
        #pragma unroll
        for (int i = tid; i < BN*4; i += 256) {
            int r = i >> 2, c = i & 3;
            uint32_t so = bbb + (uint32_t)((r*40 + c*8) * 2);
            cpa16(so, pBhi + (long long)(n0 + r)*K + k0 + c*8);
            cpa16(so + BTB, pBlo + (long long)(n0 + r)*K + k0 + c*8);
        }
    };

    load_tile(0); cpa_commit();
    if (kt > 1) load_tile(1);
    cpa_commit();

    for (int t = 0; t < kt; t++) {
        cpa_wait1();
        __syncthreads();
        if (t + 2 < kt) load_tile(t + 2);
        cpa_commit();

        int s = t % 3;
        uint32_t ab = sbase + (uint32_t)(s * STG);
        uint32_t bb = ab + 2*ATB;
        #pragma unroll
        for (int kk = 0; kk < 2; kk++) {
            uint32_t a_hi[2][4], a_lo[2][4];
            uint32_t b_hi[NT][4], b_lo[NT][4];
            #pragma unroll
            for (int mt = 0; mt < 2; mt++) {
                uint32_t ad = ab + (uint32_t)(((wm*32 + mt*16 + r16)*40 + kk*16 + kh*8) * 2);
                ldsm4(a_hi[mt], ad);
                ldsm4(a_lo[mt], ad + ATB);
            }
            #pragma unroll
            for (int nt = 0; nt < NT; nt++) {
                uint32_t bd = bb + (uint32_t)(((wn*WN + nt*16 + r16)*40 + kk*16 + kh*8) * 2);
                ldsm4(b_hi[nt], bd);
                ldsm4(b_lo[nt], bd + BTB);
            }
            // pass 1: hi * hi
            #pragma unroll
            for (int mt = 0; mt < 2; mt++)
                #pragma unroll
                for (int nt = 0; nt < NT; nt++) {
                    mma_bf16(acc[mt][2*nt],     a_hi[mt], b_hi[nt][0], b_hi[nt][2]);
                    mma_bf16(acc[mt][2*nt + 1], a_hi[mt], b_hi[nt][1], b_hi[nt][3]);
                }
            // pass 2: hi * lo
            #pragma unroll
            for (int mt = 0; mt < 2; mt++)
                #pragma unroll
                for (int nt = 0; nt < NT; nt++) {
                    mma_bf16(acc[mt][2*nt],     a_hi[mt], b_lo[nt][0], b_lo[nt][2]);
                    mma_bf16(acc[mt][2*nt + 1], a_hi[mt], b_lo[nt][1], b_lo[nt][3]);
                }
            // pass 3: lo * hi
            #pragma unroll
            for (int mt = 0; mt < 2; mt++)
                #pragma unroll
                for (int nt = 0; nt < NT; nt++) {
                    mma_bf16(acc[mt][2*nt],     a_lo[mt], b_hi[nt][0], b_hi[nt][2]);
                    mma_bf16(acc[mt][2*nt + 1], a_lo[mt], b_hi[nt][1], b_hi[nt][3]);
                }
        }
    }

    #pragma unroll
    for (int mt = 0; mt < 2; mt++)
    #pragma unroll
    for (int f = 0; f < NF; f++) {
        float* c = acc[mt][f];
        int row = m0 + wm*32 + mt*16 + (lane >> 2);
        int col = n0 + wn*WN + f*8 + ((lane & 3) << 1);
        #pragma unroll
        for (int half = 0; half < 2; half++) {
            int r = row + half*8;
            float v0 = c[half*2 + 0], v1 = c[half*2 + 1];
            if (flags & 1) { v0 += bias[col]; v1 += bias[col + 1]; }
            if (flags & 2) { v0 = gelu_f(v0); v1 = gelu_f(v1); }
            long long idx = co + (long long)r*ldc + col;
            if (flags & 4) {
                float2 rr = *(const float2*)(Rres + idx);
                v0 += rr.x; v1 += rr.y;
            }
            if (!(flags & 16)) {
                float2 o; o.x = v0; o.y = v1;
                *(float2*)(Cout + idx) = o;
            }
            if (flags & 8) {
                bf16 h0, l0, h1, l1;
                wsplit(v0, h0, l0); wsplit(v1, h1, l1);
                __nv_bfloat162 hh; hh.x = h0; hh.y = h1;
                __nv_bfloat162 ll; ll.x = l0; ll.y = l1;
                *(__nv_bfloat162*)(Whi + idx) = hh;
                *(__nv_bfloat162*)(Wlo + idx) = ll;
            }
        }
    }
}

// ---------------- v transpose via smem tile (coalesced both sides) --------------
__global__ __launch_bounds__(256) void vT_bf16_kernel(const float* __restrict__ qkv,
                                                      bf16* __restrict__ hi,
                                                      bf16* __restrict__ lo) {
    __shared__ float tile[64][65];
    int bh = blockIdx.x;
    int m0 = blockIdx.y << 6;
    int b = bh / 6, h = bh - (bh/6)*6;
    int tid = threadIdx.x;
    for (int i = tid; i < 4096; i += 256) {
        int m = i >> 6, d = i & 63;
        tile[d][m] = qkv[(long long)(b*512 + m0 + m)*1152 + 768 + h*64 + d];
    }
    __syncthreads();
    for (int i = tid; i < 4096; i += 256) {
        int d = i >> 6, m = i & 63;
        float v = tile[d][m];
        bf16 h_, l_; wsplit(v, h_, l_);
        long long o = (long long)bh*32768 + d*512 + m0 + m;
        hi[o] = h_; lo[o] = l_;
    }
}

// ---------------- Householder QR factorization (sgeqr2, float2 rows) ------------
#define QR_LDC 514
__global__ __launch_bounds__(512) void qr_forward(const float* __restrict__ qkv,
                                                  float* __restrict__ R_out) {
    extern __shared__ float As[];
    __shared__ float red[33];
    __shared__ float sbeta[64];
    __shared__ float s_ss[2];
    int mat = blockIdx.x;
    int s = (mat >= 96) ? 1 : 0;
    int bh = mat - s*96;
    int b = bh / 6, h = bh - (bh/6)*6;
    const float* Ab = qkv + (long long)b*512*1152 + s*384 + h*64;
    int tid = threadIdx.x;
    int wid = tid >> 5, lane = tid & 31;

    for (int i = tid; i < 64*512; i += 512) {
        int n = i >> 6, d = i & 63;
        As[d*QR_LDC + n] = Ab[(long long)n*1152 + d];
    }
    __syncthreads();
    {
        float x = (tid > 0) ? As[tid] : 0.f;
        float ss0 = bred_sum(x*x, red, 16);
        if (tid == 0) s_ss[0] = ss0;
    }
    __syncthreads();

    for (int j = 0; j < 64; j++) {
        float* col = As + j*QR_LDC;
        float alpha = col[j];
        float ss = s_ss[j & 1];
        float beta, teff, uj;
        if (ss == 0.f) { beta = alpha; teff = 0.f; uj = 1.f; }
        else {
            float nrm = sqrtf(alpha*alpha + ss);
            beta = (alpha >= 0.f) ? -nrm : nrm;   // LAPACK sign
            float tau = (beta - alpha) / beta;
            uj  = alpha - beta;
            teff = tau / (uj * uj);
        }
        if (tid == 0) sbeta[j] = beta;
        const float2* colv = (const float2*)col;
        float2 u[8];
        #pragma unroll
        for (int t = 0; t < 8; t++) {
            float2 vv = colv[lane + 32*t];
            int r0 = (lane + 32*t) << 1;
            u[t].x = (r0     > j) ? vv.x : ((r0     == j) ? uj : 0.f);
            u[t].y = (r0 + 1 > j) ? vv.y : ((r0 + 1 == j) ? uj : 0.f);
        }
        for (int c = j + 1 + wid; c < 64; c += 16) {
            float2* cc = (float2*)(As + c*QR_LDC);
            float2 cv[8];
            float w = 0.f;
            #pragma unroll
            for (int t = 0; t < 8; t++) {
                cv[t] = cc[lane + 32*t];
                w = fmaf(u[t].x, cv[t].x, w);
                w = fmaf(u[t].y, cv[t].y, w);
            }
            #pragma unroll
            for (int o = 16; o; o >>= 1) w += __shfl_xor_sync(0xffffffffu, w, o);
            float tw = teff * w;
            if (c == j + 1) {
                float nss = 0.f;
                #pragma unroll
                for (int t = 0; t < 8; t++) {
                    int r0 = (lane + 32*t) << 1;
                    float nx = cv[t].x - tw * u[t].x;
                    float ny = cv[t].y - tw * u[t].y;
                    float2 nv; nv.x = nx; nv.y = ny;
                    cc[lane + 32*t] = nv;
                    if (r0     > j + 1) nss = fmaf(nx, nx, nss);
                    if (r0 + 1 > j + 1) nss = fmaf(ny, ny, nss);
                }
                #pragma unroll
                for (int o = 16; o; o >>= 1) nss += __shfl_xor_sync(0xffffffffu, nss, o);
                if (lane == 0) s_ss[(j + 1) & 1] = nss;
            } else {
                #pragma unroll
                for (int t = 0; t < 8; t++) {
                    float2 nv;
                    nv.x = cv[t].x - tw * u[t].x;
                    nv.y = cv[t].y - tw * u[t].y;
                    cc[lane + 32*t] = nv;
                }
            }
        }
        __syncthreads();
    }
    for (int i = tid; i < 4096; i += 512) {
        int c = i >> 6, r = i & 63;
        float v = (r < c) ? As[c*QR_LDC + r] : ((r == c) ? sbeta[c] : 0.f);
        R_out[(long long)mat*4096 + i] = v;
    }
}

// ---------------- invert upper-triangular R -> bf16 hi/lo transposed ------------
__global__ __launch_bounds__(64) void rinv_kernel(const float* __restrict__ R,
                                                  bf16* __restrict__ rih,
                                                  bf16* __restrict__ ril) {
    __shared__ float Rs[4096];
    __shared__ float xs[64*65];
    int mat = blockIdx.x, tid = threadIdx.x;
    for (int i = tid; i < 4096; i += 64) Rs[i] = R[(long long)mat*4096 + i];
    __syncthreads();
    int c = tid;
    float* x = xs + c*65;
    for (int i = c; i >= 0; i--) {
        float sacc = (i == c) ? 1.f : 0.f;
        for (int k = i + 1; k <= c; k++)
            sacc = fmaf(-Rs[k*64 + i], x[k], sacc);
        x[i] = sacc / Rs[i*64 + i];
    }
    for (int k = 0; k < 64; k++) {
        float v = (k <= c) ? x[k] : 0.f;
        bf16 h, l; wsplit(v, h, l);
        long long o = (long long)mat*4096 + c*64 + k;
        rih[o] = h; ril[o] = l;
    }
}

// ---------------- fused head-mix + softmax (6-channel 2-level reduction) --------
__global__ __launch_bounds__(512) void mix_softmax(
    const float* __restrict__ qk, const float* __restrict__ dots,
    const float* __restrict__ qn2, const float* __restrict__ kn2,
    const float* __restrict__ conv_w, const float* __restrict__ conv_b,
    const float* __restrict__ sp, const float* __restrict__ rp,
    const float* __restrict__ gp, float* __restrict__ attn,
    bf16* __restrict__ ahi, bf16* __restrict__ alo) {
    __shared__ float wsh[108], bsh[6], qsh[6];
    __shared__ float part[6][17];
    __shared__ float fin[6], fin2[6];
    int bn = blockIdx.x; int b = bn >> 9, n = bn & 511;
    int m = threadIdx.x;
    int lane = m & 31, wid = m >> 5;
    if (m < 108) wsh[m] = conv_w[m];
    if (m < 6) { bsh[m] = conv_b[m]; qsh[m] = qn2[((b*6 + m) << 9) + n]; }
    float scale = *sp, rs = *rp, gs = *gp;
    __syncthreads();
    float mixed[6];
    #pragma unroll
    for (int o = 0; o < 6; o++) mixed[o] = bsh[o];
    #pragma unroll
    for (int h = 0; h < 6; h++) {
        long long idx = ((long long)((b*6 + h)*512 + n) << 9) + m;
        float qv = qk[idx];
        float dd = dots[idx];
        float e  = qv * scale;
        float qn = qsh[h];
        float kn = kn2[((b*6 + h) << 9) + m];
        float d2 = qn*qn + kn*kn - 2.f*qv*qv;
        float ri = sqrtf(fmaxf(d2, 0.f)) * rs;
        float gg = dd*dd * gs;
        #pragma unroll
        for (int o = 0; o < 6; o++)
            mixed[o] += wsh[o*18 + h]*e + wsh[o*18 + 6 + h]*ri + wsh[o*18 + 12 + h]*gg;
    }
    #pragma unroll
    for (int o = 0; o < 6; o++) {
        float v = mixed[o];
        #pragma unroll
        for (int d = 16; d; d >>= 1) v = fmaxf(v, __shfl_xor_sync(0xffffffffu, v, d));
        if (lane == 0) part[o][wid] = v;
    }
    __syncthreads();
    if (m < 96) {
        int o = m >> 4, l = m & 15;
        float v = part[o][l];
        #pragma unroll
        for (int d = 8; d; d >>= 1) v = fmaxf(v, __shfl_xor_sync(0xffffffffu, v, d));
        if (l == 0) fin[o] = v;
    }
    __syncthreads();
    float e[6];
    #pragma unroll
    for (int o = 0; o < 6; o++) {
        e[o] = expf(mixed[o] - fin[o]);
        float v = e[o];
        #pragma unroll
        for (int d = 16; d; d >>= 1) v += __shfl_xor_sync(0xffffffffu, v, d);
        if (lane == 0) part[o][wid] = v;
    }
    __syncthreads();
    if (m < 96) {
        int o = m >> 4, l = m & 15;
        float v = part[o][l];
        #pragma unroll
        for (int d = 8; d; d >>= 1) v += __shfl_xor_sync(0xffffffffu, v, d);
        if (l == 0) fin2[o] = v;
    }
    __syncthreads();
    #pragma unroll
    for (int o = 0; o < 6; o++) {
        float v = e[o] / fin2[o];
        long long idx = ((long long)((b*6 + o)*512 + n) << 9) + m;
        attn[idx] = v;
        bf16 h_, l_; wsplit(v, h_, l_);
        ahi[idx] = h_; alo[idx] = l_;
    }
}

// ================================================================================
extern "C" void kernel_launch(void* const* d_in, const int* in_sizes, int n_in,
                              void* d_out, int out_size) {
    const float* src     = (const float*)d_in[0];
    const float* pre_w   = (const float*)d_in[1];
    const float* pre_b   = (const float*)d_in[2];
    const float* qkv_w   = (const float*)d_in[3];
    const float* qkv_b   = (const float*)d_in[4];
    const float* scale_p = (const float*)d_in[5];
    const float* riem_p  = (const float*)d_in[6];
    const float* grass_p = (const float*)d_in[7];
    const float* conv_w  = (const float*)d_in[8];
    const float* conv_b  = (const float*)d_in[9];
    const float* proj_w  = (const float*)d_in[10];
    const float* proj_b  = (const float*)d_in[11];
    const float* n1_w    = (const float*)d_in[12];
    const float* n1_b    = (const float*)d_in[13];
    const float* l1_w    = (const float*)d_in[14];
    const float* l1_b    = (const float*)d_in[15];
    const float* l2_w    = (const float*)d_in[16];
    const float* l2_b    = (const float*)d_in[17];
    float* out = (float*)d_out;

    float *qkv, *R, *qn2, *kn2, *scores, *attn, *t, *u;
    cudaGetSymbolAddress((void**)&qkv,    g_qkv);
    cudaGetSymbolAddress((void**)&R,      g_R);
    cudaGetSymbolAddress((void**)&qn2,    g_qn2);
    cudaGetSymbolAddress((void**)&kn2,    g_kn2);
    cudaGetSymbolAddress((void**)&scores, g_scores);
    cudaGetSymbolAddress((void**)&attn,   g_attn);
    cudaGetSymbolAddress((void**)&t,      g_t);
    cudaGetSymbolAddress((void**)&u,      g_u);

    bf16 *plh,*pll,*xh,*xl,*qwh,*qwl,*rih,*ril,
         *vth,*vtl,*ath,*atl,*aoh,*aol,*pwh,*pwl,*uh,*ul,*l1h,*l1l,*h1h,*h1l,*l2h,*l2l;
    cudaGetSymbolAddress((void**)&plh, sPool_hi); cudaGetSymbolAddress((void**)&pll, sPool_lo);
    cudaGetSymbolAddress((void**)&xh,  sX_hi);  cudaGetSymbolAddress((void**)&xl,  sX_lo);
    cudaGetSymbolAddress((void**)&qwh, sQW_hi); cudaGetSymbolAddress((void**)&qwl, sQW_lo);
    cudaGetSymbolAddress((void**)&rih, sRi_hi); cudaGetSymbolAddress((void**)&ril, sRi_lo);
    cudaGetSymbolAddress((void**)&vth, sVT_hi); cudaGetSymbolAddress((void**)&vtl, sVT_lo);
    cudaGetSymbolAddress((void**)&ath, sAt_hi); cudaGetSymbolAddress((void**)&atl, sAt_lo);
    cudaGetSymbolAddress((void**)&aoh, sAo_hi); cudaGetSymbolAddress((void**)&aol, sAo_lo);
    cudaGetSymbolAddress((void**)&pwh, sPW_hi); cudaGetSymbolAddress((void**)&pwl, sPW_lo);
    cudaGetSymbolAddress((void**)&uh,  sU_hi);  cudaGetSymbolAddress((void**)&ul,  sU_lo);
    cudaGetSymbolAddress((void**)&l1h, sL1_hi); cudaGetSymbolAddress((void**)&l1l, sL1_lo);
    cudaGetSymbolAddress((void**)&h1h, sH1_hi); cudaGetSymbolAddress((void**)&h1l, sH1_lo);
    cudaGetSymbolAddress((void**)&l2h, sL2_hi); cudaGetSymbolAddress((void**)&l2l, sL2_lo);

    const int SMEM_QR = 64 * QR_LDC * 4;
    const int SMG128 = 3 * (2*128*40*2 + 2*128*40*2);   // 122880
    const int SMG64  = 3 * (2*128*40*2 + 2*64*40*2);    //  92160
    cudaFuncSetAttribute(qr_forward,    cudaFuncAttributeMaxDynamicSharedMemorySize, SMEM_QR);
    cudaFuncSetAttribute(mma_gemm<128>, cudaFuncAttributeMaxDynamicSharedMemorySize, SMG128);
    cudaFuncSetAttribute(mma_gemm<64>,  cudaFuncAttributeMaxDynamicSharedMemorySize, SMG64);

    long long need = (long long)BN_*C_ + (long long)BH_*N_*N_;
    bool attn_in_out = ((long long)out_size >= need);
    float* attn_dst = attn_in_out ? (out + (long long)BN_*C_) : attn;

    const long long SLOT = 32768;   // one head-matrix (512x64) in pool

    // 1. pre-LN -> bf16 only (fp32 x is dead)
    ln_kernel<<<BN_, 128>>>(src, pre_w, pre_b, nullptr, xh, xl);
    // 1b. split all weights in one launch
    {
        int n0 = FF_*C_, n1 = C_*C_, n2 = FF_*C_, n3 = C_*FF_;
        int tot = n0 + n1 + n2 + n3;
        split4_kernel<<<(tot + 255)/256, 256>>>(
            qkv_w, qwh, qwl, n0,  proj_w, pwh, pwl, n1,
            l1_w, l1h, l1l, n2,   l2_w, l2h, l2l, n3);
    }
    // 2. QKV GEMM (M=8192, N=1152, K=384) + bias -> qkv fp32
    mma_gemm<128><<<dim3(9, 64, 1), 256, SMG128>>>(xh, xl, qwh, qwl, nullptr, qkv_b,
        qkv, nullptr, nullptr, C_, FF_, 0, 0, 0, 0, 1, 1);
    // 3. fused q/k split + norms -> pool slots 0..191
    qk_split_kernel<<<192*512/8, 256>>>(qkv, plh, pll, qn2, kn2);
    // 4. Householder factorization -> R ; invert -> RiT bf16 hi/lo
    qr_forward<<<192, 512, SMEM_QR>>>(qkv, R);
    rinv_kernel<<<192, 64>>>(R, rih, ril);
    // 4b. [qgr;kgr] = [q;k] @ Rinv -> pool slots 192..383 (bf16 only)
    mma_gemm<64><<<dim3(1, 4, 192), 256, SMG64>>>(plh, pll, rih, ril, nullptr, nullptr,
        nullptr, plh + 192*SLOT, pll + 192*SLOT, 64, 64, SLOT, 4096LL, SLOT, 0, 1, 8|16);
    // 5+6. merged score GEMM (z=192): qk for z<96, dots for z>=96
    mma_gemm<128><<<dim3(4, 4, 192), 256, SMG128>>>(plh, pll, plh + 96*SLOT, pll + 96*SLOT,
        nullptr, nullptr, scores, nullptr, nullptr, 64, 512,
        SLOT, SLOT, 262144LL, 0, 1, 32);
    // 7. v transpose -> bf16
    vT_bf16_kernel<<<dim3(96, 8), 256>>>(qkv, vth, vtl);
    // 8. mix + softmax -> attn fp32 + bf16
    mix_softmax<<<BN_, 512>>>(scores, scores + 96LL*262144, qn2, kn2, conv_w, conv_b,
                              scale_p, riem_p, grass_p, attn_dst, ath, atl);
    // 9. ao = attn @ v -> bf16 only, laid [b,n,h*64+d]
    mma_gemm<64><<<dim3(1, 4, 96), 256, SMG64>>>(ath, atl, vth, vtl, nullptr, nullptr,
        nullptr, aoh, aol, 512, 384, 262144LL, SLOT, 196608LL, 64LL, 6, 8|16);
    // 10. proj + bias + residual(src) -> t
    mma_gemm<128><<<dim3(3, 64, 1), 256, SMG128>>>(aoh, aol, pwh, pwl, src, proj_b,
        t, nullptr, nullptr, C_, C_, 0, 0, 0, 0, 1, 1|4);
    // 11. norm1 -> u fp32 (needed for residual) + bf16
    ln_kernel<<<BN_, 128>>>(t, n1_w, n1_b, u, uh, ul);
    // 12. lin1 + bias + gelu -> h1 bf16 only
    mma_gemm<128><<<dim3(9, 64, 1), 256, SMG128>>>(uh, ul, l1h, l1l, nullptr, l1_b,
        nullptr, h1h, h1l, C_, FF_, 0, 0, 0, 0, 1, 1|2|8|16);
    // 13. lin2 + bias + residual(u) -> d_out
    mma_gemm<128><<<dim3(3, 64, 1), 256, SMG128>>>(h1h, h1l, l2h, l2l, u, l2_b,
        out, nullptr, nullptr, FF_, C_, 0, 0, 0, 0, 1, 1|4);
}

// round 15
// speedup vs baseline: 2.4117x; 1.0284x over previous
#include <cuda_runtime.h>
#include <cuda_bf16.h>
#include <math.h>
#include <stdint.h>

typedef __nv_bfloat16 bf16;

#define B_  16
#define N_  512
#define C_  384
#define H_  6
#define HD_ 64
#define FF_ 1152
#define BN_ (B_*N_)   // 8192
#define BH_ (B_*H_)   // 96

// ---------------- fp32 scratch --------------------------------------------------
__device__ __align__(16) float g_qkv [BN_*3*C_];
__device__ __align__(16) float g_R   [192*64*64];
__device__ __align__(16) float g_qn2 [BH_*N_];
__device__ __align__(16) float g_kn2 [BH_*N_];
__device__ __align__(16) float g_scores[(long long)2*BH_*N_*N_];  // [qk ; dots]
__device__ __align__(16) float g_attn[(long long)BH_*N_*N_];
__device__ __align__(16) float g_t   [BN_*C_];
__device__ __align__(16) float g_u   [BN_*C_];

// ---------------- bf16 hi/lo operand pools --------------------------------------
// unified score pool: slots [q(0..95) | k(96..191) | qgr(192..287) | kgr(288..383)]
__device__ __align__(16) bf16 sPool_hi[384LL*N_*HD_], sPool_lo[384LL*N_*HD_];
__device__ __align__(16) bf16 sX_hi [BN_*C_],        sX_lo [BN_*C_];
__device__ __align__(16) bf16 sQW_hi[FF_*C_],        sQW_lo[FF_*C_];
__device__ __align__(16) bf16 sRi_hi[192*64*64],     sRi_lo[192*64*64];
__device__ __align__(16) bf16 sVT_hi[BH_*HD_*N_],    sVT_lo[BH_*HD_*N_];
__device__ __align__(16) bf16 sAt_hi[(long long)BH_*N_*N_], sAt_lo[(long long)BH_*N_*N_];
__device__ __align__(16) bf16 sAo_hi[BN_*C_],        sAo_lo[BN_*C_];
__device__ __align__(16) bf16 sPW_hi[C_*C_],         sPW_lo[C_*C_];
__device__ __align__(16) bf16 sU_hi [BN_*C_],        sU_lo [BN_*C_];
__device__ __align__(16) bf16 sL1_hi[FF_*C_],        sL1_lo[FF_*C_];
__device__ __align__(16) bf16 sH1_hi[BN_*FF_],       sH1_lo[BN_*FF_];
__device__ __align__(16) bf16 sL2_hi[C_*FF_],        sL2_lo[C_*FF_];

// ---------------- PTX helpers ---------------------------------------------------
__device__ __forceinline__ uint32_t smem_u32(const void* p) {
    uint32_t a;
    asm("{ .reg .u64 t; cvta.to.shared.u64 t, %1; cvt.u32.u64 %0, t; }" : "=r"(a) : "l"(p));
    return a;
}
__device__ __forceinline__ void cpa16(uint32_t s, const void* g) {
    asm volatile("cp.async.ca.shared.global [%0], [%1], 16;" :: "r"(s), "l"(g));
}
__device__ __forceinline__ void cpa_commit() {
    asm volatile("cp.async.commit_group;" ::: "memory");
}
__device__ __forceinline__ void cpa_wait1() {
    asm volatile("cp.async.wait_group 1;" ::: "memory");
}
__device__ __forceinline__ void ldsm4(uint32_t* r, uint32_t addr) {
    asm volatile("ldmatrix.sync.aligned.m8n8.x4.shared.b16 {%0,%1,%2,%3}, [%4];"
        : "=r"(r[0]), "=r"(r[1]), "=r"(r[2]), "=r"(r[3]) : "r"(addr));
}
__device__ __forceinline__ void mma_bf16(float* d, const uint32_t* a, uint32_t b0, uint32_t b1) {
    asm volatile("mma.sync.aligned.m16n8k16.row.col.f32.bf16.bf16.f32 "
        "{%0,%1,%2,%3}, {%4,%5,%6,%7}, {%8,%9}, {%0,%1,%2,%3};"
        : "+f"(d[0]), "+f"(d[1]), "+f"(d[2]), "+f"(d[3])
        : "r"(a[0]), "r"(a[1]), "r"(a[2]), "r"(a[3]), "r"(b0), "r"(b1));
}
__device__ __forceinline__ float gelu_f(float v) {
    return 0.5f * v * (1.f + erff(v * 0.70710678118654752f));
}
__device__ __forceinline__ void wsplit(float v, bf16& h, bf16& l) {
    h = __float2bfloat16(v);
    l = __float2bfloat16(v - __bfloat162float(h));
}

// ---------------- block reductions ----------------------------------------------
__device__ __forceinline__ float bred_sum(float v, float* red, int nw) {
    int lane = threadIdx.x & 31, wid = threadIdx.x >> 5;
    #pragma unroll
    for (int o = 16; o; o >>= 1) v += __shfl_xor_sync(0xffffffffu, v, o);
    if (lane == 0) red[wid] = v;
    __syncthreads();
    if (wid == 0) {
        float t = (lane < nw) ? red[lane] : 0.f;
        #pragma unroll
        for (int o = 16; o; o >>= 1) t += __shfl_xor_sync(0xffffffffu, t, o);
        if (lane == 0) red[32] = t;
    }
    __syncthreads();
    float r = red[32];
    __syncthreads();
    return r;
}

// ---------------- LayerNorm (fp32 out optional + bf16 hi/lo) --------------------
__global__ __launch_bounds__(128) void ln_kernel(
    const float* __restrict__ in, const float* __restrict__ w,
    const float* __restrict__ b, float* __restrict__ out,
    bf16* __restrict__ ohi, bf16* __restrict__ olo) {
    __shared__ float red[33];
    int row = blockIdx.x;
    const float* x = in + (long long)row * C_;
    float v0[3]; float s = 0.f;
    #pragma unroll
    for (int i = 0; i < 3; i++) { v0[i] = x[threadIdx.x + 128*i]; s += v0[i]; }
    s = bred_sum(s, red, 4);
    float mu = s * (1.f / C_);
    float var = 0.f;
    #pragma unroll
    for (int i = 0; i < 3; i++) { float d = v0[i] - mu; var = fmaf(d, d, var); }
    var = bred_sum(var, red, 4) * (1.f / C_);
    float inv = rsqrtf(var + 1e-5f);
    #pragma unroll
    for (int i = 0; i < 3; i++) {
        int c = threadIdx.x + 128*i;
        float v = (v0[i] - mu) * inv * w[c] + b[c];
        long long idx = (long long)row*C_ + c;
        if (out) out[idx] = v;
        bf16 h, l; wsplit(v, h, l);
        ohi[idx] = h; olo[idx] = l;
    }
}

// ---------------- one-shot 4-segment fp32 -> bf16 hi/lo split -------------------
__global__ void split4_kernel(
    const float* __restrict__ s0, bf16* __restrict__ h0, bf16* __restrict__ l0, int n0,
    const float* __restrict__ s1, bf16* __restrict__ h1, bf16* __restrict__ l1, int n1,
    const float* __restrict__ s2, bf16* __restrict__ h2, bf16* __restrict__ l2, int n2,
    const float* __restrict__ s3, bf16* __restrict__ h3, bf16* __restrict__ l3, int n3) {
    int i = blockIdx.x * blockDim.x + threadIdx.x;
    const float* s; bf16 *hh, *ll; int j = i;
    if (j < n0) { s = s0; hh = h0; ll = l0; }
    else {
        j -= n0;
        if (j < n1) { s = s1; hh = h1; ll = l1; }
        else {
            j -= n1;
            if (j < n2) { s = s2; hh = h2; ll = l2; }
            else {
                j -= n2;
                if (j >= n3) return;
                s = s3; hh = h3; ll = l3;
            }
        }
    }
    float v = s[j];
    bf16 h, l; wsplit(v, h, l);
    hh[j] = h; ll[j] = l;
}

// ---------------- fused q/k split + per-row sumsq (warp per row) ----------------
__global__ __launch_bounds__(256) void qk_split_kernel(
    const float* __restrict__ qkv, bf16* __restrict__ hi, bf16* __restrict__ lo,
    float* __restrict__ qn2, float* __restrict__ kn2) {
    int gw = blockIdx.x * 8 + (threadIdx.x >> 5);
    int lane = threadIdx.x & 31;
    int r = gw & 511;
    int z = gw >> 9;
    int s = (z >= 96) ? 1 : 0;
    int bh = z - s*96;
    int b = bh / 6, h = bh - (bh/6)*6;
    const float* p = qkv + (long long)(b*512 + r)*1152 + s*384 + h*64;
    float v0 = p[lane], v1 = p[lane + 32];
    long long o = (long long)z*32768 + r*64 + lane;
    bf16 h0, l0, h1, l1;
    wsplit(v0, h0, l0); wsplit(v1, h1, l1);
    hi[o] = h0; lo[o] = l0;
    hi[o + 32] = h1; lo[o + 32] = l1;
    float ss = fmaf(v0, v0, v1*v1);
    #pragma unroll
    for (int d = 16; d; d >>= 1) ss += __shfl_xor_sync(0xffffffffu, ss, d);
    if (lane == 0) {
        if (s) kn2[bh*512 + r] = ss; else qn2[bh*512 + r] = ss;
    }
}

// ---------------- bf16-split tensor-core GEMM: C = A * B^T ----------------------
// flags: 1=bias, 2=gelu, 4=residual, 8=write bf16 hi/lo, 16=skip fp32 C,
//        32=score mode (zi = z + 96*[z>=96])
template<int BN>
__global__ __launch_bounds__(256) void mma_gemm(
    const bf16* __restrict__ Ahi, const bf16* __restrict__ Alo,
    const bf16* __restrict__ Bhi, const bf16* __restrict__ Blo,
    const float* __restrict__ Rres, const float* __restrict__ bias,
    float* __restrict__ Cout, bf16* __restrict__ Whi, bf16* __restrict__ Wlo,
    int K, int ldc, long long sA, long long sB,
    long long Cb, long long Ch, int Hdiv, int flags)
{
    constexpr int WN  = BN / 2;
    constexpr int NT  = WN / 16;
    constexpr int NF  = WN / 8;
    constexpr int ATB = 128*40*2;
    constexpr int BTB = BN*40*2;
    constexpr int STG = 2*ATB + 2*BTB;

    extern __shared__ __align__(16) bf16 dyn[];
    uint32_t sbase = smem_u32(dyn);

    int z = blockIdx.z;
    int zi = z + ((flags & 32) && z >= 96 ? 96 : 0);
    const bf16* pAhi = Ahi + (long long)zi*sA;
    const bf16* pAlo = Alo + (long long)zi*sA;
    const bf16* pBhi = Bhi + (long long)zi*sB;
    const bf16* pBlo = Blo + (long long)zi*sB;
    int zb = z / Hdiv, zh = z - zb*Hdiv;
    long long co = Cb*zb + Ch*zh;

    int m0 = blockIdx.y << 7, n0 = blockIdx.x * BN;
    int tid = threadIdx.x, wid = tid >> 5, lane = tid & 31;
    int wm = wid >> 1, wn = wid & 1;
    int r16 = lane & 15, kh = lane >> 4;

    float acc[2][NF][4];
    #pragma unroll
    for (int a = 0; a < 2; a++)
        #pragma unroll
        for (int f = 0; f < NF; f++)
            #pragma unroll
            for (int q = 0; q < 4; q++) acc[a][f][q] = 0.f;

    int kt = K >> 5;

    auto load_tile = [&](int t) {
        int s = t % 3;
        uint32_t ab = sbase + (uint32_t)(s * STG);
        int k0 = t << 5;
        #pragma unroll
        for (int i = tid; i < 128*4; i += 256) {
            int r = i >> 2, c = i & 3;
            uint32_t so = ab + (uint32_t)((r*40 + c*8) * 2);
            cpa16(so, pAhi + (long long)(m0 + r)*K + k0 + c*8);
            cpa16(so + ATB, pAlo + (long long)(m0 + r)*K + k0 + c*8);
        }
        uint32_t bbb = sbase + (uint32_t)(s * STG) + 2*ATB;
        #pragma unroll
        for (int i = tid; i < BN*4; i += 256) {
            int r = i >> 2, c = i & 3;
            uint32_t so = bbb + (uint32_t)((r*40 + c*8) * 2);
            cpa16(so, pBhi + (long long)(n0 + r)*K + k0 + c*8);
            cpa16(so + BTB, pBlo + (long long)(n0 + r)*K + k0 + c*8);
        }
    };

    load_tile(0); cpa_commit();
    if (kt > 1) load_tile(1);
    cpa_commit();

    for (int t = 0; t < kt; t++) {
        cpa_wait1();
        __syncthreads();
        if (t + 2 < kt) load_tile(t + 2);
        cpa_commit();

        int s = t % 3;
        uint32_t ab = sbase + (uint32_t)(s * STG);
        uint32_t bb = ab + 2*ATB;
        #pragma unroll
        for (int kk = 0; kk < 2; kk++) {
            uint32_t a_hi[2][4], a_lo[2][4];
            uint32_t b_hi[NT][4], b_lo[NT][4];
            #pragma unroll
            for (int mt = 0; mt < 2; mt++) {
                uint32_t ad = ab + (uint32_t)(((wm*32 + mt*16 + r16)*40 + kk*16 + kh*8) * 2);
                ldsm4(a_hi[mt], ad);
                ldsm4(a_lo[mt], ad + ATB);
            }
            #pragma unroll
            for (int nt = 0; nt < NT; nt++) {
                uint32_t bd = bb + (uint32_t)(((wn*WN + nt*16 + r16)*40 + kk*16 + kh*8) * 2);
                ldsm4(b_hi[nt], bd);
                ldsm4(b_lo[nt], bd + BTB);
            }
            #pragma unroll
            for (int mt = 0; mt < 2; mt++)
                #pragma unroll
                for (int nt = 0; nt < NT; nt++) {
                    mma_bf16(acc[mt][2*nt],     a_hi[mt], b_hi[nt][0], b_hi[nt][2]);
                    mma_bf16(acc[mt][2*nt + 1], a_hi[mt], b_hi[nt][1], b_hi[nt][3]);
                }
            #pragma unroll
            for (int mt = 0; mt < 2; mt++)
                #pragma unroll
                for (int nt = 0; nt < NT; nt++) {
                    mma_bf16(acc[mt][2*nt],     a_hi[mt], b_lo[nt][0], b_lo[nt][2]);
                    mma_bf16(acc[mt][2*nt + 1], a_hi[mt], b_lo[nt][1], b_lo[nt][3]);
                }
            #pragma unroll
            for (int mt = 0; mt < 2; mt++)
                #pragma unroll
                for (int nt = 0; nt < NT; nt++) {
                    mma_bf16(acc[mt][2*nt],     a_lo[mt], b_hi[nt][0], b_hi[nt][2]);
                    mma_bf16(acc[mt][2*nt + 1], a_lo[mt], b_hi[nt][1], b_hi[nt][3]);
                }
        }
    }

    #pragma unroll
    for (int mt = 0; mt < 2; mt++)
    #pragma unroll
    for (int f = 0; f < NF; f++) {
        float* c = acc[mt][f];
        int row = m0 + wm*32 + mt*16 + (lane >> 2);
        int col = n0 + wn*WN + f*8 + ((lane & 3) << 1);
        #pragma unroll
        for (int half = 0; half < 2; half++) {
            int r = row + half*8;
            float v0 = c[half*2 + 0], v1 = c[half*2 + 1];
            if (flags & 1) { v0 += bias[col]; v1 += bias[col + 1]; }
            if (flags & 2) { v0 = gelu_f(v0); v1 = gelu_f(v1); }
            long long idx = co + (long long)r*ldc + col;
            if (flags & 4) {
                float2 rr = *(const float2*)(Rres + idx);
                v0 += rr.x; v1 += rr.y;
            }
            if (!(flags & 16)) {
                float2 o; o.x = v0; o.y = v1;
                *(float2*)(Cout + idx) = o;
            }
            if (flags & 8) {
                bf16 h0, l0, h1, l1;
                wsplit(v0, h0, l0); wsplit(v1, h1, l1);
                __nv_bfloat162 hh; hh.x = h0; hh.y = h1;
                __nv_bfloat162 ll; ll.x = l0; ll.y = l1;
                *(__nv_bfloat162*)(Whi + idx) = hh;
                *(__nv_bfloat162*)(Wlo + idx) = ll;
            }
        }
    }
}

// ---------------- v transpose via smem tile (coalesced both sides) --------------
__global__ __launch_bounds__(256) void vT_bf16_kernel(const float* __restrict__ qkv,
                                                      bf16* __restrict__ hi,
                                                      bf16* __restrict__ lo) {
    __shared__ float tile[64][65];
    int bh = blockIdx.x;
    int m0 = blockIdx.y << 6;
    int b = bh / 6, h = bh - (bh/6)*6;
    int tid = threadIdx.x;
    for (int i = tid; i < 4096; i += 256) {
        int m = i >> 6, d = i & 63;
        tile[d][m] = qkv[(long long)(b*512 + m0 + m)*1152 + 768 + h*64 + d];
    }
    __syncthreads();
    for (int i = tid; i < 4096; i += 256) {
        int d = i >> 6, m = i & 63;
        float v = tile[d][m];
        bf16 h_, l_; wsplit(v, h_, l_);
        long long o = (long long)bh*32768 + d*512 + m0 + m;
        hi[o] = h_; lo[o] = l_;
    }
}

// ---------------- Householder QR factorization (sgeqr2, float2 rows) ------------
// Single-reflector version (proven correct through R11). LAPACK slarfg signs.
#define QR_LDC 514
__global__ __launch_bounds__(512) void qr_forward(const float* __restrict__ qkv,
                                                  float* __restrict__ R_out) {
    extern __shared__ float As[];
    __shared__ float red[33];
    __shared__ float sbeta[64];
    __shared__ float s_ss[2];
    int mat = blockIdx.x;
    int s = (mat >= 96) ? 1 : 0;
    int bh = mat - s*96;
    int b = bh / 6, h = bh - (bh/6)*6;
    const float* Ab = qkv + (long long)b*512*1152 + s*384 + h*64;
    int tid = threadIdx.x;
    int wid = tid >> 5, lane = tid & 31;

    for (int i = tid; i < 64*512; i += 512) {
        int n = i >> 6, d = i & 63;
        As[d*QR_LDC + n] = Ab[(long long)n*1152 + d];
    }
    __syncthreads();
    {
        float x = (tid > 0) ? As[tid] : 0.f;
        float ss0 = bred_sum(x*x, red, 16);
        if (tid == 0) s_ss[0] = ss0;
    }
    __syncthreads();

    for (int j = 0; j < 64; j++) {
        float* col = As + j*QR_LDC;
        float alpha = col[j];
        float ss = s_ss[j & 1];
        float beta, teff, uj;
        if (ss == 0.f) { beta = alpha; teff = 0.f; uj = 1.f; }
        else {
            float nrm = sqrtf(alpha*alpha + ss);
            beta = (alpha >= 0.f) ? -nrm : nrm;   // LAPACK sign
            uj  = alpha - beta;
            teff = ((beta - alpha) / beta) / (uj * uj);
        }
        if (tid == 0) sbeta[j] = beta;
        const float2* colv = (const float2*)col;
        float2 u[8];
        #pragma unroll
        for (int t = 0; t < 8; t++) {
            float2 vv = colv[lane + 32*t];
            int r0 = (lane + 32*t) << 1;
            u[t].x = (r0     > j) ? vv.x : ((r0     == j) ? uj : 0.f);
            u[t].y = (r0 + 1 > j) ? vv.y : ((r0 + 1 == j) ? uj : 0.f);
        }
        for (int c = j + 1 + wid; c < 64; c += 16) {
            float2* cc = (float2*)(As + c*QR_LDC);
            float2 cv[8];
            float w = 0.f;
            #pragma unroll
            for (int t = 0; t < 8; t++) {
                cv[t] = cc[lane + 32*t];
                w = fmaf(u[t].x, cv[t].x, w);
                w = fmaf(u[t].y, cv[t].y, w);
            }
            #pragma unroll
            for (int o = 16; o; o >>= 1) w += __shfl_xor_sync(0xffffffffu, w, o);
            float tw = teff * w;
            if (c == j + 1) {
                float nss = 0.f;
                #pragma unroll
                for (int t = 0; t < 8; t++) {
                    int r0 = (lane + 32*t) << 1;
                    float nx = cv[t].x - tw * u[t].x;
                    float ny = cv[t].y - tw * u[t].y;
                    float2 nv; nv.x = nx; nv.y = ny;
                    cc[lane + 32*t] = nv;
                    if (r0     > j + 1) nss = fmaf(nx, nx, nss);
                    if (r0 + 1 > j + 1) nss = fmaf(ny, ny, nss);
                }
                #pragma unroll
                for (int o = 16; o; o >>= 1) nss += __shfl_xor_sync(0xffffffffu, nss, o);
                if (lane == 0) s_ss[(j + 1) & 1] = nss;
            } else {
                #pragma unroll
                for (int t = 0; t < 8; t++) {
                    float2 nv;
                    nv.x = cv[t].x - tw * u[t].x;
                    nv.y = cv[t].y - tw * u[t].y;
                    cc[lane + 32*t] = nv;
                }
            }
        }
        __syncthreads();
    }
    for (int i = tid; i < 4096; i += 512) {
        int c = i >> 6, r = i & 63;
        float v = (r < c) ? As[c*QR_LDC + r] : ((r == c) ? sbeta[c] : 0.f);
        R_out[(long long)mat*4096 + i] = v;
    }
}

// ---------------- invert upper-triangular R -> bf16 hi/lo transposed ------------
__global__ __launch_bounds__(64) void rinv_kernel(const float* __restrict__ R,
                                                  bf16* __restrict__ rih,
                                                  bf16* __restrict__ ril) {
    __shared__ float Rs[4096];
    __shared__ float xs[64*65];
    int mat = blockIdx.x, tid = threadIdx.x;
    for (int i = tid; i < 4096; i += 64) Rs[i] = R[(long long)mat*4096 + i];
    __syncthreads();
    int c = tid;
    float* x = xs + c*65;
    for (int i = c; i >= 0; i--) {
        float sacc = (i == c) ? 1.f : 0.f;
        for (int k = i + 1; k <= c; k++)
            sacc = fmaf(-Rs[k*64 + i], x[k], sacc);
        x[i] = sacc / Rs[i*64 + i];
    }
    for (int k = 0; k < 64; k++) {
        float v = (k <= c) ? x[k] : 0.f;
        bf16 h, l; wsplit(v, h, l);
        long long o = (long long)mat*4096 + c*64 + k;
        rih[o] = h; ril[o] = l;
    }
}

// ---------------- fused head-mix + softmax (6-channel 2-level reduction) --------
__global__ __launch_bounds__(512) void mix_softmax(
    const float* __restrict__ qk, const float* __restrict__ dots,
    const float* __restrict__ qn2, const float* __restrict__ kn2,
    const float* __restrict__ conv_w, const float* __restrict__ conv_b,
    const float* __restrict__ sp, const float* __restrict__ rp,
    const float* __restrict__ gp, float* __restrict__ attn,
    bf16* __restrict__ ahi, bf16* __restrict__ alo) {
    __shared__ float wsh[108], bsh[6], qsh[6];
    __shared__ float part[6][17];
    __shared__ float fin[6], fin2[6];
    int bn = blockIdx.x; int b = bn >> 9, n = bn & 511;
    int m = threadIdx.x;
    int lane = m & 31, wid = m >> 5;
    if (m < 108) wsh[m] = conv_w[m];
    if (m < 6) { bsh[m] = conv_b[m]; qsh[m] = qn2[((b*6 + m) << 9) + n]; }
    float scale = *sp, rs = *rp, gs = *gp;
    __syncthreads();
    float mixed[6];
    #pragma unroll
    for (int o = 0; o < 6; o++) mixed[o] = bsh[o];
    #pragma unroll
    for (int h = 0; h < 6; h++) {
        long long idx = ((long long)((b*6 + h)*512 + n) << 9) + m;
        float qv = qk[idx];
        float dd = dots[idx];
        float e  = qv * scale;
        float qn = qsh[h];
        float kn = kn2[((b*6 + h) << 9) + m];
        float d2 = qn*qn + kn*kn - 2.f*qv*qv;
        float ri = sqrtf(fmaxf(d2, 0.f)) * rs;
        float gg = dd*dd * gs;
        #pragma unroll
        for (int o = 0; o < 6; o++)
            mixed[o] += wsh[o*18 + h]*e + wsh[o*18 + 6 + h]*ri + wsh[o*18 + 12 + h]*gg;
    }
    #pragma unroll
    for (int o = 0; o < 6; o++) {
        float v = mixed[o];
        #pragma unroll
        for (int d = 16; d; d >>= 1) v = fmaxf(v, __shfl_xor_sync(0xffffffffu, v, d));
        if (lane == 0) part[o][wid] = v;
    }
    __syncthreads();
    if (m < 96) {
        int o = m >> 4, l = m & 15;
        float v = part[o][l];
        #pragma unroll
        for (int d = 8; d; d >>= 1) v = fmaxf(v, __shfl_xor_sync(0xffffffffu, v, d));
        if (l == 0) fin[o] = v;
    }
    __syncthreads();
    float e[6];
    #pragma unroll
    for (int o = 0; o < 6; o++) {
        e[o] = expf(mixed[o] - fin[o]);
        float v = e[o];
        #pragma unroll
        for (int d = 16; d; d >>= 1) v += __shfl_xor_sync(0xffffffffu, v, d);
        if (lane == 0) part[o][wid] = v;
    }
    __syncthreads();
    if (m < 96) {
        int o = m >> 4, l = m & 15;
        float v = part[o][l];
        #pragma unroll
        for (int d = 8; d; d >>= 1) v += __shfl_xor_sync(0xffffffffu, v, d);
        if (l == 0) fin2[o] = v;
    }
    __syncthreads();
    #pragma unroll
    for (int o = 0; o < 6; o++) {
        float v = e[o] / fin2[o];
        long long idx = ((long long)((b*6 + o)*512 + n) << 9) + m;
        attn[idx] = v;
        bf16 h_, l_; wsplit(v, h_, l_);
        ahi[idx] = h_; alo[idx] = l_;
    }
}

// ================================================================================
extern "C" void kernel_launch(void* const* d_in, const int* in_sizes, int n_in,
                              void* d_out, int out_size) {
    const float* src     = (const float*)d_in[0];
    const float* pre_w   = (const float*)d_in[1];
    const float* pre_b   = (const float*)d_in[2];
    const float* qkv_w   = (const float*)d_in[3];
    const float* qkv_b   = (const float*)d_in[4];
    const float* scale_p = (const float*)d_in[5];
    const float* riem_p  = (const float*)d_in[6];
    const float* grass_p = (const float*)d_in[7];
    const float* conv_w  = (const float*)d_in[8];
    const float* conv_b  = (const float*)d_in[9];
    const float* proj_w  = (const float*)d_in[10];
    const float* proj_b  = (const float*)d_in[11];
    const float* n1_w    = (const float*)d_in[12];
    const float* n1_b    = (const float*)d_in[13];
    const float* l1_w    = (const float*)d_in[14];
    const float* l1_b    = (const float*)d_in[15];
    const float* l2_w    = (const float*)d_in[16];
    const float* l2_b    = (const float*)d_in[17];
    float* out = (float*)d_out;

    float *qkv, *R, *qn2, *kn2, *scores, *attn, *t, *u;
    cudaGetSymbolAddress((void**)&qkv,    g_qkv);
    cudaGetSymbolAddress((void**)&R,      g_R);
    cudaGetSymbolAddress((void**)&qn2,    g_qn2);
    cudaGetSymbolAddress((void**)&kn2,    g_kn2);
    cudaGetSymbolAddress((void**)&scores, g_scores);
    cudaGetSymbolAddress((void**)&attn,   g_attn);
    cudaGetSymbolAddress((void**)&t,      g_t);
    cudaGetSymbolAddress((void**)&u,      g_u);

    bf16 *plh,*pll,*xh,*xl,*qwh,*qwl,*rih,*ril,
         *vth,*vtl,*ath,*atl,*aoh,*aol,*pwh,*pwl,*uh,*ul,*l1h,*l1l,*h1h,*h1l,*l2h,*l2l;
    cudaGetSymbolAddress((void**)&plh, sPool_hi); cudaGetSymbolAddress((void**)&pll, sPool_lo);
    cudaGetSymbolAddress((void**)&xh,  sX_hi);  cudaGetSymbolAddress((void**)&xl,  sX_lo);
    cudaGetSymbolAddress((void**)&qwh, sQW_hi); cudaGetSymbolAddress((void**)&qwl, sQW_lo);
    cudaGetSymbolAddress((void**)&rih, sRi_hi); cudaGetSymbolAddress((void**)&ril, sRi_lo);
    cudaGetSymbolAddress((void**)&vth, sVT_hi); cudaGetSymbolAddress((void**)&vtl, sVT_lo);
    cudaGetSymbolAddress((void**)&ath, sAt_hi); cudaGetSymbolAddress((void**)&atl, sAt_lo);
    cudaGetSymbolAddress((void**)&aoh, sAo_hi); cudaGetSymbolAddress((void**)&aol, sAo_lo);
    cudaGetSymbolAddress((void**)&pwh, sPW_hi); cudaGetSymbolAddress((void**)&pwl, sPW_lo);
    cudaGetSymbolAddress((void**)&uh,  sU_hi);  cudaGetSymbolAddress((void**)&ul,  sU_lo);
    cudaGetSymbolAddress((void**)&l1h, sL1_hi); cudaGetSymbolAddress((void**)&l1l, sL1_lo);
    cudaGetSymbolAddress((void**)&h1h, sH1_hi); cudaGetSymbolAddress((void**)&h1l, sH1_lo);
    cudaGetSymbolAddress((void**)&l2h, sL2_hi); cudaGetSymbolAddress((void**)&l2l, sL2_lo);

    const int SMEM_QR = 64 * QR_LDC * 4;
    const int SMG128 = 3 * (2*128*40*2 + 2*128*40*2);   // 122880
    const int SMG64  = 3 * (2*128*40*2 + 2*64*40*2);    //  92160
    cudaFuncSetAttribute(qr_forward,    cudaFuncAttributeMaxDynamicSharedMemorySize, SMEM_QR);
    cudaFuncSetAttribute(mma_gemm<128>, cudaFuncAttributeMaxDynamicSharedMemorySize, SMG128);
    cudaFuncSetAttribute(mma_gemm<64>,  cudaFuncAttributeMaxDynamicSharedMemorySize, SMG64);

    long long need = (long long)BN_*C_ + (long long)BH_*N_*N_;
    bool attn_in_out = ((long long)out_size >= need);
    float* attn_dst = attn_in_out ? (out + (long long)BN_*C_) : attn;

    const long long SLOT = 32768;

    // 1. pre-LN -> bf16 only
    ln_kernel<<<BN_, 128>>>(src, pre_w, pre_b, nullptr, xh, xl);
    // 1b. split all weights in one launch
    {
        int n0 = FF_*C_, n1 = C_*C_, n2 = FF_*C_, n3 = C_*FF_;
        int tot = n0 + n1 + n2 + n3;
        split4_kernel<<<(tot + 255)/256, 256>>>(
            qkv_w, qwh, qwl, n0,  proj_w, pwh, pwl, n1,
            l1_w, l1h, l1l, n2,   l2_w, l2h, l2l, n3);
    }
    // 2. QKV GEMM (M=8192, N=1152, K=384) + bias -> qkv fp32
    mma_gemm<128><<<dim3(9, 64, 1), 256, SMG128>>>(xh, xl, qwh, qwl, nullptr, qkv_b,
        qkv, nullptr, nullptr, C_, FF_, 0, 0, 0, 0, 1, 1);
    // 3. fused q/k split + norms -> pool slots 0..191
    qk_split_kernel<<<192*512/8, 256>>>(qkv, plh, pll, qn2, kn2);
    // 4. Householder factorization -> R ; invert -> RiT bf16 hi/lo
    qr_forward<<<192, 512, SMEM_QR>>>(qkv, R);
    rinv_kernel<<<192, 64>>>(R, rih, ril);
    // 4b. [qgr;kgr] = [q;k] @ Rinv -> pool slots 192..383 (bf16 only)
    mma_gemm<64><<<dim3(1, 4, 192), 256, SMG64>>>(plh, pll, rih, ril, nullptr, nullptr,
        nullptr, plh + 192*SLOT, pll + 192*SLOT, 64, 64, SLOT, 4096LL, SLOT, 0, 1, 8|16);
    // 5+6. merged score GEMM (z=192): qk for z<96, dots for z>=96
    mma_gemm<128><<<dim3(4, 4, 192), 256, SMG128>>>(plh, pll, plh + 96*SLOT, pll + 96*SLOT,
        nullptr, nullptr, scores, nullptr, nullptr, 64, 512,
        SLOT, SLOT, 262144LL, 0, 1, 32);
    // 7. v transpose -> bf16
    vT_bf16_kernel<<<dim3(96, 8), 256>>>(qkv, vth, vtl);
    // 8. mix + softmax -> attn fp32 + bf16
    mix_softmax<<<BN_, 512>>>(scores, scores + 96LL*262144, qn2, kn2, conv_w, conv_b,
                              scale_p, riem_p, grass_p, attn_dst, ath, atl);
    // 9. ao = attn @ v -> bf16 only, laid [b,n,h*64+d]
    mma_gemm<64><<<dim3(1, 4, 96), 256, SMG64>>>(ath, atl, vth, vtl, nullptr, nullptr,
        nullptr, aoh, aol, 512, 384, 262144LL, SLOT, 196608LL, 64LL, 6, 8|16);
    // 10. proj + bias + residual(src) -> t  (BN=64: 384 CTAs, better wave balance)
    mma_gemm<64><<<dim3(6, 64, 1), 256, SMG64>>>(aoh, aol, pwh, pwl, src, proj_b,
        t, nullptr, nullptr, C_, C_, 0, 0, 0, 0, 1, 1|4);
    // 11. norm1 -> u fp32 + bf16
    ln_kernel<<<BN_, 128>>>(t, n1_w, n1_b, u, uh, ul);
    // 12. lin1 + bias + gelu -> h1 bf16 only
    mma_gemm<128><<<dim3(9, 64, 1), 256, SMG128>>>(uh, ul, l1h, l1l, nullptr, l1_b,
        nullptr, h1h, h1l, C_, FF_, 0, 0, 0, 0, 1, 1|2|8|16);
    // 13. lin2 + bias + residual(u) -> d_out  (BN=64: 384 CTAs vs 192)
    mma_gemm<64><<<dim3(6, 64, 1), 256, SMG64>>>(h1h, h1l, l2h, l2l, u, l2_b,
        out, nullptr, nullptr, FF_, C_, 0, 0, 0, 0, 1, 1|4);
}